// round 5
// baseline (speedup 1.0000x reference)
#include <cuda_runtime.h>
#include <cuda_bf16.h>
#include <cstdint>
#include <cmath>

// Problem constants
#define BB   4
#define SS   1024
#define DD   1024
#define HH   16
#define DKH  64
#define LL   4
#define FF   4096
#define VV   32000
#define NT   (BB*SS)   // 4096 tokens
#define QKVW 3072      // packed q|k|v width

// GEMM tile config (mma.sync path)
#define BM 128
#define BN 128
#define BK 64                      // bf16 elems per k-stage
#define AROWB 144                  // A smem row: 128B data + 16B pad
#define AMATB (128*AROWB)          // one 128xBK bf16 matrix: 18432 B
#define ASTAGE (2*AMATB)           // Ahi|Alo per stage: 36864 B
#define BROWB 272                  // B smem row: 256B data + 16B pad
#define BHALF (64*BROWB)           // one 64x128 bf16 matrix: 17408 B
#define BSTG  (2*BHALF)            // Bhi|Blo per stage: 34816 B
#define BBASE (3*ASTAGE)           // 110592
#define GEMM_SMEM (BBASE + 3*BSTG) // 215040 B

// ---------------------------------------------------------------------------
// Scratch (device globals — no runtime allocation allowed)
// ---------------------------------------------------------------------------
__device__ float g_h  [NT*(size_t)DD];
__device__ float g_qkv[NT*(size_t)QKVW];
__device__ float g_tmp[NT*(size_t)DD];
__device__ __nv_bfloat16 g_ahi[NT*(size_t)DD];
__device__ __nv_bfloat16 g_alo[NT*(size_t)DD];
__device__ __nv_bfloat16 g_fhi[NT*(size_t)FF];
__device__ __nv_bfloat16 g_flo[NT*(size_t)FF];

// ---------------------------------------------------------------------------
// PTX helpers (arch-agnostic: sm_80-era instructions only)
// ---------------------------------------------------------------------------
__device__ __forceinline__ uint32_t smem_u32(const void* p) {
    uint32_t a;
    asm("{ .reg .u64 t; cvta.to.shared.u64 t, %1; cvt.u32.u64 %0, t; }" : "=r"(a) : "l"(p));
    return a;
}
__device__ __forceinline__ void cp_async16(uint32_t dst, const void* src) {
    asm volatile("cp.async.cg.shared.global [%0], [%1], 16;" :: "r"(dst), "l"(src));
}
__device__ __forceinline__ void cp_commit() {
    asm volatile("cp.async.commit_group;");
}
__device__ __forceinline__ void cp_wait1() {
    asm volatile("cp.async.wait_group 1;");
}
__device__ __forceinline__ void cp_wait0() {
    asm volatile("cp.async.wait_group 0;");
}
__device__ __forceinline__ void ldmx4(uint32_t addr, uint32_t& r0, uint32_t& r1,
                                      uint32_t& r2, uint32_t& r3) {
    asm volatile("ldmatrix.sync.aligned.m8n8.x4.shared.b16 {%0,%1,%2,%3}, [%4];"
                 : "=r"(r0), "=r"(r1), "=r"(r2), "=r"(r3) : "r"(addr));
}
__device__ __forceinline__ void ldmx4t(uint32_t addr, uint32_t& r0, uint32_t& r1,
                                       uint32_t& r2, uint32_t& r3) {
    asm volatile("ldmatrix.sync.aligned.m8n8.x4.trans.shared.b16 {%0,%1,%2,%3}, [%4];"
                 : "=r"(r0), "=r"(r1), "=r"(r2), "=r"(r3) : "r"(addr));
}
__device__ __forceinline__ void mma_bf16(float* c, const uint32_t* a, const uint32_t* b) {
    asm volatile("mma.sync.aligned.m16n8k16.row.col.f32.bf16.bf16.f32 "
                 "{%0,%1,%2,%3}, {%4,%5,%6,%7}, {%8,%9}, {%0,%1,%2,%3};"
                 : "+f"(c[0]), "+f"(c[1]), "+f"(c[2]), "+f"(c[3])
                 : "r"(a[0]), "r"(a[1]), "r"(a[2]), "r"(a[3]), "r"(b[0]), "r"(b[1]));
}
__device__ __forceinline__ uint32_t bf2_bits(__nv_bfloat162 v) {
    return *reinterpret_cast<uint32_t*>(&v);
}
// split a float pair into hi/lo bf16x2 words
__device__ __forceinline__ void split2(float a, float b, uint32_t& hw, uint32_t& lw) {
    __nv_bfloat162 h = __floats2bfloat162_rn(a, b);
    float la = a - __low2float(h);
    float lb = b - __high2float(h);
    __nv_bfloat162 l = __floats2bfloat162_rn(la, lb);
    hw = bf2_bits(h);
    lw = bf2_bits(l);
}

// ---------------------------------------------------------------------------
// Embedding + positional encoding; writes fp32 h AND bf16 hi/lo split
// ---------------------------------------------------------------------------
__global__ __launch_bounds__(256) void embed_kernel(const int* __restrict__ x,
                                                    const float* __restrict__ emb,
                                                    float* __restrict__ h,
                                                    __nv_bfloat16* __restrict__ ahi,
                                                    __nv_bfloat16* __restrict__ alo)
{
    int t = blockIdx.x;
    int s = t & (SS - 1);
    int tok = x[t];
    const float* e = emb + (size_t)tok * DD;
    const float negln = -9.210340371976184f;
    size_t base = (size_t)t * DD;
    for (int d0 = threadIdx.x * 2; d0 < DD; d0 += blockDim.x * 2) {
        float v[2];
        #pragma unroll
        for (int j = 0; j < 2; j++) {
            int d = d0 + j;
            int i2 = (d >> 1) * 2;
            float div = expf((float)i2 * (negln / (float)DD));
            float ang = (float)s * div;
            float pe = (d & 1) ? cosf(ang) : sinf(ang);
            v[j] = e[d] * 32.0f + pe;
        }
        h[base + d0] = v[0];
        h[base + d0 + 1] = v[1];
        uint32_t hw, lw;
        split2(v[0], v[1], hw, lw);
        *reinterpret_cast<uint32_t*>(ahi + base + d0) = hw;
        *reinterpret_cast<uint32_t*>(alo + base + d0) = lw;
    }
}

// ---------------------------------------------------------------------------
// bf16x3 GEMM via mma.sync: C[M,N] = A[M,K] @ W[K,N] (+bias)(+GELU)
// A: pre-split hi/lo bf16 [M,K]. W: ORIGINAL fp32 [K,N], split on the fly.
// BM=BN=128, BK=64, 256 threads (8 warps, 64x32 warp tiles).
// Triple-buffered A (cp.async) and B (LDG->cvt->STS). ONE barrier per stage:
// all stores/loads for future stages are issued before the MMA burst and
// drain underneath it.
// ---------------------------------------------------------------------------
__device__ __forceinline__ void stage_loadA(uint32_t sdst,
                                            const __nv_bfloat16* Ahi, const __nv_bfloat16* Alo,
                                            int rowBase, int K, int k0, int tid)
{
    #pragma unroll
    for (int i = 0; i < 4; i++) {
        int idx = tid + i * 256;           // 0..1023
        int r  = idx >> 3;
        int ch = idx & 7;
        uint32_t so = (uint32_t)r * AROWB + (uint32_t)ch * 16;
        size_t gA = (size_t)(rowBase + r) * K + k0 + ch * 8;
        cp_async16(sdst + so,         Ahi + gA);
        cp_async16(sdst + AMATB + so, Alo + gA);
    }
}

__device__ __forceinline__ void loadB_regs(float4* breg, const float* __restrict__ W,
                                           int Nw, int colBase, int k0, int tid)
{
    int r  = tid >> 2;
    int cq = tid & 3;
    const float* base = W + (size_t)(k0 + r) * Nw + colBase + cq * 4;
    #pragma unroll
    for (int i = 0; i < 8; i++)
        breg[i] = *reinterpret_cast<const float4*>(base + i * 16);
}

__device__ __forceinline__ void stsB(uint32_t bB, const float4* breg, int tid)
{
    int r  = tid >> 2;
    int cq = tid & 3;
    uint32_t base = bB + (uint32_t)r * BROWB + (uint32_t)cq * 8;
    #pragma unroll
    for (int i = 0; i < 8; i++) {
        float4 f = breg[i];
        uint2 uh, ul;
        split2(f.x, f.y, uh.x, ul.x);
        split2(f.z, f.w, uh.y, ul.y);
        uint32_t a = base + (uint32_t)i * 32;
        asm volatile("st.shared.v2.b32 [%0], {%1, %2};" :: "r"(a), "r"(uh.x), "r"(uh.y));
        asm volatile("st.shared.v2.b32 [%0], {%1, %2};" :: "r"(a + BHALF), "r"(ul.x), "r"(ul.y));
    }
}

template<int ACT, int OUTBF>
__global__ __launch_bounds__(256) void gemm_mma(const __nv_bfloat16* __restrict__ Ahi,
                                                const __nv_bfloat16* __restrict__ Alo,
                                                const float* __restrict__ W,
                                                const float* __restrict__ bias,
                                                float* __restrict__ C,
                                                __nv_bfloat16* __restrict__ Chi,
                                                __nv_bfloat16* __restrict__ Clo,
                                                int M, int Nw, int K, int ldC)
{
    extern __shared__ char smem[];
    const uint32_t sb = smem_u32(smem);
    const int tid  = threadIdx.x;
    const int wid  = tid >> 5;
    const int lane = tid & 31;
    const int rowBase = blockIdx.x * BM;
    const int colBase = blockIdx.y * BN;
    const int m0 = (wid >> 2) * 64;     // warp M offset
    const int n0 = (wid & 3) * 32;      // warp N offset
    const int g  = lane >> 3;
    const int lr = lane & 7;

    float acc[4][4][4];
    #pragma unroll
    for (int mt = 0; mt < 4; mt++)
        #pragma unroll
        for (int nt = 0; nt < 4; nt++)
            #pragma unroll
            for (int e = 0; e < 4; e++) acc[mt][nt][e] = 0.0f;

    const int KT = K / BK;   // >= 16 in all calls

    // Prologue: A0, A1 in flight; B0 stored to smem; B1 in regs.
    float4 breg[8];
    loadB_regs(breg, W, Nw, colBase, 0, tid);
    stage_loadA(sb,          Ahi, Alo, rowBase, K, 0,  tid);
    cp_commit();
    stage_loadA(sb + ASTAGE, Ahi, Alo, rowBase, K, BK, tid);
    cp_commit();
    stsB(sb + BBASE, breg, tid);
    loadB_regs(breg, W, Nw, colBase, BK, tid);

    int i0 = 0, i1 = 1, i2 = 2;   // rotating buffer indices (it, it+1, it+2 mod 3)

    for (int it = 0; it < KT; it++) {
        // Wait for A(it); keep A(it+1) in flight.
        if (it + 1 < KT) cp_wait1(); else cp_wait0();
        __syncthreads();   // B(it) stores + A-buffer reuse safety

        // Issue all future-stage traffic; it drains under the MMA burst.
        if (it + 2 < KT) {
            stage_loadA(sb + (uint32_t)i2 * ASTAGE, Ahi, Alo, rowBase, K, (it + 2) * BK, tid);
            cp_commit();
        }
        if (it + 1 < KT) stsB(sb + BBASE + (uint32_t)i1 * BSTG, breg, tid);
        if (it + 2 < KT) loadB_regs(breg, W, Nw, colBase, (it + 2) * BK, tid);

        const uint32_t aB = sb + (uint32_t)i0 * ASTAGE;
        const uint32_t bB = sb + BBASE + (uint32_t)i0 * BSTG;

        #pragma unroll
        for (int ks = 0; ks < 4; ks++) {
            uint32_t Ah[4][4], Al[4][4];
            #pragma unroll
            for (int mt = 0; mt < 4; mt++) {
                int r  = m0 + mt * 16 + (g & 1) * 8 + lr;
                int ch = ks * 2 + (g >> 1);
                uint32_t ad = aB + (uint32_t)r * AROWB + (uint32_t)ch * 16;
                ldmx4(ad,         Ah[mt][0], Ah[mt][1], Ah[mt][2], Ah[mt][3]);
                ldmx4(ad + AMATB, Al[mt][0], Al[mt][1], Al[mt][2], Al[mt][3]);
            }
            uint32_t Bh[4][2], Bl[4][2];
            #pragma unroll
            for (int p = 0; p < 2; p++) {
                int kr = ks * 16 + (lane & 15);
                int nc = n0 + p * 16 + (lane >> 4) * 8;
                uint32_t bd = bB + (uint32_t)kr * BROWB + (uint32_t)nc * 2;
                ldmx4t(bd,         Bh[2*p][0], Bh[2*p][1], Bh[2*p+1][0], Bh[2*p+1][1]);
                ldmx4t(bd + BHALF, Bl[2*p][0], Bl[2*p][1], Bl[2*p+1][0], Bl[2*p+1][1]);
            }
            #pragma unroll
            for (int mt = 0; mt < 4; mt++)
                #pragma unroll
                for (int nt = 0; nt < 4; nt++) {
                    mma_bf16(acc[mt][nt], Ah[mt], Bh[nt]);
                    mma_bf16(acc[mt][nt], Ah[mt], Bl[nt]);
                    mma_bf16(acc[mt][nt], Al[mt], Bh[nt]);
                }
        }

        // rotate buffers
        int t0 = i0; i0 = i1; i1 = i2; i2 = t0;
    }

    // Epilogue
    const int crow = lane >> 2;
    const int ccol = (lane & 3) * 2;
    #pragma unroll
    for (int mt = 0; mt < 4; mt++) {
        #pragma unroll
        for (int nt = 0; nt < 4; nt++) {
            int col = colBase + n0 + nt * 8 + ccol;
            float b0 = 0.0f, b1 = 0.0f;
            if (bias) { b0 = __ldg(bias + col); b1 = __ldg(bias + col + 1); }
            #pragma unroll
            for (int half = 0; half < 2; half++) {
                int row = rowBase + m0 + mt * 16 + crow + half * 8;
                float v0 = acc[mt][nt][half * 2 + 0] + b0;
                float v1 = acc[mt][nt][half * 2 + 1] + b1;
                if (ACT == 1) {
                    v0 = 0.5f * v0 * (1.0f + erff(v0 * 0.7071067811865476f));
                    v1 = 0.5f * v1 * (1.0f + erff(v1 * 0.7071067811865476f));
                }
                if (OUTBF) {
                    uint32_t hw, lw;
                    split2(v0, v1, hw, lw);
                    *reinterpret_cast<uint32_t*>(Chi + (size_t)row * ldC + col) = hw;
                    *reinterpret_cast<uint32_t*>(Clo + (size_t)row * ldC + col) = lw;
                } else {
                    *reinterpret_cast<float2*>(&C[(size_t)row * ldC + col]) = make_float2(v0, v1);
                }
            }
        }
    }
}

// ---------------------------------------------------------------------------
// Flash attention (fp32) on packed qkv [NT, 3072]; emits bf16 hi/lo ctx split.
// ---------------------------------------------------------------------------
__global__ __launch_bounds__(64) void attn_kernel(const float* __restrict__ QKV,
                                                  const int* __restrict__ x,
                                                  __nv_bfloat16* __restrict__ Ohi,
                                                  __nv_bfloat16* __restrict__ Olo)
{
    __shared__ float Ks[32][64];
    __shared__ float Vs[32][64];
    __shared__ int   validS[32];

    const int bh = blockIdx.x;
    const int b  = bh >> 4;
    const int h  = bh & 15;
    const int qt = blockIdx.y;
    const int tid = threadIdx.x;
    const int qrow = qt * 64 + tid;
    const int tQ = b * SS + qrow;

    const float* qp = QKV + (size_t)tQ * QKVW + h * DKH;
    float qreg[64], acc[64];
    #pragma unroll
    for (int d = 0; d < 64; d += 4) {
        float4 f = *reinterpret_cast<const float4*>(qp + d);
        qreg[d] = f.x; qreg[d+1] = f.y; qreg[d+2] = f.z; qreg[d+3] = f.w;
    }
    #pragma unroll
    for (int d = 0; d < 64; d++) acc[d] = 0.0f;

    float mrun = -1e30f, lsum = 0.0f;
    const int ntiles = 2 * qt + 2;

    for (int kt = 0; kt < ntiles; kt++) {
        const int kbase = kt * 32;
        #pragma unroll 4
        for (int i = 0; i < 32; i++) {
            size_t off = (size_t)(b * SS + kbase + i) * QKVW + h * DKH + tid;
            Ks[i][tid] = QKV[off + 1024];
            Vs[i][tid] = QKV[off + 2048];
        }
        if (tid < 32) validS[tid] = (x[b * SS + kbase + tid] != 0);
        __syncthreads();

        int jmax = qrow - kbase + 1;
        if (jmax > 32) jmax = 32;
        if (jmax > 0) {
            float s[32];
            float tmax = -1e30f;
            #pragma unroll
            for (int j = 0; j < 32; j++) {
                if (j < jmax) {
                    float sum = 0.0f;
                    const float4* kr = reinterpret_cast<const float4*>(Ks[j]);
                    #pragma unroll
                    for (int dq = 0; dq < 16; dq++) {
                        float4 k4 = kr[dq];
                        sum += qreg[4*dq]   * k4.x;
                        sum += qreg[4*dq+1] * k4.y;
                        sum += qreg[4*dq+2] * k4.z;
                        sum += qreg[4*dq+3] * k4.w;
                    }
                    sum *= 0.125f;
                    if (!validS[j]) sum = -1e30f;
                    s[j] = sum;
                    tmax = fmaxf(tmax, sum);
                } else {
                    s[j] = -1e30f;
                }
            }
            float mnew = fmaxf(mrun, tmax);
            float corr = __expf(mrun - mnew);
            lsum *= corr;
            #pragma unroll
            for (int d = 0; d < 64; d++) acc[d] *= corr;
            mrun = mnew;
            #pragma unroll
            for (int j = 0; j < 32; j++) {
                float p = __expf(s[j] - mrun);
                lsum += p;
                const float4* vr = reinterpret_cast<const float4*>(Vs[j]);
                #pragma unroll
                for (int dq = 0; dq < 16; dq++) {
                    float4 v4 = vr[dq];
                    acc[4*dq]   += p * v4.x;
                    acc[4*dq+1] += p * v4.y;
                    acc[4*dq+2] += p * v4.z;
                    acc[4*dq+3] += p * v4.w;
                }
            }
        }
        __syncthreads();
    }

    float inv = 1.0f / lsum;
    size_t ob = (size_t)tQ * DD + h * DKH;
    #pragma unroll
    for (int d = 0; d < 64; d += 2) {
        uint32_t hw, lw;
        split2(acc[d] * inv, acc[d+1] * inv, hw, lw);
        *reinterpret_cast<uint32_t*>(Ohi + ob + d) = hw;
        *reinterpret_cast<uint32_t*>(Olo + ob + d) = lw;
    }
}

// ---------------------------------------------------------------------------
// Residual add + LayerNorm (in place on h); also emits bf16 hi/lo split
// ---------------------------------------------------------------------------
__device__ __forceinline__ float block_sum(float v, float* red)
{
    #pragma unroll
    for (int o = 16; o > 0; o >>= 1) v += __shfl_xor_sync(0xffffffffu, v, o);
    int w = threadIdx.x >> 5;
    if ((threadIdx.x & 31) == 0) red[w] = v;
    __syncthreads();
    if (threadIdx.x < 32) {
        float t = (threadIdx.x < 8) ? red[threadIdx.x] : 0.0f;
        #pragma unroll
        for (int o = 4; o > 0; o >>= 1) t += __shfl_xor_sync(0xffffffffu, t, o);
        if (threadIdx.x == 0) red[0] = t;
    }
    __syncthreads();
    float r = red[0];
    __syncthreads();
    return r;
}

__global__ __launch_bounds__(256) void add_ln_kernel(float* __restrict__ h,
                                                     const float* __restrict__ r,
                                                     const float* __restrict__ g,
                                                     const float* __restrict__ bta,
                                                     __nv_bfloat16* __restrict__ ahi,
                                                     __nv_bfloat16* __restrict__ alo)
{
    __shared__ float red[32];
    const int t = blockIdx.x;
    const int tid = threadIdx.x;
    size_t base = (size_t)t * DD;
    float v[4];
    float sum = 0.0f;
    #pragma unroll
    for (int i = 0; i < 4; i++) {
        int d = tid * 2 + (i & 1) + (i >> 1) * 512;
        float val = h[base + d] + r[base + d];
        v[i] = val;
        sum += val;
    }
    float tot = block_sum(sum, red);
    float mu = tot * (1.0f / (float)DD);
    float sq = 0.0f;
    #pragma unroll
    for (int i = 0; i < 4; i++) { float dvi = v[i] - mu; sq += dvi * dvi; }
    float var = block_sum(sq, red) * (1.0f / (float)DD);
    float rs = rsqrtf(var + 1e-5f);
    #pragma unroll
    for (int p = 0; p < 2; p++) {
        int d = tid * 2 + p * 512;
        float o0 = (v[p*2]   - mu) * rs * g[d]     + bta[d];
        float o1 = (v[p*2+1] - mu) * rs * g[d + 1] + bta[d + 1];
        h[base + d]     = o0;
        h[base + d + 1] = o1;
        uint32_t hw, lw;
        split2(o0, o1, hw, lw);
        *reinterpret_cast<uint32_t*>(ahi + base + d) = hw;
        *reinterpret_cast<uint32_t*>(alo + base + d) = lw;
    }
}

// ---------------------------------------------------------------------------
// Launch
// ---------------------------------------------------------------------------
extern "C" void kernel_launch(void* const* d_in, const int* in_sizes, int n_in,
                              void* d_out, int out_size)
{
    const int*   x    = (const int*)  d_in[0];
    const float* emb  = (const float*)d_in[1];
    const float* Wq   = (const float*)d_in[2];
    const float* Wk   = (const float*)d_in[3];
    const float* Wv   = (const float*)d_in[4];
    const float* Wo   = (const float*)d_in[5];
    const float* bo   = (const float*)d_in[6];
    const float* ln1g = (const float*)d_in[7];
    const float* ln1b = (const float*)d_in[8];
    const float* ln2g = (const float*)d_in[9];
    const float* ln2b = (const float*)d_in[10];
    const float* W1   = (const float*)d_in[11];
    const float* b1   = (const float*)d_in[12];
    const float* W2   = (const float*)d_in[13];
    const float* b2   = (const float*)d_in[14];
    const float* Wout = (const float*)d_in[15];
    const float* bout = (const float*)d_in[16];
    float* out = (float*)d_out;

    void* p;
    cudaGetSymbolAddress(&p, g_h);   float* h   = (float*)p;
    cudaGetSymbolAddress(&p, g_qkv); float* qkv = (float*)p;
    cudaGetSymbolAddress(&p, g_tmp); float* tmp = (float*)p;
    cudaGetSymbolAddress(&p, g_ahi); __nv_bfloat16* ahi = (__nv_bfloat16*)p;
    cudaGetSymbolAddress(&p, g_alo); __nv_bfloat16* alo = (__nv_bfloat16*)p;
    cudaGetSymbolAddress(&p, g_fhi); __nv_bfloat16* fhi = (__nv_bfloat16*)p;
    cudaGetSymbolAddress(&p, g_flo); __nv_bfloat16* flo = (__nv_bfloat16*)p;

    cudaFuncSetAttribute(gemm_mma<0,0>, cudaFuncAttributeMaxDynamicSharedMemorySize, GEMM_SMEM);
    cudaFuncSetAttribute(gemm_mma<1,1>, cudaFuncAttributeMaxDynamicSharedMemorySize, GEMM_SMEM);

    embed_kernel<<<NT, 256>>>(x, emb, h, ahi, alo);

    const dim3 gD(NT/BM, DD/BN);     // 32 x 8
    const dim3 gF(NT/BM, FF/BN);     // 32 x 32
    const dim3 gV(NT/BM, VV/BN);     // 32 x 250

    for (int l = 0; l < LL; l++) {
        const float* wq = Wq + (size_t)l * DD * DD;
        const float* wk = Wk + (size_t)l * DD * DD;
        const float* wv = Wv + (size_t)l * DD * DD;
        const float* wo = Wo + (size_t)l * DD * DD;
        const float* w1 = W1 + (size_t)l * DD * FF;
        const float* w2 = W2 + (size_t)l * FF * DD;

        // QKV projections (C strided into packed qkv buffer)
        gemm_mma<0,0><<<gD, 256, GEMM_SMEM>>>(ahi, alo, wq, nullptr, qkv,        nullptr, nullptr, NT, DD, DD, QKVW);
        gemm_mma<0,0><<<gD, 256, GEMM_SMEM>>>(ahi, alo, wk, nullptr, qkv + 1024, nullptr, nullptr, NT, DD, DD, QKVW);
        gemm_mma<0,0><<<gD, 256, GEMM_SMEM>>>(ahi, alo, wv, nullptr, qkv + 2048, nullptr, nullptr, NT, DD, DD, QKVW);

        attn_kernel<<<dim3(BB * HH, SS / 64), 64>>>(qkv, x, ahi, alo);   // ctx split

        gemm_mma<0,0><<<gD, 256, GEMM_SMEM>>>(ahi, alo, wo, bo + l * DD, tmp, nullptr, nullptr, NT, DD, DD, DD);
        add_ln_kernel<<<NT, 256>>>(h, tmp, ln1g + l * DD, ln1b + l * DD, ahi, alo);

        gemm_mma<1,1><<<gF, 256, GEMM_SMEM>>>(ahi, alo, w1, b1 + l * FF, nullptr, fhi, flo, NT, FF, DD, FF);
        gemm_mma<0,0><<<gD, 256, GEMM_SMEM>>>(fhi, flo, w2, b2 + l * DD, tmp, nullptr, nullptr, NT, DD, FF, DD);
        add_ln_kernel<<<NT, 256>>>(h, tmp, ln2g + l * DD, ln2b + l * DD, ahi, alo);
    }

    gemm_mma<0,0><<<gV, 256, GEMM_SMEM>>>(ahi, alo, Wout, bout, out, nullptr, nullptr, NT, VV, DD, VV);
}

// round 6
// speedup vs baseline: 1.2798x; 1.2798x over previous
#include <cuda_runtime.h>
#include <cuda_fp16.h>
#include <cstdint>
#include <cmath>

// Problem constants
#define BB   4
#define SS   1024
#define DD   1024
#define HH   16
#define DKH  64
#define LL   4
#define FF   4096
#define VV   32000
#define NT   (BB*SS)   // 4096 tokens
#define QKVW 3072      // packed q|k|v width

// GEMM tile config (mma.sync path, fp16 2-term split)
#define BM 128
#define BN 128
#define BK 64                      // fp16 elems per k-stage
#define AROWB 144                  // A smem row: 128B data + 16B pad
#define AMATB (128*AROWB)          // one 128xBK fp16 matrix: 18432 B
#define BROWB 272                  // B smem row: 256B data + 16B pad
#define BHALF (64*BROWB)           // one 64x128 fp16 matrix: 17408 B
#define BBASE (2*AMATB)            // 36864 (A double-buffered)
#define GEMM_SMEM (BBASE + 2*BHALF)   // 71680 B

// ---------------------------------------------------------------------------
// Scratch (device globals — no runtime allocation allowed)
// ---------------------------------------------------------------------------
__device__ float g_h  [NT*(size_t)DD];
__device__ float g_qkv[NT*(size_t)QKVW];
__device__ float g_tmp[NT*(size_t)DD];
__device__ __half g_ah [NT*(size_t)DD];
__device__ __half g_fh [NT*(size_t)FF];

// ---------------------------------------------------------------------------
// PTX helpers (arch-agnostic: sm_80-era instructions only)
// ---------------------------------------------------------------------------
__device__ __forceinline__ uint32_t smem_u32(const void* p) {
    uint32_t a;
    asm("{ .reg .u64 t; cvta.to.shared.u64 t, %1; cvt.u32.u64 %0, t; }" : "=r"(a) : "l"(p));
    return a;
}
__device__ __forceinline__ void cp_async16(uint32_t dst, const void* src) {
    asm volatile("cp.async.cg.shared.global [%0], [%1], 16;" :: "r"(dst), "l"(src));
}
__device__ __forceinline__ void cp_commit() {
    asm volatile("cp.async.commit_group;");
}
__device__ __forceinline__ void cp_wait1() {
    asm volatile("cp.async.wait_group 1;");
}
__device__ __forceinline__ void cp_wait0() {
    asm volatile("cp.async.wait_group 0;");
}
__device__ __forceinline__ void ldmx4(uint32_t addr, uint32_t& r0, uint32_t& r1,
                                      uint32_t& r2, uint32_t& r3) {
    asm volatile("ldmatrix.sync.aligned.m8n8.x4.shared.b16 {%0,%1,%2,%3}, [%4];"
                 : "=r"(r0), "=r"(r1), "=r"(r2), "=r"(r3) : "r"(addr));
}
__device__ __forceinline__ void ldmx4t(uint32_t addr, uint32_t& r0, uint32_t& r1,
                                       uint32_t& r2, uint32_t& r3) {
    asm volatile("ldmatrix.sync.aligned.m8n8.x4.trans.shared.b16 {%0,%1,%2,%3}, [%4];"
                 : "=r"(r0), "=r"(r1), "=r"(r2), "=r"(r3) : "r"(addr));
}
__device__ __forceinline__ void mma_f16(float* c, const uint32_t* a, const uint32_t* b) {
    asm volatile("mma.sync.aligned.m16n8k16.row.col.f32.f16.f16.f32 "
                 "{%0,%1,%2,%3}, {%4,%5,%6,%7}, {%8,%9}, {%0,%1,%2,%3};"
                 : "+f"(c[0]), "+f"(c[1]), "+f"(c[2]), "+f"(c[3])
                 : "r"(a[0]), "r"(a[1]), "r"(a[2]), "r"(a[3]), "r"(b[0]), "r"(b[1]));
}
__device__ __forceinline__ uint32_t h2_bits(__half2 v) {
    return *reinterpret_cast<uint32_t*>(&v);
}
// split a float pair into fp16 hi/lo words (hi + lo ~= x to ~2^-22)
__device__ __forceinline__ void split2h(float a, float b, uint32_t& hw, uint32_t& lw) {
    __half2 h = __floats2half2_rn(a, b);
    float la = a - __low2float(h);
    float lb = b - __high2float(h);
    __half2 l = __floats2half2_rn(la, lb);
    hw = h2_bits(h);
    lw = h2_bits(l);
}
__device__ __forceinline__ uint32_t pack_h2(float a, float b) {
    return h2_bits(__floats2half2_rn(a, b));
}

// ---------------------------------------------------------------------------
// Embedding + positional encoding; writes fp32 h AND fp16 activation plane
// ---------------------------------------------------------------------------
__global__ __launch_bounds__(256) void embed_kernel(const int* __restrict__ x,
                                                    const float* __restrict__ emb,
                                                    float* __restrict__ h,
                                                    __half* __restrict__ ah)
{
    int t = blockIdx.x;
    int s = t & (SS - 1);
    int tok = x[t];
    const float* e = emb + (size_t)tok * DD;
    const float negln = -9.210340371976184f;
    size_t base = (size_t)t * DD;
    for (int d0 = threadIdx.x * 2; d0 < DD; d0 += blockDim.x * 2) {
        float v[2];
        #pragma unroll
        for (int j = 0; j < 2; j++) {
            int d = d0 + j;
            int i2 = (d >> 1) * 2;
            float div = expf((float)i2 * (negln / (float)DD));
            float ang = (float)s * div;
            float pe = (d & 1) ? cosf(ang) : sinf(ang);
            v[j] = e[d] * 32.0f + pe;
        }
        h[base + d0] = v[0];
        h[base + d0 + 1] = v[1];
        *reinterpret_cast<uint32_t*>(ah + base + d0) = pack_h2(v[0], v[1]);
    }
}

// ---------------------------------------------------------------------------
// fp16x2 GEMM via mma.sync: C[M,N] = A[M,K] @ W[K,N] (+bias)(+GELU)
// A: fp16 [M,K]. W: fp32 [K,N], split on the fly into fp16 hi/lo.
// BM=BN=128, BK=64, 256 threads (8 warps, 64x32 warp tiles).
// A double-buffered (cp.async); B through regs (LDG->cvt->STS), 2 MMAs/tile.
// Optional 3-way W select (fused QKV) via blockIdx.y>>3.
// ---------------------------------------------------------------------------
__device__ __forceinline__ void stage_loadA(uint32_t sdst, const __half* A,
                                            int rowBase, int K, int k0, int tid)
{
    #pragma unroll
    for (int i = 0; i < 4; i++) {
        int idx = tid + i * 256;           // 0..1023
        int r  = idx >> 3;
        int ch = idx & 7;
        uint32_t so = (uint32_t)r * AROWB + (uint32_t)ch * 16;
        cp_async16(sdst + so, A + (size_t)(rowBase + r) * K + k0 + ch * 8);
    }
}

__device__ __forceinline__ void loadB_regs(float4* breg, const float* __restrict__ W,
                                           int Nw, int colW, int k0, int tid)
{
    int r  = tid >> 2;
    int cq = tid & 3;
    const float* base = W + (size_t)(k0 + r) * Nw + colW + cq * 4;
    #pragma unroll
    for (int i = 0; i < 8; i++)
        breg[i] = *reinterpret_cast<const float4*>(base + i * 16);
}

__device__ __forceinline__ void stsB(uint32_t bB, const float4* breg, int tid)
{
    int r  = tid >> 2;
    int cq = tid & 3;
    uint32_t base = bB + (uint32_t)r * BROWB + (uint32_t)cq * 8;
    #pragma unroll
    for (int i = 0; i < 8; i++) {
        float4 f = breg[i];
        uint2 uh, ul;
        split2h(f.x, f.y, uh.x, ul.x);
        split2h(f.z, f.w, uh.y, ul.y);
        uint32_t a = base + (uint32_t)i * 32;
        asm volatile("st.shared.v2.b32 [%0], {%1, %2};" :: "r"(a), "r"(uh.x), "r"(uh.y));
        asm volatile("st.shared.v2.b32 [%0], {%1, %2};" :: "r"(a + BHALF), "r"(ul.x), "r"(ul.y));
    }
}

template<int ACT, int OUTH>
__global__ __launch_bounds__(256) void gemm_mma(const __half* __restrict__ A,
                                                const float* __restrict__ W,
                                                const float* __restrict__ Wb,
                                                const float* __restrict__ Wc,
                                                const float* __restrict__ bias,
                                                float* __restrict__ C,
                                                __half* __restrict__ Ch,
                                                int M, int Nw, int K, int ldC)
{
    extern __shared__ char smem[];
    const uint32_t sb = smem_u32(smem);
    const int tid  = threadIdx.x;
    const int wid  = tid >> 5;
    const int lane = tid & 31;
    const int rowBase = blockIdx.x * BM;

    const float* Wuse = W;
    int colW;
    if (Wb) {
        int wsel = blockIdx.y >> 3;
        Wuse = (wsel == 0) ? W : ((wsel == 1) ? Wb : Wc);
        colW = (blockIdx.y & 7) * BN;
    } else {
        colW = blockIdx.y * BN;
    }
    const int colC = blockIdx.y * BN;

    const int m0 = (wid >> 2) * 64;     // warp M offset
    const int n0 = (wid & 3) * 32;      // warp N offset
    const int g  = lane >> 3;
    const int lr = lane & 7;

    float acc[4][4][4];
    #pragma unroll
    for (int mt = 0; mt < 4; mt++)
        #pragma unroll
        for (int nt = 0; nt < 4; nt++)
            #pragma unroll
            for (int e = 0; e < 4; e++) acc[mt][nt][e] = 0.0f;

    const int KT = K / BK;
    const uint32_t bB = sb + BBASE;

    float4 breg[8];
    loadB_regs(breg, Wuse, Nw, colW, 0, tid);
    stage_loadA(sb, A, rowBase, K, 0, tid);
    cp_commit();

    for (int it = 0; it < KT; it++) {
        const int buf = it & 1;
        if (it + 1 < KT) {
            stage_loadA(sb + (buf ^ 1) * AMATB, A, rowBase, K, (it + 1) * BK, tid);
            cp_commit();
            cp_wait1();
        } else {
            cp_wait0();
        }
        stsB(bB, breg, tid);
        __syncthreads();
        if (it + 1 < KT) loadB_regs(breg, Wuse, Nw, colW, (it + 1) * BK, tid);

        const uint32_t aB = sb + buf * AMATB;
        #pragma unroll
        for (int ks = 0; ks < 4; ks++) {
            uint32_t Af[4][4];
            #pragma unroll
            for (int mt = 0; mt < 4; mt++) {
                int r  = m0 + mt * 16 + (g & 1) * 8 + lr;
                int ch = ks * 2 + (g >> 1);
                uint32_t ad = aB + (uint32_t)r * AROWB + (uint32_t)ch * 16;
                ldmx4(ad, Af[mt][0], Af[mt][1], Af[mt][2], Af[mt][3]);
            }
            uint32_t Bh[4][2], Bl[4][2];
            #pragma unroll
            for (int p = 0; p < 2; p++) {
                int kr = ks * 16 + (lane & 15);
                int nc = n0 + p * 16 + (lane >> 4) * 8;
                uint32_t bd = bB + (uint32_t)kr * BROWB + (uint32_t)nc * 2;
                ldmx4t(bd,         Bh[2*p][0], Bh[2*p][1], Bh[2*p+1][0], Bh[2*p+1][1]);
                ldmx4t(bd + BHALF, Bl[2*p][0], Bl[2*p][1], Bl[2*p+1][0], Bl[2*p+1][1]);
            }
            #pragma unroll
            for (int mt = 0; mt < 4; mt++)
                #pragma unroll
                for (int nt = 0; nt < 4; nt++) {
                    mma_f16(acc[mt][nt], Af[mt], Bh[nt]);
                    mma_f16(acc[mt][nt], Af[mt], Bl[nt]);
                }
        }
        __syncthreads();
    }

    // Epilogue
    const int crow = lane >> 2;
    const int ccol = (lane & 3) * 2;
    #pragma unroll
    for (int mt = 0; mt < 4; mt++) {
        #pragma unroll
        for (int nt = 0; nt < 4; nt++) {
            int col = colC + n0 + nt * 8 + ccol;
            float b0 = 0.0f, b1 = 0.0f;
            if (bias) { b0 = __ldg(bias + col); b1 = __ldg(bias + col + 1); }
            #pragma unroll
            for (int half = 0; half < 2; half++) {
                int row = rowBase + m0 + mt * 16 + crow + half * 8;
                float v0 = acc[mt][nt][half * 2 + 0] + b0;
                float v1 = acc[mt][nt][half * 2 + 1] + b1;
                if (ACT == 1) {
                    v0 = 0.5f * v0 * (1.0f + erff(v0 * 0.7071067811865476f));
                    v1 = 0.5f * v1 * (1.0f + erff(v1 * 0.7071067811865476f));
                }
                if (OUTH) {
                    *reinterpret_cast<uint32_t*>(Ch + (size_t)row * ldC + col) = pack_h2(v0, v1);
                } else {
                    *reinterpret_cast<float2*>(&C[(size_t)row * ldC + col]) = make_float2(v0, v1);
                }
            }
        }
    }
}

// ---------------------------------------------------------------------------
// Flash attention (fp32) on packed qkv [NT, 3072]; emits fp16 ctx plane.
// ---------------------------------------------------------------------------
__global__ __launch_bounds__(64) void attn_kernel(const float* __restrict__ QKV,
                                                  const int* __restrict__ x,
                                                  __half* __restrict__ Oh)
{
    __shared__ float Ks[32][64];
    __shared__ float Vs[32][64];
    __shared__ int   validS[32];

    const int bh = blockIdx.x;
    const int b  = bh >> 4;
    const int h  = bh & 15;
    const int qt = blockIdx.y;
    const int tid = threadIdx.x;
    const int qrow = qt * 64 + tid;
    const int tQ = b * SS + qrow;

    const float* qp = QKV + (size_t)tQ * QKVW + h * DKH;
    float qreg[64], acc[64];
    #pragma unroll
    for (int d = 0; d < 64; d += 4) {
        float4 f = *reinterpret_cast<const float4*>(qp + d);
        qreg[d] = f.x; qreg[d+1] = f.y; qreg[d+2] = f.z; qreg[d+3] = f.w;
    }
    #pragma unroll
    for (int d = 0; d < 64; d++) acc[d] = 0.0f;

    float mrun = -1e30f, lsum = 0.0f;
    const int ntiles = 2 * qt + 2;

    for (int kt = 0; kt < ntiles; kt++) {
        const int kbase = kt * 32;
        #pragma unroll 4
        for (int i = 0; i < 32; i++) {
            size_t off = (size_t)(b * SS + kbase + i) * QKVW + h * DKH + tid;
            Ks[i][tid] = QKV[off + 1024];
            Vs[i][tid] = QKV[off + 2048];
        }
        if (tid < 32) validS[tid] = (x[b * SS + kbase + tid] != 0);
        __syncthreads();

        int jmax = qrow - kbase + 1;
        if (jmax > 32) jmax = 32;
        if (jmax > 0) {
            float s[32];
            float tmax = -1e30f;
            #pragma unroll
            for (int j = 0; j < 32; j++) {
                if (j < jmax) {
                    float sum = 0.0f;
                    const float4* kr = reinterpret_cast<const float4*>(Ks[j]);
                    #pragma unroll
                    for (int dq = 0; dq < 16; dq++) {
                        float4 k4 = kr[dq];
                        sum += qreg[4*dq]   * k4.x;
                        sum += qreg[4*dq+1] * k4.y;
                        sum += qreg[4*dq+2] * k4.z;
                        sum += qreg[4*dq+3] * k4.w;
                    }
                    sum *= 0.125f;
                    if (!validS[j]) sum = -1e30f;
                    s[j] = sum;
                    tmax = fmaxf(tmax, sum);
                } else {
                    s[j] = -1e30f;
                }
            }
            float mnew = fmaxf(mrun, tmax);
            float corr = __expf(mrun - mnew);
            lsum *= corr;
            #pragma unroll
            for (int d = 0; d < 64; d++) acc[d] *= corr;
            mrun = mnew;
            #pragma unroll
            for (int j = 0; j < 32; j++) {
                float p = __expf(s[j] - mrun);
                lsum += p;
                const float4* vr = reinterpret_cast<const float4*>(Vs[j]);
                #pragma unroll
                for (int dq = 0; dq < 16; dq++) {
                    float4 v4 = vr[dq];
                    acc[4*dq]   += p * v4.x;
                    acc[4*dq+1] += p * v4.y;
                    acc[4*dq+2] += p * v4.z;
                    acc[4*dq+3] += p * v4.w;
                }
            }
        }
        __syncthreads();
    }

    float inv = 1.0f / lsum;
    size_t ob = (size_t)tQ * DD + h * DKH;
    #pragma unroll
    for (int d = 0; d < 64; d += 2) {
        *reinterpret_cast<uint32_t*>(Oh + ob + d) = pack_h2(acc[d] * inv, acc[d+1] * inv);
    }
}

// ---------------------------------------------------------------------------
// Residual add + LayerNorm (in place on h); also emits fp16 activation plane
// ---------------------------------------------------------------------------
__device__ __forceinline__ float block_sum(float v, float* red)
{
    #pragma unroll
    for (int o = 16; o > 0; o >>= 1) v += __shfl_xor_sync(0xffffffffu, v, o);
    int w = threadIdx.x >> 5;
    if ((threadIdx.x & 31) == 0) red[w] = v;
    __syncthreads();
    if (threadIdx.x < 32) {
        float t = (threadIdx.x < 8) ? red[threadIdx.x] : 0.0f;
        #pragma unroll
        for (int o = 4; o > 0; o >>= 1) t += __shfl_xor_sync(0xffffffffu, t, o);
        if (threadIdx.x == 0) red[0] = t;
    }
    __syncthreads();
    float r = red[0];
    __syncthreads();
    return r;
}

__global__ __launch_bounds__(256) void add_ln_kernel(float* __restrict__ h,
                                                     const float* __restrict__ r,
                                                     const float* __restrict__ g,
                                                     const float* __restrict__ bta,
                                                     __half* __restrict__ ah)
{
    __shared__ float red[32];
    const int t = blockIdx.x;
    const int tid = threadIdx.x;
    size_t base = (size_t)t * DD;
    float v[4];
    float sum = 0.0f;
    #pragma unroll
    for (int i = 0; i < 4; i++) {
        int d = tid * 2 + (i & 1) + (i >> 1) * 512;
        float val = h[base + d] + r[base + d];
        v[i] = val;
        sum += val;
    }
    float tot = block_sum(sum, red);
    float mu = tot * (1.0f / (float)DD);
    float sq = 0.0f;
    #pragma unroll
    for (int i = 0; i < 4; i++) { float dvi = v[i] - mu; sq += dvi * dvi; }
    float var = block_sum(sq, red) * (1.0f / (float)DD);
    float rs = rsqrtf(var + 1e-5f);
    #pragma unroll
    for (int p = 0; p < 2; p++) {
        int d = tid * 2 + p * 512;
        float o0 = (v[p*2]   - mu) * rs * g[d]     + bta[d];
        float o1 = (v[p*2+1] - mu) * rs * g[d + 1] + bta[d + 1];
        h[base + d]     = o0;
        h[base + d + 1] = o1;
        *reinterpret_cast<uint32_t*>(ah + base + d) = pack_h2(o0, o1);
    }
}

// ---------------------------------------------------------------------------
// Launch
// ---------------------------------------------------------------------------
extern "C" void kernel_launch(void* const* d_in, const int* in_sizes, int n_in,
                              void* d_out, int out_size)
{
    const int*   x    = (const int*)  d_in[0];
    const float* emb  = (const float*)d_in[1];
    const float* Wq   = (const float*)d_in[2];
    const float* Wk   = (const float*)d_in[3];
    const float* Wv   = (const float*)d_in[4];
    const float* Wo   = (const float*)d_in[5];
    const float* bo   = (const float*)d_in[6];
    const float* ln1g = (const float*)d_in[7];
    const float* ln1b = (const float*)d_in[8];
    const float* ln2g = (const float*)d_in[9];
    const float* ln2b = (const float*)d_in[10];
    const float* W1   = (const float*)d_in[11];
    const float* b1   = (const float*)d_in[12];
    const float* W2   = (const float*)d_in[13];
    const float* b2   = (const float*)d_in[14];
    const float* Wout = (const float*)d_in[15];
    const float* bout = (const float*)d_in[16];
    float* out = (float*)d_out;

    void* p;
    cudaGetSymbolAddress(&p, g_h);   float* h   = (float*)p;
    cudaGetSymbolAddress(&p, g_qkv); float* qkv = (float*)p;
    cudaGetSymbolAddress(&p, g_tmp); float* tmp = (float*)p;
    cudaGetSymbolAddress(&p, g_ah);  __half* ah = (__half*)p;
    cudaGetSymbolAddress(&p, g_fh);  __half* fh = (__half*)p;

    cudaFuncSetAttribute(gemm_mma<0,0>, cudaFuncAttributeMaxDynamicSharedMemorySize, GEMM_SMEM);
    cudaFuncSetAttribute(gemm_mma<1,1>, cudaFuncAttributeMaxDynamicSharedMemorySize, GEMM_SMEM);

    embed_kernel<<<NT, 256>>>(x, emb, h, ah);

    const dim3 gQKV(NT/BM, QKVW/BN);  // 32 x 24 (fused q|k|v)
    const dim3 gD(NT/BM, DD/BN);      // 32 x 8
    const dim3 gF(NT/BM, FF/BN);      // 32 x 32
    const dim3 gV(NT/BM, VV/BN);      // 32 x 250

    for (int l = 0; l < LL; l++) {
        const float* wq = Wq + (size_t)l * DD * DD;
        const float* wk = Wk + (size_t)l * DD * DD;
        const float* wv = Wv + (size_t)l * DD * DD;
        const float* wo = Wo + (size_t)l * DD * DD;
        const float* w1 = W1 + (size_t)l * DD * FF;
        const float* w2 = W2 + (size_t)l * FF * DD;

        // Fused QKV projection (one launch, W selected per block)
        gemm_mma<0,0><<<gQKV, 256, GEMM_SMEM>>>(ah, wq, wk, wv, nullptr, qkv, nullptr, NT, DD, DD, QKVW);

        attn_kernel<<<dim3(BB * HH, SS / 64), 64>>>(qkv, x, ah);   // ctx -> fp16 plane

        gemm_mma<0,0><<<gD, 256, GEMM_SMEM>>>(ah, wo, nullptr, nullptr, bo + l * DD, tmp, nullptr, NT, DD, DD, DD);
        add_ln_kernel<<<NT, 256>>>(h, tmp, ln1g + l * DD, ln1b + l * DD, ah);

        gemm_mma<1,1><<<gF, 256, GEMM_SMEM>>>(ah, w1, nullptr, nullptr, b1 + l * FF, nullptr, fh, NT, FF, DD, FF);
        gemm_mma<0,0><<<gD, 256, GEMM_SMEM>>>(fh, w2, nullptr, nullptr, b2 + l * DD, tmp, nullptr, NT, DD, FF, DD);
        add_ln_kernel<<<NT, 256>>>(h, tmp, ln2g + l * DD, ln2b + l * DD, ah);
    }

    gemm_mma<0,0><<<gV, 256, GEMM_SMEM>>>(ah, Wout, nullptr, nullptr, bout, out, nullptr, NT, VV, DD, VV);
}

// round 7
// speedup vs baseline: 1.4068x; 1.0993x over previous
#include <cuda_runtime.h>
#include <cuda_fp16.h>
#include <cstdint>
#include <cmath>

// Problem constants
#define BB   4
#define SS   1024
#define DD   1024
#define HH   16
#define DKH  64
#define LL   4
#define FF   4096
#define VV   32000
#define NT   (BB*SS)   // 4096 tokens
#define QKVW 3072      // packed q|k|v width

// GEMM tile config (mma.sync path, fp16 2-term split)
#define BM 128
#define BN 128
#define BK 64                      // fp16 elems per k-stage
#define AROWB 144                  // A smem row: 128B data + 16B pad
#define AMATB (128*AROWB)          // one 128xBK fp16 matrix: 18432 B
#define BROWB 272                  // B smem row: 256B data + 16B pad
#define BHALF (64*BROWB)           // one 64x128 fp16 matrix: 17408 B
#define BBASE (2*AMATB)            // 36864 (A double-buffered)
#define GEMM_SMEM (BBASE + 2*BHALF)   // 71680 B  (2 CTAs/SM fit: 143360 < 228KB)

// ---------------------------------------------------------------------------
// Scratch (device globals — no runtime allocation allowed)
// ---------------------------------------------------------------------------
__device__ float g_h  [NT*(size_t)DD];
__device__ float g_qkv[NT*(size_t)QKVW];
__device__ float g_tmp[NT*(size_t)DD];
__device__ __half g_ah [NT*(size_t)DD];
__device__ __half g_fh [NT*(size_t)FF];

// ---------------------------------------------------------------------------
// PTX helpers (arch-agnostic: sm_80-era instructions only)
// ---------------------------------------------------------------------------
__device__ __forceinline__ uint32_t smem_u32(const void* p) {
    uint32_t a;
    asm("{ .reg .u64 t; cvta.to.shared.u64 t, %1; cvt.u32.u64 %0, t; }" : "=r"(a) : "l"(p));
    return a;
}
__device__ __forceinline__ void cp_async16(uint32_t dst, const void* src) {
    asm volatile("cp.async.cg.shared.global [%0], [%1], 16;" :: "r"(dst), "l"(src));
}
__device__ __forceinline__ void cp_commit() {
    asm volatile("cp.async.commit_group;");
}
__device__ __forceinline__ void cp_wait1() {
    asm volatile("cp.async.wait_group 1;");
}
__device__ __forceinline__ void cp_wait0() {
    asm volatile("cp.async.wait_group 0;");
}
__device__ __forceinline__ void ldmx4(uint32_t addr, uint32_t& r0, uint32_t& r1,
                                      uint32_t& r2, uint32_t& r3) {
    asm volatile("ldmatrix.sync.aligned.m8n8.x4.shared.b16 {%0,%1,%2,%3}, [%4];"
                 : "=r"(r0), "=r"(r1), "=r"(r2), "=r"(r3) : "r"(addr));
}
__device__ __forceinline__ void ldmx4t(uint32_t addr, uint32_t& r0, uint32_t& r1,
                                       uint32_t& r2, uint32_t& r3) {
    asm volatile("ldmatrix.sync.aligned.m8n8.x4.trans.shared.b16 {%0,%1,%2,%3}, [%4];"
                 : "=r"(r0), "=r"(r1), "=r"(r2), "=r"(r3) : "r"(addr));
}
__device__ __forceinline__ void mma_f16(float* c, const uint32_t* a, const uint32_t* b) {
    asm volatile("mma.sync.aligned.m16n8k16.row.col.f32.f16.f16.f32 "
                 "{%0,%1,%2,%3}, {%4,%5,%6,%7}, {%8,%9}, {%0,%1,%2,%3};"
                 : "+f"(c[0]), "+f"(c[1]), "+f"(c[2]), "+f"(c[3])
                 : "r"(a[0]), "r"(a[1]), "r"(a[2]), "r"(a[3]), "r"(b[0]), "r"(b[1]));
}
__device__ __forceinline__ uint32_t h2_bits(__half2 v) {
    return *reinterpret_cast<uint32_t*>(&v);
}
// split a float pair into fp16 hi/lo words (hi + lo ~= x to ~2^-22)
__device__ __forceinline__ void split2h(float a, float b, uint32_t& hw, uint32_t& lw) {
    __half2 h = __floats2half2_rn(a, b);
    float la = a - __low2float(h);
    float lb = b - __high2float(h);
    __half2 l = __floats2half2_rn(la, lb);
    hw = h2_bits(h);
    lw = h2_bits(l);
}
__device__ __forceinline__ uint32_t pack_h2(float a, float b) {
    return h2_bits(__floats2half2_rn(a, b));
}

// ---------------------------------------------------------------------------
// Embedding + positional encoding; writes fp32 h AND fp16 activation plane
// ---------------------------------------------------------------------------
__global__ __launch_bounds__(256) void embed_kernel(const int* __restrict__ x,
                                                    const float* __restrict__ emb,
                                                    float* __restrict__ h,
                                                    __half* __restrict__ ah)
{
    int t = blockIdx.x;
    int s = t & (SS - 1);
    int tok = x[t];
    const float* e = emb + (size_t)tok * DD;
    const float negln = -9.210340371976184f;
    size_t base = (size_t)t * DD;
    for (int d0 = threadIdx.x * 2; d0 < DD; d0 += blockDim.x * 2) {
        float v[2];
        #pragma unroll
        for (int j = 0; j < 2; j++) {
            int d = d0 + j;
            int i2 = (d >> 1) * 2;
            float div = expf((float)i2 * (negln / (float)DD));
            float ang = (float)s * div;
            float pe = (d & 1) ? cosf(ang) : sinf(ang);
            v[j] = e[d] * 32.0f + pe;
        }
        h[base + d0] = v[0];
        h[base + d0 + 1] = v[1];
        *reinterpret_cast<uint32_t*>(ah + base + d0) = pack_h2(v[0], v[1]);
    }
}

// ---------------------------------------------------------------------------
// fp16x2 GEMM via mma.sync: C[M,N] = A[M,K] @ W[K,N] (+bias)(+GELU)
// A: fp16 [M,K]. W: fp32 [K,N], split on the fly into fp16 hi/lo.
// BM=BN=128, BK=64, 256 threads (8 warps, 64x32 warp tiles), 2 CTAs/SM.
// ---------------------------------------------------------------------------
__device__ __forceinline__ void stage_loadA(uint32_t sdst, const __half* A,
                                            int rowBase, int K, int k0, int tid)
{
    #pragma unroll
    for (int i = 0; i < 4; i++) {
        int idx = tid + i * 256;           // 0..1023
        int r  = idx >> 3;
        int ch = idx & 7;
        uint32_t so = (uint32_t)r * AROWB + (uint32_t)ch * 16;
        cp_async16(sdst + so, A + (size_t)(rowBase + r) * K + k0 + ch * 8);
    }
}

__device__ __forceinline__ void loadB_regs(float4* breg, const float* __restrict__ W,
                                           int Nw, int colW, int k0, int tid)
{
    int r  = tid >> 2;
    int cq = tid & 3;
    const float* base = W + (size_t)(k0 + r) * Nw + colW + cq * 4;
    #pragma unroll
    for (int i = 0; i < 8; i++)
        breg[i] = *reinterpret_cast<const float4*>(base + i * 16);
}

__device__ __forceinline__ void stsB(uint32_t bB, const float4* breg, int tid)
{
    int r  = tid >> 2;
    int cq = tid & 3;
    uint32_t base = bB + (uint32_t)r * BROWB + (uint32_t)cq * 8;
    #pragma unroll
    for (int i = 0; i < 8; i++) {
        float4 f = breg[i];
        uint2 uh, ul;
        split2h(f.x, f.y, uh.x, ul.x);
        split2h(f.z, f.w, uh.y, ul.y);
        uint32_t a = base + (uint32_t)i * 32;
        asm volatile("st.shared.v2.b32 [%0], {%1, %2};" :: "r"(a), "r"(uh.x), "r"(uh.y));
        asm volatile("st.shared.v2.b32 [%0], {%1, %2};" :: "r"(a + BHALF), "r"(ul.x), "r"(ul.y));
    }
}

template<int ACT, int OUTH>
__global__ __launch_bounds__(256, 2) void gemm_mma(const __half* __restrict__ A,
                                                   const float* __restrict__ W,
                                                   const float* __restrict__ Wb,
                                                   const float* __restrict__ Wc,
                                                   const float* __restrict__ bias,
                                                   float* __restrict__ C,
                                                   __half* __restrict__ Ch,
                                                   int M, int Nw, int K, int ldC)
{
    extern __shared__ char smem[];
    const uint32_t sb = smem_u32(smem);
    const int tid  = threadIdx.x;
    const int wid  = tid >> 5;
    const int lane = tid & 31;
    const int rowBase = blockIdx.x * BM;

    const float* Wuse = W;
    int colW;
    if (Wb) {
        int wsel = blockIdx.y >> 3;
        Wuse = (wsel == 0) ? W : ((wsel == 1) ? Wb : Wc);
        colW = (blockIdx.y & 7) * BN;
    } else {
        colW = blockIdx.y * BN;
    }
    const int colC = blockIdx.y * BN;

    const int m0 = (wid >> 2) * 64;     // warp M offset
    const int n0 = (wid & 3) * 32;      // warp N offset
    const int g  = lane >> 3;
    const int lr = lane & 7;

    float acc[4][4][4];
    #pragma unroll
    for (int mt = 0; mt < 4; mt++)
        #pragma unroll
        for (int nt = 0; nt < 4; nt++)
            #pragma unroll
            for (int e = 0; e < 4; e++) acc[mt][nt][e] = 0.0f;

    const int KT = K / BK;
    const uint32_t bB = sb + BBASE;

    float4 breg[8];
    loadB_regs(breg, Wuse, Nw, colW, 0, tid);
    stage_loadA(sb, A, rowBase, K, 0, tid);
    cp_commit();

    for (int it = 0; it < KT; it++) {
        const int buf = it & 1;
        if (it + 1 < KT) {
            stage_loadA(sb + (buf ^ 1) * AMATB, A, rowBase, K, (it + 1) * BK, tid);
            cp_commit();
            cp_wait1();
        } else {
            cp_wait0();
        }
        stsB(bB, breg, tid);
        __syncthreads();
        if (it + 1 < KT) loadB_regs(breg, Wuse, Nw, colW, (it + 1) * BK, tid);

        const uint32_t aB = sb + buf * AMATB;
        #pragma unroll
        for (int ks = 0; ks < 4; ks++) {
            uint32_t Af[4][4];
            #pragma unroll
            for (int mt = 0; mt < 4; mt++) {
                int r  = m0 + mt * 16 + (g & 1) * 8 + lr;
                int ch = ks * 2 + (g >> 1);
                uint32_t ad = aB + (uint32_t)r * AROWB + (uint32_t)ch * 16;
                ldmx4(ad, Af[mt][0], Af[mt][1], Af[mt][2], Af[mt][3]);
            }
            uint32_t Bh[4][2], Bl[4][2];
            #pragma unroll
            for (int p = 0; p < 2; p++) {
                int kr = ks * 16 + (lane & 15);
                int nc = n0 + p * 16 + (lane >> 4) * 8;
                uint32_t bd = bB + (uint32_t)kr * BROWB + (uint32_t)nc * 2;
                ldmx4t(bd,         Bh[2*p][0], Bh[2*p][1], Bh[2*p+1][0], Bh[2*p+1][1]);
                ldmx4t(bd + BHALF, Bl[2*p][0], Bl[2*p][1], Bl[2*p+1][0], Bl[2*p+1][1]);
            }
            #pragma unroll
            for (int mt = 0; mt < 4; mt++)
                #pragma unroll
                for (int nt = 0; nt < 4; nt++) {
                    mma_f16(acc[mt][nt], Af[mt], Bh[nt]);
                    mma_f16(acc[mt][nt], Af[mt], Bl[nt]);
                }
        }
        __syncthreads();
    }

    // Epilogue
    const int crow = lane >> 2;
    const int ccol = (lane & 3) * 2;
    #pragma unroll
    for (int mt = 0; mt < 4; mt++) {
        #pragma unroll
        for (int nt = 0; nt < 4; nt++) {
            int col = colC + n0 + nt * 8 + ccol;
            float b0 = 0.0f, b1 = 0.0f;
            if (bias) { b0 = __ldg(bias + col); b1 = __ldg(bias + col + 1); }
            #pragma unroll
            for (int half = 0; half < 2; half++) {
                int row = rowBase + m0 + mt * 16 + crow + half * 8;
                float v0 = acc[mt][nt][half * 2 + 0] + b0;
                float v1 = acc[mt][nt][half * 2 + 1] + b1;
                if (ACT == 1) {
                    v0 = 0.5f * v0 * (1.0f + erff(v0 * 0.7071067811865476f));
                    v1 = 0.5f * v1 * (1.0f + erff(v1 * 0.7071067811865476f));
                }
                if (OUTH) {
                    *reinterpret_cast<uint32_t*>(Ch + (size_t)row * ldC + col) = pack_h2(v0, v1);
                } else {
                    *reinterpret_cast<float2*>(&C[(size_t)row * ldC + col]) = make_float2(v0, v1);
                }
            }
        }
    }
}

// ---------------------------------------------------------------------------
// Flash attention (fp32) on packed qkv [NT, 3072]; emits fp16 ctx plane.
// 128 threads per block: one q row per thread, K/V tiles shared by 128 rows.
// ---------------------------------------------------------------------------
__global__ __launch_bounds__(128) void attn_kernel(const float* __restrict__ QKV,
                                                   const int* __restrict__ x,
                                                   __half* __restrict__ Oh)
{
    __shared__ float Ks[32][64];
    __shared__ float Vs[32][64];
    __shared__ int   validS[32];

    const int bh = blockIdx.x;
    const int b  = bh >> 4;
    const int h  = bh & 15;
    const int qt = blockIdx.y;
    const int tid = threadIdx.x;       // 0..127
    const int qrow = qt * 128 + tid;
    const int tQ = b * SS + qrow;

    const float* qp = QKV + (size_t)tQ * QKVW + h * DKH;
    float qreg[64], acc[64];
    #pragma unroll
    for (int d = 0; d < 64; d += 4) {
        float4 f = *reinterpret_cast<const float4*>(qp + d);
        qreg[d] = f.x; qreg[d+1] = f.y; qreg[d+2] = f.z; qreg[d+3] = f.w;
    }
    #pragma unroll
    for (int d = 0; d < 64; d++) acc[d] = 0.0f;

    float mrun = -1e30f, lsum = 0.0f;
    const int ntiles = 4 * qt + 4;     // 32-row tiles to cover causal span

    const int lrow = tid >> 2;         // 0..31: K/V tile row this thread helps load
    const int lcol = (tid & 3) * 16;   // 16 cols per thread (4 float4)

    for (int kt = 0; kt < ntiles; kt++) {
        const int kbase = kt * 32;
        {
            size_t off = (size_t)(b * SS + kbase + lrow) * QKVW + h * DKH + lcol;
            #pragma unroll
            for (int q = 0; q < 4; q++) {
                *reinterpret_cast<float4*>(&Ks[lrow][lcol + q * 4]) =
                    *reinterpret_cast<const float4*>(QKV + off + 1024 + q * 4);
                *reinterpret_cast<float4*>(&Vs[lrow][lcol + q * 4]) =
                    *reinterpret_cast<const float4*>(QKV + off + 2048 + q * 4);
            }
        }
        if (tid < 32) validS[tid] = (x[b * SS + kbase + tid] != 0);
        __syncthreads();

        int jmax = qrow - kbase + 1;
        if (jmax > 32) jmax = 32;
        if (jmax > 0) {
            float s[32];
            float tmax = -1e30f;
            #pragma unroll
            for (int j = 0; j < 32; j++) {
                if (j < jmax) {
                    float sum = 0.0f;
                    const float4* kr = reinterpret_cast<const float4*>(Ks[j]);
                    #pragma unroll
                    for (int dq = 0; dq < 16; dq++) {
                        float4 k4 = kr[dq];
                        sum += qreg[4*dq]   * k4.x;
                        sum += qreg[4*dq+1] * k4.y;
                        sum += qreg[4*dq+2] * k4.z;
                        sum += qreg[4*dq+3] * k4.w;
                    }
                    sum *= 0.125f;
                    if (!validS[j]) sum = -1e30f;
                    s[j] = sum;
                    tmax = fmaxf(tmax, sum);
                } else {
                    s[j] = -1e30f;
                }
            }
            float mnew = fmaxf(mrun, tmax);
            float corr = __expf(mrun - mnew);
            lsum *= corr;
            #pragma unroll
            for (int d = 0; d < 64; d++) acc[d] *= corr;
            mrun = mnew;
            #pragma unroll
            for (int j = 0; j < 32; j++) {
                float p = __expf(s[j] - mrun);
                lsum += p;
                const float4* vr = reinterpret_cast<const float4*>(Vs[j]);
                #pragma unroll
                for (int dq = 0; dq < 16; dq++) {
                    float4 v4 = vr[dq];
                    acc[4*dq]   += p * v4.x;
                    acc[4*dq+1] += p * v4.y;
                    acc[4*dq+2] += p * v4.z;
                    acc[4*dq+3] += p * v4.w;
                }
            }
        }
        __syncthreads();
    }

    float inv = 1.0f / lsum;
    size_t ob = (size_t)tQ * DD + h * DKH;
    #pragma unroll
    for (int d = 0; d < 64; d += 2) {
        *reinterpret_cast<uint32_t*>(Oh + ob + d) = pack_h2(acc[d] * inv, acc[d+1] * inv);
    }
}

// ---------------------------------------------------------------------------
// Residual add + LayerNorm (in place on h); also emits fp16 activation plane
// ---------------------------------------------------------------------------
__device__ __forceinline__ float block_sum(float v, float* red)
{
    #pragma unroll
    for (int o = 16; o > 0; o >>= 1) v += __shfl_xor_sync(0xffffffffu, v, o);
    int w = threadIdx.x >> 5;
    if ((threadIdx.x & 31) == 0) red[w] = v;
    __syncthreads();
    if (threadIdx.x < 32) {
        float t = (threadIdx.x < 8) ? red[threadIdx.x] : 0.0f;
        #pragma unroll
        for (int o = 4; o > 0; o >>= 1) t += __shfl_xor_sync(0xffffffffu, t, o);
        if (threadIdx.x == 0) red[0] = t;
    }
    __syncthreads();
    float r = red[0];
    __syncthreads();
    return r;
}

__global__ __launch_bounds__(256) void add_ln_kernel(float* __restrict__ h,
                                                     const float* __restrict__ r,
                                                     const float* __restrict__ g,
                                                     const float* __restrict__ bta,
                                                     __half* __restrict__ ah)
{
    __shared__ float red[32];
    const int t = blockIdx.x;
    const int tid = threadIdx.x;
    size_t base = (size_t)t * DD;
    float v[4];
    float sum = 0.0f;
    #pragma unroll
    for (int i = 0; i < 4; i++) {
        int d = tid * 2 + (i & 1) + (i >> 1) * 512;
        float val = h[base + d] + r[base + d];
        v[i] = val;
        sum += val;
    }
    float tot = block_sum(sum, red);
    float mu = tot * (1.0f / (float)DD);
    float sq = 0.0f;
    #pragma unroll
    for (int i = 0; i < 4; i++) { float dvi = v[i] - mu; sq += dvi * dvi; }
    float var = block_sum(sq, red) * (1.0f / (float)DD);
    float rs = rsqrtf(var + 1e-5f);
    #pragma unroll
    for (int p = 0; p < 2; p++) {
        int d = tid * 2 + p * 512;
        float o0 = (v[p*2]   - mu) * rs * g[d]     + bta[d];
        float o1 = (v[p*2+1] - mu) * rs * g[d + 1] + bta[d + 1];
        h[base + d]     = o0;
        h[base + d + 1] = o1;
        *reinterpret_cast<uint32_t*>(ah + base + d) = pack_h2(o0, o1);
    }
}

// ---------------------------------------------------------------------------
// Launch
// ---------------------------------------------------------------------------
extern "C" void kernel_launch(void* const* d_in, const int* in_sizes, int n_in,
                              void* d_out, int out_size)
{
    const int*   x    = (const int*)  d_in[0];
    const float* emb  = (const float*)d_in[1];
    const float* Wq   = (const float*)d_in[2];
    const float* Wk   = (const float*)d_in[3];
    const float* Wv   = (const float*)d_in[4];
    const float* Wo   = (const float*)d_in[5];
    const float* bo   = (const float*)d_in[6];
    const float* ln1g = (const float*)d_in[7];
    const float* ln1b = (const float*)d_in[8];
    const float* ln2g = (const float*)d_in[9];
    const float* ln2b = (const float*)d_in[10];
    const float* W1   = (const float*)d_in[11];
    const float* b1   = (const float*)d_in[12];
    const float* W2   = (const float*)d_in[13];
    const float* b2   = (const float*)d_in[14];
    const float* Wout = (const float*)d_in[15];
    const float* bout = (const float*)d_in[16];
    float* out = (float*)d_out;

    void* p;
    cudaGetSymbolAddress(&p, g_h);   float* h   = (float*)p;
    cudaGetSymbolAddress(&p, g_qkv); float* qkv = (float*)p;
    cudaGetSymbolAddress(&p, g_tmp); float* tmp = (float*)p;
    cudaGetSymbolAddress(&p, g_ah);  __half* ah = (__half*)p;
    cudaGetSymbolAddress(&p, g_fh);  __half* fh = (__half*)p;

    cudaFuncSetAttribute(gemm_mma<0,0>, cudaFuncAttributeMaxDynamicSharedMemorySize, GEMM_SMEM);
    cudaFuncSetAttribute(gemm_mma<1,1>, cudaFuncAttributeMaxDynamicSharedMemorySize, GEMM_SMEM);

    embed_kernel<<<NT, 256>>>(x, emb, h, ah);

    const dim3 gQKV(NT/BM, QKVW/BN);  // 32 x 24 (fused q|k|v)
    const dim3 gD(NT/BM, DD/BN);      // 32 x 8
    const dim3 gF(NT/BM, FF/BN);      // 32 x 32
    const dim3 gV(NT/BM, VV/BN);      // 32 x 250

    for (int l = 0; l < LL; l++) {
        const float* wq = Wq + (size_t)l * DD * DD;
        const float* wk = Wk + (size_t)l * DD * DD;
        const float* wv = Wv + (size_t)l * DD * DD;
        const float* wo = Wo + (size_t)l * DD * DD;
        const float* w1 = W1 + (size_t)l * DD * FF;
        const float* w2 = W2 + (size_t)l * FF * DD;

        // Fused QKV projection (one launch, W selected per block)
        gemm_mma<0,0><<<gQKV, 256, GEMM_SMEM>>>(ah, wq, wk, wv, nullptr, qkv, nullptr, NT, DD, DD, QKVW);

        attn_kernel<<<dim3(BB * HH, SS / 128), 128>>>(qkv, x, ah);   // ctx -> fp16 plane

        gemm_mma<0,0><<<gD, 256, GEMM_SMEM>>>(ah, wo, nullptr, nullptr, bo + l * DD, tmp, nullptr, NT, DD, DD, DD);
        add_ln_kernel<<<NT, 256>>>(h, tmp, ln1g + l * DD, ln1b + l * DD, ah);

        gemm_mma<1,1><<<gF, 256, GEMM_SMEM>>>(ah, w1, nullptr, nullptr, b1 + l * FF, nullptr, fh, NT, FF, DD, FF);
        gemm_mma<0,0><<<gD, 256, GEMM_SMEM>>>(fh, w2, nullptr, nullptr, b2 + l * DD, tmp, nullptr, NT, DD, FF, DD);
        add_ln_kernel<<<NT, 256>>>(h, tmp, ln2g + l * DD, ln2b + l * DD, ah);
    }

    gemm_mma<0,0><<<gV, 256, GEMM_SMEM>>>(ah, Wout, nullptr, nullptr, bout, out, nullptr, NT, VV, DD, VV);
}

// round 8
// speedup vs baseline: 1.4234x; 1.0118x over previous
#include <cuda_runtime.h>
#include <cuda_fp16.h>
#include <cstdint>
#include <cmath>

// Problem constants
#define BB   4
#define SS   1024
#define DD   1024
#define HH   16
#define DKH  64
#define LL   4
#define FF   4096
#define VV   32000
#define NT   (BB*SS)   // 4096 tokens
#define QKVW 3072      // packed q|k|v width

// GEMM tile config: CTA 256x128, warp 64x64 (4x2 warps), BK=64
#define BM 256
#define BN 128
#define BK 64
#define AROWB 144                  // A smem row: 128B data + 16B pad
#define ASTG (BM*AROWB)            // one 256xBK fp16 matrix: 36864 B
#define BROWB 272                  // B smem row: 256B data + 16B pad
#define BHALF (64*BROWB)           // one 64x128 fp16 matrix: 17408 B
#define BBASE (2*ASTG)             // 73728 (A double-buffered)
#define GEMM_SMEM (BBASE + 2*BHALF)   // 108544 B

// ---------------------------------------------------------------------------
// Scratch (device globals — no runtime allocation allowed)
// ---------------------------------------------------------------------------
__device__ float g_h  [NT*(size_t)DD];
__device__ float g_qkv[NT*(size_t)QKVW];
__device__ float g_tmp[NT*(size_t)DD];
__device__ __half g_ah [NT*(size_t)DD];
__device__ __half g_fh [NT*(size_t)FF];

// ---------------------------------------------------------------------------
// PTX helpers (arch-agnostic: sm_80-era instructions only)
// ---------------------------------------------------------------------------
__device__ __forceinline__ uint32_t smem_u32(const void* p) {
    uint32_t a;
    asm("{ .reg .u64 t; cvta.to.shared.u64 t, %1; cvt.u32.u64 %0, t; }" : "=r"(a) : "l"(p));
    return a;
}
__device__ __forceinline__ void cp_async16(uint32_t dst, const void* src) {
    asm volatile("cp.async.cg.shared.global [%0], [%1], 16;" :: "r"(dst), "l"(src));
}
__device__ __forceinline__ void cp_commit() {
    asm volatile("cp.async.commit_group;");
}
__device__ __forceinline__ void cp_wait1() {
    asm volatile("cp.async.wait_group 1;");
}
__device__ __forceinline__ void cp_wait0() {
    asm volatile("cp.async.wait_group 0;");
}
__device__ __forceinline__ void ldmx4(uint32_t addr, uint32_t& r0, uint32_t& r1,
                                      uint32_t& r2, uint32_t& r3) {
    asm volatile("ldmatrix.sync.aligned.m8n8.x4.shared.b16 {%0,%1,%2,%3}, [%4];"
                 : "=r"(r0), "=r"(r1), "=r"(r2), "=r"(r3) : "r"(addr));
}
__device__ __forceinline__ void ldmx4t(uint32_t addr, uint32_t& r0, uint32_t& r1,
                                       uint32_t& r2, uint32_t& r3) {
    asm volatile("ldmatrix.sync.aligned.m8n8.x4.trans.shared.b16 {%0,%1,%2,%3}, [%4];"
                 : "=r"(r0), "=r"(r1), "=r"(r2), "=r"(r3) : "r"(addr));
}
__device__ __forceinline__ void mma_f16(float* c, const uint32_t* a, const uint32_t* b) {
    asm volatile("mma.sync.aligned.m16n8k16.row.col.f32.f16.f16.f32 "
                 "{%0,%1,%2,%3}, {%4,%5,%6,%7}, {%8,%9}, {%0,%1,%2,%3};"
                 : "+f"(c[0]), "+f"(c[1]), "+f"(c[2]), "+f"(c[3])
                 : "r"(a[0]), "r"(a[1]), "r"(a[2]), "r"(a[3]), "r"(b[0]), "r"(b[1]));
}
__device__ __forceinline__ uint32_t h2_bits(__half2 v) {
    return *reinterpret_cast<uint32_t*>(&v);
}
// split a float pair into fp16 hi/lo words (hi + lo ~= x to ~2^-22)
__device__ __forceinline__ void split2h(float a, float b, uint32_t& hw, uint32_t& lw) {
    __half2 h = __floats2half2_rn(a, b);
    float la = a - __low2float(h);
    float lb = b - __high2float(h);
    __half2 l = __floats2half2_rn(la, lb);
    hw = h2_bits(h);
    lw = h2_bits(l);
}
__device__ __forceinline__ uint32_t pack_h2(float a, float b) {
    return h2_bits(__floats2half2_rn(a, b));
}

// ---------------------------------------------------------------------------
// Embedding + positional encoding; writes fp32 h AND fp16 activation plane
// ---------------------------------------------------------------------------
__global__ __launch_bounds__(256) void embed_kernel(const int* __restrict__ x,
                                                    const float* __restrict__ emb,
                                                    float* __restrict__ h,
                                                    __half* __restrict__ ah)
{
    int t = blockIdx.x;
    int s = t & (SS - 1);
    int tok = x[t];
    const float* e = emb + (size_t)tok * DD;
    const float negln = -9.210340371976184f;
    size_t base = (size_t)t * DD;
    for (int d0 = threadIdx.x * 2; d0 < DD; d0 += blockDim.x * 2) {
        float v[2];
        #pragma unroll
        for (int j = 0; j < 2; j++) {
            int d = d0 + j;
            int i2 = (d >> 1) * 2;
            float div = expf((float)i2 * (negln / (float)DD));
            float ang = (float)s * div;
            float pe = (d & 1) ? cosf(ang) : sinf(ang);
            v[j] = e[d] * 32.0f + pe;
        }
        h[base + d0] = v[0];
        h[base + d0 + 1] = v[1];
        *reinterpret_cast<uint32_t*>(ah + base + d0) = pack_h2(v[0], v[1]);
    }
}

// ---------------------------------------------------------------------------
// fp16x2 GEMM via mma.sync: C[M,N] = A[M,K] @ W[K,N] (+bias)(+GELU)
// A: fp16 [M,K]. W: fp32 [K,N], split on the fly into fp16 hi/lo.
// CTA 256x128, 8 warps of 64x64 (4 m-rows x 2 n-cols), BK=64.
// ---------------------------------------------------------------------------
__device__ __forceinline__ void stage_loadA(uint32_t sdst, const __half* A,
                                            int rowBase, int K, int k0, int tid)
{
    #pragma unroll
    for (int i = 0; i < 8; i++) {
        int idx = tid + i * 256;           // 0..2047
        int r  = idx >> 3;
        int ch = idx & 7;
        uint32_t so = (uint32_t)r * AROWB + (uint32_t)ch * 16;
        cp_async16(sdst + so, A + (size_t)(rowBase + r) * K + k0 + ch * 8);
    }
}

__device__ __forceinline__ void loadB_regs(float4* breg, const float* __restrict__ W,
                                           int Nw, int colW, int k0, int tid)
{
    int r  = tid >> 2;
    int cq = tid & 3;
    const float* base = W + (size_t)(k0 + r) * Nw + colW + cq * 4;
    #pragma unroll
    for (int i = 0; i < 8; i++)
        breg[i] = *reinterpret_cast<const float4*>(base + i * 16);
}

__device__ __forceinline__ void stsB(uint32_t bB, const float4* breg, int tid)
{
    int r  = tid >> 2;
    int cq = tid & 3;
    uint32_t base = bB + (uint32_t)r * BROWB + (uint32_t)cq * 8;
    #pragma unroll
    for (int i = 0; i < 8; i++) {
        float4 f = breg[i];
        uint2 uh, ul;
        split2h(f.x, f.y, uh.x, ul.x);
        split2h(f.z, f.w, uh.y, ul.y);
        uint32_t a = base + (uint32_t)i * 32;
        asm volatile("st.shared.v2.b32 [%0], {%1, %2};" :: "r"(a), "r"(uh.x), "r"(uh.y));
        asm volatile("st.shared.v2.b32 [%0], {%1, %2};" :: "r"(a + BHALF), "r"(ul.x), "r"(ul.y));
    }
}

template<int ACT, int OUTH>
__global__ __launch_bounds__(256) void gemm_mma(const __half* __restrict__ A,
                                                const float* __restrict__ W,
                                                const float* __restrict__ Wb,
                                                const float* __restrict__ Wc,
                                                const float* __restrict__ bias,
                                                float* __restrict__ C,
                                                __half* __restrict__ Ch,
                                                int M, int Nw, int K, int ldC)
{
    extern __shared__ char smem[];
    const uint32_t sb = smem_u32(smem);
    const int tid  = threadIdx.x;
    const int wid  = tid >> 5;
    const int lane = tid & 31;
    const int rowBase = blockIdx.x * BM;

    const float* Wuse = W;
    int colW;
    if (Wb) {
        int wsel = blockIdx.y >> 3;
        Wuse = (wsel == 0) ? W : ((wsel == 1) ? Wb : Wc);
        colW = (blockIdx.y & 7) * BN;
    } else {
        colW = blockIdx.y * BN;
    }
    const int colC = blockIdx.y * BN;

    const int m0 = (wid >> 1) * 64;     // warp M offset (4 rows of warps)
    const int n0 = (wid & 1) * 64;      // warp N offset (2 cols of warps)
    const int g  = lane >> 3;
    const int lr = lane & 7;

    float acc[4][8][4];
    #pragma unroll
    for (int mt = 0; mt < 4; mt++)
        #pragma unroll
        for (int nt = 0; nt < 8; nt++)
            #pragma unroll
            for (int e = 0; e < 4; e++) acc[mt][nt][e] = 0.0f;

    const int KT = K / BK;
    const uint32_t bB = sb + BBASE;

    float4 breg[8];
    loadB_regs(breg, Wuse, Nw, colW, 0, tid);
    stage_loadA(sb, A, rowBase, K, 0, tid);
    cp_commit();

    for (int it = 0; it < KT; it++) {
        const int buf = it & 1;
        if (it + 1 < KT) {
            stage_loadA(sb + (buf ^ 1) * ASTG, A, rowBase, K, (it + 1) * BK, tid);
            cp_commit();
            cp_wait1();
        } else {
            cp_wait0();
        }
        stsB(bB, breg, tid);
        __syncthreads();
        if (it + 1 < KT) loadB_regs(breg, Wuse, Nw, colW, (it + 1) * BK, tid);

        const uint32_t aB = sb + buf * ASTG;
        #pragma unroll
        for (int ks = 0; ks < 4; ks++) {
            uint32_t Af[4][4];
            #pragma unroll
            for (int mt = 0; mt < 4; mt++) {
                int r  = m0 + mt * 16 + (g & 1) * 8 + lr;
                int ch = ks * 2 + (g >> 1);
                uint32_t ad = aB + (uint32_t)r * AROWB + (uint32_t)ch * 16;
                ldmx4(ad, Af[mt][0], Af[mt][1], Af[mt][2], Af[mt][3]);
            }
            uint32_t Bh[8][2], Bl[8][2];
            #pragma unroll
            for (int p = 0; p < 4; p++) {
                int kr = ks * 16 + (lane & 15);
                int nc = n0 + p * 16 + (lane >> 4) * 8;
                uint32_t bd = bB + (uint32_t)kr * BROWB + (uint32_t)nc * 2;
                ldmx4t(bd,         Bh[2*p][0], Bh[2*p][1], Bh[2*p+1][0], Bh[2*p+1][1]);
                ldmx4t(bd + BHALF, Bl[2*p][0], Bl[2*p][1], Bl[2*p+1][0], Bl[2*p+1][1]);
            }
            #pragma unroll
            for (int mt = 0; mt < 4; mt++)
                #pragma unroll
                for (int nt = 0; nt < 8; nt++) {
                    mma_f16(acc[mt][nt], Af[mt], Bh[nt]);
                    mma_f16(acc[mt][nt], Af[mt], Bl[nt]);
                }
        }
        __syncthreads();
    }

    // Epilogue
    const int crow = lane >> 2;
    const int ccol = (lane & 3) * 2;
    #pragma unroll
    for (int mt = 0; mt < 4; mt++) {
        #pragma unroll
        for (int nt = 0; nt < 8; nt++) {
            int col = colC + n0 + nt * 8 + ccol;
            float b0 = 0.0f, b1 = 0.0f;
            if (bias) { b0 = __ldg(bias + col); b1 = __ldg(bias + col + 1); }
            #pragma unroll
            for (int half = 0; half < 2; half++) {
                int row = rowBase + m0 + mt * 16 + crow + half * 8;
                float v0 = acc[mt][nt][half * 2 + 0] + b0;
                float v1 = acc[mt][nt][half * 2 + 1] + b1;
                if (ACT == 1) {
                    v0 = 0.5f * v0 * (1.0f + erff(v0 * 0.7071067811865476f));
                    v1 = 0.5f * v1 * (1.0f + erff(v1 * 0.7071067811865476f));
                }
                if (OUTH) {
                    *reinterpret_cast<uint32_t*>(Ch + (size_t)row * ldC + col) = pack_h2(v0, v1);
                } else {
                    *reinterpret_cast<float2*>(&C[(size_t)row * ldC + col]) = make_float2(v0, v1);
                }
            }
        }
    }
}

// ---------------------------------------------------------------------------
// Flash attention (fp32) on packed qkv [NT, 3072]; emits fp16 ctx plane.
// 128 threads per block: one q row per thread, K/V tiles shared by 128 rows.
// ---------------------------------------------------------------------------
__global__ __launch_bounds__(128) void attn_kernel(const float* __restrict__ QKV,
                                                   const int* __restrict__ x,
                                                   __half* __restrict__ Oh)
{
    __shared__ float Ks[32][64];
    __shared__ float Vs[32][64];
    __shared__ int   validS[32];

    const int bh = blockIdx.x;
    const int b  = bh >> 4;
    const int h  = bh & 15;
    const int qt = blockIdx.y;
    const int tid = threadIdx.x;       // 0..127
    const int qrow = qt * 128 + tid;
    const int tQ = b * SS + qrow;

    const float* qp = QKV + (size_t)tQ * QKVW + h * DKH;
    float qreg[64], acc[64];
    #pragma unroll
    for (int d = 0; d < 64; d += 4) {
        float4 f = *reinterpret_cast<const float4*>(qp + d);
        qreg[d] = f.x; qreg[d+1] = f.y; qreg[d+2] = f.z; qreg[d+3] = f.w;
    }
    #pragma unroll
    for (int d = 0; d < 64; d++) acc[d] = 0.0f;

    float mrun = -1e30f, lsum = 0.0f;
    const int ntiles = 4 * qt + 4;

    const int lrow = tid >> 2;
    const int lcol = (tid & 3) * 16;

    for (int kt = 0; kt < ntiles; kt++) {
        const int kbase = kt * 32;
        {
            size_t off = (size_t)(b * SS + kbase + lrow) * QKVW + h * DKH + lcol;
            #pragma unroll
            for (int q = 0; q < 4; q++) {
                *reinterpret_cast<float4*>(&Ks[lrow][lcol + q * 4]) =
                    *reinterpret_cast<const float4*>(QKV + off + 1024 + q * 4);
                *reinterpret_cast<float4*>(&Vs[lrow][lcol + q * 4]) =
                    *reinterpret_cast<const float4*>(QKV + off + 2048 + q * 4);
            }
        }
        if (tid < 32) validS[tid] = (x[b * SS + kbase + tid] != 0);
        __syncthreads();

        int jmax = qrow - kbase + 1;
        if (jmax > 32) jmax = 32;
        if (jmax > 0) {
            float s[32];
            float tmax = -1e30f;
            #pragma unroll
            for (int j = 0; j < 32; j++) {
                if (j < jmax) {
                    float sum = 0.0f;
                    const float4* kr = reinterpret_cast<const float4*>(Ks[j]);
                    #pragma unroll
                    for (int dq = 0; dq < 16; dq++) {
                        float4 k4 = kr[dq];
                        sum += qreg[4*dq]   * k4.x;
                        sum += qreg[4*dq+1] * k4.y;
                        sum += qreg[4*dq+2] * k4.z;
                        sum += qreg[4*dq+3] * k4.w;
                    }
                    sum *= 0.125f;
                    if (!validS[j]) sum = -1e30f;
                    s[j] = sum;
                    tmax = fmaxf(tmax, sum);
                } else {
                    s[j] = -1e30f;
                }
            }
            float mnew = fmaxf(mrun, tmax);
            float corr = __expf(mrun - mnew);
            lsum *= corr;
            #pragma unroll
            for (int d = 0; d < 64; d++) acc[d] *= corr;
            mrun = mnew;
            #pragma unroll
            for (int j = 0; j < 32; j++) {
                float p = __expf(s[j] - mrun);
                lsum += p;
                const float4* vr = reinterpret_cast<const float4*>(Vs[j]);
                #pragma unroll
                for (int dq = 0; dq < 16; dq++) {
                    float4 v4 = vr[dq];
                    acc[4*dq]   += p * v4.x;
                    acc[4*dq+1] += p * v4.y;
                    acc[4*dq+2] += p * v4.z;
                    acc[4*dq+3] += p * v4.w;
                }
            }
        }
        __syncthreads();
    }

    float inv = 1.0f / lsum;
    size_t ob = (size_t)tQ * DD + h * DKH;
    #pragma unroll
    for (int d = 0; d < 64; d += 2) {
        *reinterpret_cast<uint32_t*>(Oh + ob + d) = pack_h2(acc[d] * inv, acc[d+1] * inv);
    }
}

// ---------------------------------------------------------------------------
// Residual add + LayerNorm (in place on h); also emits fp16 activation plane
// ---------------------------------------------------------------------------
__device__ __forceinline__ float block_sum(float v, float* red)
{
    #pragma unroll
    for (int o = 16; o > 0; o >>= 1) v += __shfl_xor_sync(0xffffffffu, v, o);
    int w = threadIdx.x >> 5;
    if ((threadIdx.x & 31) == 0) red[w] = v;
    __syncthreads();
    if (threadIdx.x < 32) {
        float t = (threadIdx.x < 8) ? red[threadIdx.x] : 0.0f;
        #pragma unroll
        for (int o = 4; o > 0; o >>= 1) t += __shfl_xor_sync(0xffffffffu, t, o);
        if (threadIdx.x == 0) red[0] = t;
    }
    __syncthreads();
    float r = red[0];
    __syncthreads();
    return r;
}

__global__ __launch_bounds__(256) void add_ln_kernel(float* __restrict__ h,
                                                     const float* __restrict__ r,
                                                     const float* __restrict__ g,
                                                     const float* __restrict__ bta,
                                                     __half* __restrict__ ah)
{
    __shared__ float red[32];
    const int t = blockIdx.x;
    const int tid = threadIdx.x;
    size_t base = (size_t)t * DD;
    float v[4];
    float sum = 0.0f;
    #pragma unroll
    for (int i = 0; i < 4; i++) {
        int d = tid * 2 + (i & 1) + (i >> 1) * 512;
        float val = h[base + d] + r[base + d];
        v[i] = val;
        sum += val;
    }
    float tot = block_sum(sum, red);
    float mu = tot * (1.0f / (float)DD);
    float sq = 0.0f;
    #pragma unroll
    for (int i = 0; i < 4; i++) { float dvi = v[i] - mu; sq += dvi * dvi; }
    float var = block_sum(sq, red) * (1.0f / (float)DD);
    float rs = rsqrtf(var + 1e-5f);
    #pragma unroll
    for (int p = 0; p < 2; p++) {
        int d = tid * 2 + p * 512;
        float o0 = (v[p*2]   - mu) * rs * g[d]     + bta[d];
        float o1 = (v[p*2+1] - mu) * rs * g[d + 1] + bta[d + 1];
        h[base + d]     = o0;
        h[base + d + 1] = o1;
        *reinterpret_cast<uint32_t*>(ah + base + d) = pack_h2(o0, o1);
    }
}

// ---------------------------------------------------------------------------
// Launch
// ---------------------------------------------------------------------------
extern "C" void kernel_launch(void* const* d_in, const int* in_sizes, int n_in,
                              void* d_out, int out_size)
{
    const int*   x    = (const int*)  d_in[0];
    const float* emb  = (const float*)d_in[1];
    const float* Wq   = (const float*)d_in[2];
    const float* Wk   = (const float*)d_in[3];
    const float* Wv   = (const float*)d_in[4];
    const float* Wo   = (const float*)d_in[5];
    const float* bo   = (const float*)d_in[6];
    const float* ln1g = (const float*)d_in[7];
    const float* ln1b = (const float*)d_in[8];
    const float* ln2g = (const float*)d_in[9];
    const float* ln2b = (const float*)d_in[10];
    const float* W1   = (const float*)d_in[11];
    const float* b1   = (const float*)d_in[12];
    const float* W2   = (const float*)d_in[13];
    const float* b2   = (const float*)d_in[14];
    const float* Wout = (const float*)d_in[15];
    const float* bout = (const float*)d_in[16];
    float* out = (float*)d_out;

    void* p;
    cudaGetSymbolAddress(&p, g_h);   float* h   = (float*)p;
    cudaGetSymbolAddress(&p, g_qkv); float* qkv = (float*)p;
    cudaGetSymbolAddress(&p, g_tmp); float* tmp = (float*)p;
    cudaGetSymbolAddress(&p, g_ah);  __half* ah = (__half*)p;
    cudaGetSymbolAddress(&p, g_fh);  __half* fh = (__half*)p;

    cudaFuncSetAttribute(gemm_mma<0,0>, cudaFuncAttributeMaxDynamicSharedMemorySize, GEMM_SMEM);
    cudaFuncSetAttribute(gemm_mma<1,1>, cudaFuncAttributeMaxDynamicSharedMemorySize, GEMM_SMEM);

    embed_kernel<<<NT, 256>>>(x, emb, h, ah);

    const dim3 gQKV(NT/BM, QKVW/BN);  // 16 x 24 (fused q|k|v)
    const dim3 gD(NT/BM, DD/BN);      // 16 x 8
    const dim3 gF(NT/BM, FF/BN);      // 16 x 32
    const dim3 gV(NT/BM, VV/BN);      // 16 x 250

    for (int l = 0; l < LL; l++) {
        const float* wq = Wq + (size_t)l * DD * DD;
        const float* wk = Wk + (size_t)l * DD * DD;
        const float* wv = Wv + (size_t)l * DD * DD;
        const float* wo = Wo + (size_t)l * DD * DD;
        const float* w1 = W1 + (size_t)l * DD * FF;
        const float* w2 = W2 + (size_t)l * FF * DD;

        // Fused QKV projection (one launch, W selected per block)
        gemm_mma<0,0><<<gQKV, 256, GEMM_SMEM>>>(ah, wq, wk, wv, nullptr, qkv, nullptr, NT, DD, DD, QKVW);

        attn_kernel<<<dim3(BB * HH, SS / 128), 128>>>(qkv, x, ah);   // ctx -> fp16 plane

        gemm_mma<0,0><<<gD, 256, GEMM_SMEM>>>(ah, wo, nullptr, nullptr, bo + l * DD, tmp, nullptr, NT, DD, DD, DD);
        add_ln_kernel<<<NT, 256>>>(h, tmp, ln1g + l * DD, ln1b + l * DD, ah);

        gemm_mma<1,1><<<gF, 256, GEMM_SMEM>>>(ah, w1, nullptr, nullptr, b1 + l * FF, nullptr, fh, NT, FF, DD, FF);
        gemm_mma<0,0><<<gD, 256, GEMM_SMEM>>>(fh, w2, nullptr, nullptr, b2 + l * DD, tmp, nullptr, NT, DD, FF, DD);
        add_ln_kernel<<<NT, 256>>>(h, tmp, ln2g + l * DD, ln2b + l * DD, ah);
    }

    gemm_mma<0,0><<<gV, 256, GEMM_SMEM>>>(ah, Wout, nullptr, nullptr, bout, out, nullptr, NT, VV, DD, VV);
}

// round 9
// speedup vs baseline: 1.4320x; 1.0060x over previous
#include <cuda_runtime.h>
#include <cuda_fp16.h>
#include <cstdint>
#include <cmath>

// Problem constants
#define BB   4
#define SS   1024
#define DD   1024
#define HH   16
#define DKH  64
#define LL   4
#define FF   4096
#define VV   32000
#define NT   (BB*SS)   // 4096 tokens
#define QKVW 3072      // packed q|k|v width

// GEMM tile config: CTA 256x128, warp 64x64 (4x2 warps), BK=64
#define BM 256
#define BN 128
#define BK 64
#define AROWB 144                  // A smem row: 128B data + 16B pad
#define ASTG (BM*AROWB)            // one 256xBK fp16 matrix: 36864 B
#define BROWB 272                  // B smem row: 256B data + 16B pad
#define BHALF (64*BROWB)           // one 64x128 fp16 plane: 17408 B
#define BSTG (2*BHALF)             // hi+lo per stage: 34816 B
#define BBASE (2*ASTG)             // 73728 (A double-buffered)
#define GEMM_SMEM (BBASE + 2*BSTG) // 143360 B

// Pre-split weight plane offsets (elements)
#define OFF_WQ   0
#define OFF_WK   (4*DD*DD)
#define OFF_WV   (8*DD*DD)
#define OFF_WO   (12*DD*DD)
#define OFF_W1   (16*DD*DD)
#define OFF_W2   (OFF_W1 + LL*DD*FF)
#define OFF_WOUT (OFF_W2 + LL*DD*FF)
#define WTOT     (OFF_WOUT + (size_t)DD*VV)   // 83,099,648 elems

// ---------------------------------------------------------------------------
// Scratch (device globals — no runtime allocation allowed)
// ---------------------------------------------------------------------------
__device__ float g_h  [NT*(size_t)DD];
__device__ float g_qkv[NT*(size_t)QKVW];
__device__ float g_tmp[NT*(size_t)DD];
__device__ __half g_ah [NT*(size_t)DD];
__device__ __half g_fh [NT*(size_t)FF];
__device__ __half g_whi[WTOT];
__device__ __half g_wlo[WTOT];

// ---------------------------------------------------------------------------
// PTX helpers (arch-agnostic: sm_80-era instructions only)
// ---------------------------------------------------------------------------
__device__ __forceinline__ uint32_t smem_u32(const void* p) {
    uint32_t a;
    asm("{ .reg .u64 t; cvta.to.shared.u64 t, %1; cvt.u32.u64 %0, t; }" : "=r"(a) : "l"(p));
    return a;
}
__device__ __forceinline__ void cp_async16(uint32_t dst, const void* src) {
    asm volatile("cp.async.cg.shared.global [%0], [%1], 16;" :: "r"(dst), "l"(src));
}
__device__ __forceinline__ void cp_commit() {
    asm volatile("cp.async.commit_group;");
}
__device__ __forceinline__ void cp_wait1() {
    asm volatile("cp.async.wait_group 1;");
}
__device__ __forceinline__ void cp_wait0() {
    asm volatile("cp.async.wait_group 0;");
}
__device__ __forceinline__ void ldmx4(uint32_t addr, uint32_t& r0, uint32_t& r1,
                                      uint32_t& r2, uint32_t& r3) {
    asm volatile("ldmatrix.sync.aligned.m8n8.x4.shared.b16 {%0,%1,%2,%3}, [%4];"
                 : "=r"(r0), "=r"(r1), "=r"(r2), "=r"(r3) : "r"(addr));
}
__device__ __forceinline__ void ldmx4t(uint32_t addr, uint32_t& r0, uint32_t& r1,
                                       uint32_t& r2, uint32_t& r3) {
    asm volatile("ldmatrix.sync.aligned.m8n8.x4.trans.shared.b16 {%0,%1,%2,%3}, [%4];"
                 : "=r"(r0), "=r"(r1), "=r"(r2), "=r"(r3) : "r"(addr));
}
__device__ __forceinline__ void mma_f16(float* c, const uint32_t* a, const uint32_t* b) {
    asm volatile("mma.sync.aligned.m16n8k16.row.col.f32.f16.f16.f32 "
                 "{%0,%1,%2,%3}, {%4,%5,%6,%7}, {%8,%9}, {%0,%1,%2,%3};"
                 : "+f"(c[0]), "+f"(c[1]), "+f"(c[2]), "+f"(c[3])
                 : "r"(a[0]), "r"(a[1]), "r"(a[2]), "r"(a[3]), "r"(b[0]), "r"(b[1]));
}
__device__ __forceinline__ uint32_t h2_bits(__half2 v) {
    return *reinterpret_cast<uint32_t*>(&v);
}
// split a float pair into fp16 hi/lo words (hi + lo ~= x to ~2^-22)
__device__ __forceinline__ void split2h(float a, float b, uint32_t& hw, uint32_t& lw) {
    __half2 h = __floats2half2_rn(a, b);
    float la = a - __low2float(h);
    float lb = b - __high2float(h);
    __half2 l = __floats2half2_rn(la, lb);
    hw = h2_bits(h);
    lw = h2_bits(l);
}
__device__ __forceinline__ uint32_t pack_h2(float a, float b) {
    return h2_bits(__floats2half2_rn(a, b));
}

// ---------------------------------------------------------------------------
// Weight split: W fp32 -> hi/lo fp16 planes (same layout), streaming
// ---------------------------------------------------------------------------
__global__ __launch_bounds__(256) void wsplit_kernel(const float* __restrict__ W,
                                                     __half* __restrict__ hi,
                                                     __half* __restrict__ lo,
                                                     int n4)   // n/4
{
    const float4* W4 = reinterpret_cast<const float4*>(W);
    uint2* H2 = reinterpret_cast<uint2*>(hi);
    uint2* L2 = reinterpret_cast<uint2*>(lo);
    for (int i = blockIdx.x * blockDim.x + threadIdx.x; i < n4; i += gridDim.x * blockDim.x) {
        float4 f = W4[i];
        uint2 h, l;
        split2h(f.x, f.y, h.x, l.x);
        split2h(f.z, f.w, h.y, l.y);
        H2[i] = h;
        L2[i] = l;
    }
}

// ---------------------------------------------------------------------------
// Embedding + positional encoding; writes fp32 h AND fp16 activation plane
// ---------------------------------------------------------------------------
__global__ __launch_bounds__(256) void embed_kernel(const int* __restrict__ x,
                                                    const float* __restrict__ emb,
                                                    float* __restrict__ h,
                                                    __half* __restrict__ ah)
{
    int t = blockIdx.x;
    int s = t & (SS - 1);
    int tok = x[t];
    const float* e = emb + (size_t)tok * DD;
    const float negln = -9.210340371976184f;
    size_t base = (size_t)t * DD;
    for (int d0 = threadIdx.x * 2; d0 < DD; d0 += blockDim.x * 2) {
        float v[2];
        #pragma unroll
        for (int j = 0; j < 2; j++) {
            int d = d0 + j;
            int i2 = (d >> 1) * 2;
            float div = expf((float)i2 * (negln / (float)DD));
            float ang = (float)s * div;
            float pe = (d & 1) ? cosf(ang) : sinf(ang);
            v[j] = e[d] * 32.0f + pe;
        }
        h[base + d0] = v[0];
        h[base + d0 + 1] = v[1];
        *reinterpret_cast<uint32_t*>(ah + base + d0) = pack_h2(v[0], v[1]);
    }
}

// ---------------------------------------------------------------------------
// fp16x2 GEMM via mma.sync: C[M,N] = A[M,K] @ W[K,N] (+bias)(+GELU)
// A: fp16 [M,K]. W: pre-split fp16 hi/lo [K,N] planes, both via cp.async.
// CTA 256x128, 8 warps of 64x64 (4x2 warps), BK=64, double-buffered.
// ---------------------------------------------------------------------------
__device__ __forceinline__ void stage_loadA(uint32_t sdst, const __half* A,
                                            int rowBase, int K, int k0, int tid)
{
    #pragma unroll
    for (int i = 0; i < 8; i++) {
        int idx = tid + i * 256;           // 0..2047
        int r  = idx >> 3;
        int ch = idx & 7;
        uint32_t so = (uint32_t)r * AROWB + (uint32_t)ch * 16;
        cp_async16(sdst + so, A + (size_t)(rowBase + r) * K + k0 + ch * 8);
    }
}

__device__ __forceinline__ void stage_loadB(uint32_t sdst, const __half* Bhi,
                                            const __half* Blo, int Nw, int colW,
                                            int k0, int tid)
{
    #pragma unroll
    for (int i = 0; i < 4; i++) {
        int idx = tid + i * 256;           // 0..1023
        int r  = idx >> 4;                 // row 0..63
        int ch = idx & 15;                 // 16B chunk 0..15
        uint32_t so = (uint32_t)r * BROWB + (uint32_t)ch * 16;
        size_t g = (size_t)(k0 + r) * Nw + colW + ch * 8;
        cp_async16(sdst + so,         Bhi + g);
        cp_async16(sdst + BHALF + so, Blo + g);
    }
}

template<int ACT, int OUTH>
__global__ __launch_bounds__(256) void gemm_mma(const __half* __restrict__ A,
                                                const __half* __restrict__ Whi,
                                                const __half* __restrict__ Wlo,
                                                const __half* __restrict__ Whib,
                                                const __half* __restrict__ Wlob,
                                                const __half* __restrict__ Whic,
                                                const __half* __restrict__ Wloc,
                                                const float* __restrict__ bias,
                                                float* __restrict__ C,
                                                __half* __restrict__ Ch,
                                                int M, int Nw, int K, int ldC)
{
    extern __shared__ char smem[];
    const uint32_t sb = smem_u32(smem);
    const int tid  = threadIdx.x;
    const int wid  = tid >> 5;
    const int lane = tid & 31;
    const int rowBase = blockIdx.x * BM;

    const __half* Bhi = Whi;
    const __half* Blo = Wlo;
    int colW;
    if (Whib) {
        int wsel = blockIdx.y >> 3;
        if (wsel == 1)      { Bhi = Whib; Blo = Wlob; }
        else if (wsel == 2) { Bhi = Whic; Blo = Wloc; }
        colW = (blockIdx.y & 7) * BN;
    } else {
        colW = blockIdx.y * BN;
    }
    const int colC = blockIdx.y * BN;

    const int m0 = (wid >> 1) * 64;     // warp M offset (4 rows of warps)
    const int n0 = (wid & 1) * 64;      // warp N offset (2 cols of warps)
    const int g  = lane >> 3;
    const int lr = lane & 7;

    float acc[4][8][4];
    #pragma unroll
    for (int mt = 0; mt < 4; mt++)
        #pragma unroll
        for (int nt = 0; nt < 8; nt++)
            #pragma unroll
            for (int e = 0; e < 4; e++) acc[mt][nt][e] = 0.0f;

    const int KT = K / BK;

    stage_loadA(sb, A, rowBase, K, 0, tid);
    stage_loadB(sb + BBASE, Bhi, Blo, Nw, colW, 0, tid);
    cp_commit();

    for (int it = 0; it < KT; it++) {
        const int buf = it & 1;
        if (it + 1 < KT) {
            stage_loadA(sb + (buf ^ 1) * ASTG, A, rowBase, K, (it + 1) * BK, tid);
            stage_loadB(sb + BBASE + (buf ^ 1) * BSTG, Bhi, Blo, Nw, colW, (it + 1) * BK, tid);
            cp_commit();
            cp_wait1();
        } else {
            cp_wait0();
        }
        __syncthreads();

        const uint32_t aB = sb + buf * ASTG;
        const uint32_t bB = sb + BBASE + buf * BSTG;
        #pragma unroll
        for (int ks = 0; ks < 4; ks++) {
            uint32_t Af[4][4];
            #pragma unroll
            for (int mt = 0; mt < 4; mt++) {
                int r  = m0 + mt * 16 + (g & 1) * 8 + lr;
                int ch = ks * 2 + (g >> 1);
                uint32_t ad = aB + (uint32_t)r * AROWB + (uint32_t)ch * 16;
                ldmx4(ad, Af[mt][0], Af[mt][1], Af[mt][2], Af[mt][3]);
            }
            uint32_t Bh[8][2], Bl[8][2];
            #pragma unroll
            for (int p = 0; p < 4; p++) {
                int kr = ks * 16 + (lane & 15);
                int nc = n0 + p * 16 + (lane >> 4) * 8;
                uint32_t bd = bB + (uint32_t)kr * BROWB + (uint32_t)nc * 2;
                ldmx4t(bd,         Bh[2*p][0], Bh[2*p][1], Bh[2*p+1][0], Bh[2*p+1][1]);
                ldmx4t(bd + BHALF, Bl[2*p][0], Bl[2*p][1], Bl[2*p+1][0], Bl[2*p+1][1]);
            }
            #pragma unroll
            for (int mt = 0; mt < 4; mt++)
                #pragma unroll
                for (int nt = 0; nt < 8; nt++) {
                    mma_f16(acc[mt][nt], Af[mt], Bh[nt]);
                    mma_f16(acc[mt][nt], Af[mt], Bl[nt]);
                }
        }
        __syncthreads();
    }

    // Epilogue
    const int crow = lane >> 2;
    const int ccol = (lane & 3) * 2;
    #pragma unroll
    for (int mt = 0; mt < 4; mt++) {
        #pragma unroll
        for (int nt = 0; nt < 8; nt++) {
            int col = colC + n0 + nt * 8 + ccol;
            float b0 = 0.0f, b1 = 0.0f;
            if (bias) { b0 = __ldg(bias + col); b1 = __ldg(bias + col + 1); }
            #pragma unroll
            for (int half = 0; half < 2; half++) {
                int row = rowBase + m0 + mt * 16 + crow + half * 8;
                float v0 = acc[mt][nt][half * 2 + 0] + b0;
                float v1 = acc[mt][nt][half * 2 + 1] + b1;
                if (ACT == 1) {
                    v0 = 0.5f * v0 * (1.0f + erff(v0 * 0.7071067811865476f));
                    v1 = 0.5f * v1 * (1.0f + erff(v1 * 0.7071067811865476f));
                }
                if (OUTH) {
                    *reinterpret_cast<uint32_t*>(Ch + (size_t)row * ldC + col) = pack_h2(v0, v1);
                } else {
                    *reinterpret_cast<float2*>(&C[(size_t)row * ldC + col]) = make_float2(v0, v1);
                }
            }
        }
    }
}

// ---------------------------------------------------------------------------
// Flash attention (fp32) on packed qkv [NT, 3072]; emits fp16 ctx plane.
// ---------------------------------------------------------------------------
__global__ __launch_bounds__(128) void attn_kernel(const float* __restrict__ QKV,
                                                   const int* __restrict__ x,
                                                   __half* __restrict__ Oh)
{
    __shared__ float Ks[32][64];
    __shared__ float Vs[32][64];
    __shared__ int   validS[32];

    const int bh = blockIdx.x;
    const int b  = bh >> 4;
    const int h  = bh & 15;
    const int qt = blockIdx.y;
    const int tid = threadIdx.x;       // 0..127
    const int qrow = qt * 128 + tid;
    const int tQ = b * SS + qrow;

    const float* qp = QKV + (size_t)tQ * QKVW + h * DKH;
    float qreg[64], acc[64];
    #pragma unroll
    for (int d = 0; d < 64; d += 4) {
        float4 f = *reinterpret_cast<const float4*>(qp + d);
        qreg[d] = f.x; qreg[d+1] = f.y; qreg[d+2] = f.z; qreg[d+3] = f.w;
    }
    #pragma unroll
    for (int d = 0; d < 64; d++) acc[d] = 0.0f;

    float mrun = -1e30f, lsum = 0.0f;
    const int ntiles = 4 * qt + 4;

    const int lrow = tid >> 2;
    const int lcol = (tid & 3) * 16;

    for (int kt = 0; kt < ntiles; kt++) {
        const int kbase = kt * 32;
        {
            size_t off = (size_t)(b * SS + kbase + lrow) * QKVW + h * DKH + lcol;
            #pragma unroll
            for (int q = 0; q < 4; q++) {
                *reinterpret_cast<float4*>(&Ks[lrow][lcol + q * 4]) =
                    *reinterpret_cast<const float4*>(QKV + off + 1024 + q * 4);
                *reinterpret_cast<float4*>(&Vs[lrow][lcol + q * 4]) =
                    *reinterpret_cast<const float4*>(QKV + off + 2048 + q * 4);
            }
        }
        if (tid < 32) validS[tid] = (x[b * SS + kbase + tid] != 0);
        __syncthreads();

        int jmax = qrow - kbase + 1;
        if (jmax > 32) jmax = 32;
        if (jmax > 0) {
            float s[32];
            float tmax = -1e30f;
            #pragma unroll
            for (int j = 0; j < 32; j++) {
                if (j < jmax) {
                    float sum = 0.0f;
                    const float4* kr = reinterpret_cast<const float4*>(Ks[j]);
                    #pragma unroll
                    for (int dq = 0; dq < 16; dq++) {
                        float4 k4 = kr[dq];
                        sum += qreg[4*dq]   * k4.x;
                        sum += qreg[4*dq+1] * k4.y;
                        sum += qreg[4*dq+2] * k4.z;
                        sum += qreg[4*dq+3] * k4.w;
                    }
                    sum *= 0.125f;
                    if (!validS[j]) sum = -1e30f;
                    s[j] = sum;
                    tmax = fmaxf(tmax, sum);
                } else {
                    s[j] = -1e30f;
                }
            }
            float mnew = fmaxf(mrun, tmax);
            float corr = __expf(mrun - mnew);
            lsum *= corr;
            #pragma unroll
            for (int d = 0; d < 64; d++) acc[d] *= corr;
            mrun = mnew;
            #pragma unroll
            for (int j = 0; j < 32; j++) {
                float p = __expf(s[j] - mrun);
                lsum += p;
                const float4* vr = reinterpret_cast<const float4*>(Vs[j]);
                #pragma unroll
                for (int dq = 0; dq < 16; dq++) {
                    float4 v4 = vr[dq];
                    acc[4*dq]   += p * v4.x;
                    acc[4*dq+1] += p * v4.y;
                    acc[4*dq+2] += p * v4.z;
                    acc[4*dq+3] += p * v4.w;
                }
            }
        }
        __syncthreads();
    }

    float inv = 1.0f / lsum;
    size_t ob = (size_t)tQ * DD + h * DKH;
    #pragma unroll
    for (int d = 0; d < 64; d += 2) {
        *reinterpret_cast<uint32_t*>(Oh + ob + d) = pack_h2(acc[d] * inv, acc[d+1] * inv);
    }
}

// ---------------------------------------------------------------------------
// Residual add + LayerNorm (in place on h); also emits fp16 activation plane
// ---------------------------------------------------------------------------
__device__ __forceinline__ float block_sum(float v, float* red)
{
    #pragma unroll
    for (int o = 16; o > 0; o >>= 1) v += __shfl_xor_sync(0xffffffffu, v, o);
    int w = threadIdx.x >> 5;
    if ((threadIdx.x & 31) == 0) red[w] = v;
    __syncthreads();
    if (threadIdx.x < 32) {
        float t = (threadIdx.x < 8) ? red[threadIdx.x] : 0.0f;
        #pragma unroll
        for (int o = 4; o > 0; o >>= 1) t += __shfl_xor_sync(0xffffffffu, t, o);
        if (threadIdx.x == 0) red[0] = t;
    }
    __syncthreads();
    float r = red[0];
    __syncthreads();
    return r;
}

__global__ __launch_bounds__(256) void add_ln_kernel(float* __restrict__ h,
                                                     const float* __restrict__ r,
                                                     const float* __restrict__ g,
                                                     const float* __restrict__ bta,
                                                     __half* __restrict__ ah)
{
    __shared__ float red[32];
    const int t = blockIdx.x;
    const int tid = threadIdx.x;
    size_t base = (size_t)t * DD;
    float v[4];
    float sum = 0.0f;
    #pragma unroll
    for (int i = 0; i < 4; i++) {
        int d = tid * 2 + (i & 1) + (i >> 1) * 512;
        float val = h[base + d] + r[base + d];
        v[i] = val;
        sum += val;
    }
    float tot = block_sum(sum, red);
    float mu = tot * (1.0f / (float)DD);
    float sq = 0.0f;
    #pragma unroll
    for (int i = 0; i < 4; i++) { float dvi = v[i] - mu; sq += dvi * dvi; }
    float var = block_sum(sq, red) * (1.0f / (float)DD);
    float rs = rsqrtf(var + 1e-5f);
    #pragma unroll
    for (int p = 0; p < 2; p++) {
        int d = tid * 2 + p * 512;
        float o0 = (v[p*2]   - mu) * rs * g[d]     + bta[d];
        float o1 = (v[p*2+1] - mu) * rs * g[d + 1] + bta[d + 1];
        h[base + d]     = o0;
        h[base + d + 1] = o1;
        *reinterpret_cast<uint32_t*>(ah + base + d) = pack_h2(o0, o1);
    }
}

// ---------------------------------------------------------------------------
// Launch
// ---------------------------------------------------------------------------
extern "C" void kernel_launch(void* const* d_in, const int* in_sizes, int n_in,
                              void* d_out, int out_size)
{
    const int*   x    = (const int*)  d_in[0];
    const float* emb  = (const float*)d_in[1];
    const float* Wq   = (const float*)d_in[2];
    const float* Wk   = (const float*)d_in[3];
    const float* Wv   = (const float*)d_in[4];
    const float* Wo   = (const float*)d_in[5];
    const float* bo   = (const float*)d_in[6];
    const float* ln1g = (const float*)d_in[7];
    const float* ln1b = (const float*)d_in[8];
    const float* ln2g = (const float*)d_in[9];
    const float* ln2b = (const float*)d_in[10];
    const float* W1   = (const float*)d_in[11];
    const float* b1   = (const float*)d_in[12];
    const float* W2   = (const float*)d_in[13];
    const float* b2   = (const float*)d_in[14];
    const float* Wout = (const float*)d_in[15];
    const float* bout = (const float*)d_in[16];
    float* out = (float*)d_out;

    void* p;
    cudaGetSymbolAddress(&p, g_h);   float* h   = (float*)p;
    cudaGetSymbolAddress(&p, g_qkv); float* qkv = (float*)p;
    cudaGetSymbolAddress(&p, g_tmp); float* tmp = (float*)p;
    cudaGetSymbolAddress(&p, g_ah);  __half* ah = (__half*)p;
    cudaGetSymbolAddress(&p, g_fh);  __half* fh = (__half*)p;
    cudaGetSymbolAddress(&p, g_whi); __half* whi = (__half*)p;
    cudaGetSymbolAddress(&p, g_wlo); __half* wlo = (__half*)p;

    cudaFuncSetAttribute(gemm_mma<0,0>, cudaFuncAttributeMaxDynamicSharedMemorySize, GEMM_SMEM);
    cudaFuncSetAttribute(gemm_mma<1,1>, cudaFuncAttributeMaxDynamicSharedMemorySize, GEMM_SMEM);

    // Pre-split all weights to fp16 hi/lo planes (streaming, once per launch)
    wsplit_kernel<<<4096, 256>>>(Wq,   whi + OFF_WQ,   wlo + OFF_WQ,   LL*DD*DD/4);
    wsplit_kernel<<<4096, 256>>>(Wk,   whi + OFF_WK,   wlo + OFF_WK,   LL*DD*DD/4);
    wsplit_kernel<<<4096, 256>>>(Wv,   whi + OFF_WV,   wlo + OFF_WV,   LL*DD*DD/4);
    wsplit_kernel<<<4096, 256>>>(Wo,   whi + OFF_WO,   wlo + OFF_WO,   LL*DD*DD/4);
    wsplit_kernel<<<8192, 256>>>(W1,   whi + OFF_W1,   wlo + OFF_W1,   LL*DD*FF/4);
    wsplit_kernel<<<8192, 256>>>(W2,   whi + OFF_W2,   wlo + OFF_W2,   LL*DD*FF/4);
    wsplit_kernel<<<8192, 256>>>(Wout, whi + OFF_WOUT, wlo + OFF_WOUT, DD*VV/4);

    embed_kernel<<<NT, 256>>>(x, emb, h, ah);

    const dim3 gQKV(NT/BM, QKVW/BN);  // 16 x 24 (fused q|k|v)
    const dim3 gD(NT/BM, DD/BN);      // 16 x 8
    const dim3 gF(NT/BM, FF/BN);      // 16 x 32
    const dim3 gV(NT/BM, VV/BN);      // 16 x 250

    for (int l = 0; l < LL; l++) {
        const size_t oD = (size_t)l * DD * DD;
        const size_t oF = (size_t)l * DD * FF;

        // Fused QKV projection (one launch, W planes selected per block)
        gemm_mma<0,0><<<gQKV, 256, GEMM_SMEM>>>(ah,
            whi + OFF_WQ + oD, wlo + OFF_WQ + oD,
            whi + OFF_WK + oD, wlo + OFF_WK + oD,
            whi + OFF_WV + oD, wlo + OFF_WV + oD,
            nullptr, qkv, nullptr, NT, DD, DD, QKVW);

        attn_kernel<<<dim3(BB * HH, SS / 128), 128>>>(qkv, x, ah);   // ctx -> fp16 plane

        gemm_mma<0,0><<<gD, 256, GEMM_SMEM>>>(ah,
            whi + OFF_WO + oD, wlo + OFF_WO + oD,
            nullptr, nullptr, nullptr, nullptr,
            bo + l * DD, tmp, nullptr, NT, DD, DD, DD);
        add_ln_kernel<<<NT, 256>>>(h, tmp, ln1g + l * DD, ln1b + l * DD, ah);

        gemm_mma<1,1><<<gF, 256, GEMM_SMEM>>>(ah,
            whi + OFF_W1 + oF, wlo + OFF_W1 + oF,
            nullptr, nullptr, nullptr, nullptr,
            b1 + l * FF, nullptr, fh, NT, FF, DD, FF);
        gemm_mma<0,0><<<gD, 256, GEMM_SMEM>>>(fh,
            whi + OFF_W2 + oF, wlo + OFF_W2 + oF,
            nullptr, nullptr, nullptr, nullptr,
            b2 + l * DD, tmp, nullptr, NT, DD, FF, DD);
        add_ln_kernel<<<NT, 256>>>(h, tmp, ln2g + l * DD, ln2b + l * DD, ah);
    }

    gemm_mma<0,0><<<gV, 256, GEMM_SMEM>>>(ah,
        whi + OFF_WOUT, wlo + OFF_WOUT,
        nullptr, nullptr, nullptr, nullptr,
        bout, out, nullptr, NT, VV, DD, VV);
}

// round 10
// speedup vs baseline: 1.4874x; 1.0387x over previous
#include <cuda_runtime.h>
#include <cuda_fp16.h>
#include <cstdint>
#include <cmath>

// Problem constants
#define BB   4
#define SS   1024
#define DD   1024
#define HH   16
#define DKH  64
#define LL   4
#define FF   4096
#define VV   32000
#define NT   (BB*SS)   // 4096 tokens
#define QKVW 3072      // packed q|k|v width

// GEMM tile config: CTA 128x128, warp 64x32 (2x4 warps), BK=64, 2 CTAs/SM
#define BM 128
#define BN 128
#define BK 64
#define AROWB 144                  // A smem row: 128B data + 16B pad
#define ASTG (BM*AROWB)            // one 128xBK fp16 matrix: 18432 B
#define BROWB 272                  // B smem row: 256B data + 16B pad
#define BHALF (64*BROWB)           // one 64x128 fp16 plane: 17408 B
#define BSTG (2*BHALF)             // hi+lo per stage: 34816 B
#define BBASE (2*ASTG)             // 36864 (A double-buffered)
#define GEMM_SMEM (BBASE + 2*BSTG) // 106496 B  (x2 CTAs = 212992 <= 227KB)

// Pre-split weight plane offsets (elements)
#define OFF_WQ   0
#define OFF_WK   (4*DD*DD)
#define OFF_WV   (8*DD*DD)
#define OFF_WO   (12*DD*DD)
#define OFF_W1   (16*DD*DD)
#define OFF_W2   (OFF_W1 + LL*DD*FF)
#define OFF_WOUT (OFF_W2 + LL*DD*FF)
#define WTOT     (OFF_WOUT + (size_t)DD*VV)   // 83,099,648 elems

// ---------------------------------------------------------------------------
// Scratch (device globals — no runtime allocation allowed)
// ---------------------------------------------------------------------------
__device__ float g_h  [NT*(size_t)DD];
__device__ float g_qkv[NT*(size_t)QKVW];
__device__ float g_tmp[NT*(size_t)DD];
__device__ __half g_ah [NT*(size_t)DD];
__device__ __half g_fh [NT*(size_t)FF];
__device__ __half g_whi[WTOT];
__device__ __half g_wlo[WTOT];

// ---------------------------------------------------------------------------
// PTX helpers (arch-agnostic: sm_80-era instructions only)
// ---------------------------------------------------------------------------
__device__ __forceinline__ uint32_t smem_u32(const void* p) {
    uint32_t a;
    asm("{ .reg .u64 t; cvta.to.shared.u64 t, %1; cvt.u32.u64 %0, t; }" : "=r"(a) : "l"(p));
    return a;
}
__device__ __forceinline__ void cp_async16(uint32_t dst, const void* src) {
    asm volatile("cp.async.cg.shared.global [%0], [%1], 16;" :: "r"(dst), "l"(src));
}
__device__ __forceinline__ void cp_commit() {
    asm volatile("cp.async.commit_group;");
}
__device__ __forceinline__ void cp_wait1() {
    asm volatile("cp.async.wait_group 1;");
}
__device__ __forceinline__ void cp_wait0() {
    asm volatile("cp.async.wait_group 0;");
}
__device__ __forceinline__ void ldmx4(uint32_t addr, uint32_t& r0, uint32_t& r1,
                                      uint32_t& r2, uint32_t& r3) {
    asm volatile("ldmatrix.sync.aligned.m8n8.x4.shared.b16 {%0,%1,%2,%3}, [%4];"
                 : "=r"(r0), "=r"(r1), "=r"(r2), "=r"(r3) : "r"(addr));
}
__device__ __forceinline__ void ldmx4t(uint32_t addr, uint32_t& r0, uint32_t& r1,
                                       uint32_t& r2, uint32_t& r3) {
    asm volatile("ldmatrix.sync.aligned.m8n8.x4.trans.shared.b16 {%0,%1,%2,%3}, [%4];"
                 : "=r"(r0), "=r"(r1), "=r"(r2), "=r"(r3) : "r"(addr));
}
__device__ __forceinline__ void mma_f16(float* c, const uint32_t* a, const uint32_t* b) {
    asm volatile("mma.sync.aligned.m16n8k16.row.col.f32.f16.f16.f32 "
                 "{%0,%1,%2,%3}, {%4,%5,%6,%7}, {%8,%9}, {%0,%1,%2,%3};"
                 : "+f"(c[0]), "+f"(c[1]), "+f"(c[2]), "+f"(c[3])
                 : "r"(a[0]), "r"(a[1]), "r"(a[2]), "r"(a[3]), "r"(b[0]), "r"(b[1]));
}
__device__ __forceinline__ uint32_t h2_bits(__half2 v) {
    return *reinterpret_cast<uint32_t*>(&v);
}
// split a float pair into fp16 hi/lo words (hi + lo ~= x to ~2^-22)
__device__ __forceinline__ void split2h(float a, float b, uint32_t& hw, uint32_t& lw) {
    __half2 h = __floats2half2_rn(a, b);
    float la = a - __low2float(h);
    float lb = b - __high2float(h);
    __half2 l = __floats2half2_rn(la, lb);
    hw = h2_bits(h);
    lw = h2_bits(l);
}
__device__ __forceinline__ uint32_t pack_h2(float a, float b) {
    return h2_bits(__floats2half2_rn(a, b));
}

// ---------------------------------------------------------------------------
// Weight split: W fp32 -> hi/lo fp16 planes (same layout), streaming
// ---------------------------------------------------------------------------
__global__ __launch_bounds__(256) void wsplit_kernel(const float* __restrict__ W,
                                                     __half* __restrict__ hi,
                                                     __half* __restrict__ lo,
                                                     int n4)   // n/4
{
    const float4* W4 = reinterpret_cast<const float4*>(W);
    uint2* H2 = reinterpret_cast<uint2*>(hi);
    uint2* L2 = reinterpret_cast<uint2*>(lo);
    for (int i = blockIdx.x * blockDim.x + threadIdx.x; i < n4; i += gridDim.x * blockDim.x) {
        float4 f = W4[i];
        uint2 h, l;
        split2h(f.x, f.y, h.x, l.x);
        split2h(f.z, f.w, h.y, l.y);
        H2[i] = h;
        L2[i] = l;
    }
}

// ---------------------------------------------------------------------------
// Embedding + positional encoding; writes fp32 h AND fp16 activation plane
// ---------------------------------------------------------------------------
__global__ __launch_bounds__(256) void embed_kernel(const int* __restrict__ x,
                                                    const float* __restrict__ emb,
                                                    float* __restrict__ h,
                                                    __half* __restrict__ ah)
{
    int t = blockIdx.x;
    int s = t & (SS - 1);
    int tok = x[t];
    const float* e = emb + (size_t)tok * DD;
    const float negln = -9.210340371976184f;
    size_t base = (size_t)t * DD;
    for (int d0 = threadIdx.x * 2; d0 < DD; d0 += blockDim.x * 2) {
        float v[2];
        #pragma unroll
        for (int j = 0; j < 2; j++) {
            int d = d0 + j;
            int i2 = (d >> 1) * 2;
            float div = expf((float)i2 * (negln / (float)DD));
            float ang = (float)s * div;
            float pe = (d & 1) ? cosf(ang) : sinf(ang);
            v[j] = e[d] * 32.0f + pe;
        }
        h[base + d0] = v[0];
        h[base + d0 + 1] = v[1];
        *reinterpret_cast<uint32_t*>(ah + base + d0) = pack_h2(v[0], v[1]);
    }
}

// ---------------------------------------------------------------------------
// fp16x2 GEMM via mma.sync: C[M,N] = A[M,K] @ W[K,N] (+bias)(+GELU)
// A: fp16 [M,K]. W: pre-split fp16 hi/lo [K,N] planes, both via cp.async.
// CTA 128x128, 8 warps of 64x32 (2x4), BK=64, double-buffered, 2 CTAs/SM.
// ---------------------------------------------------------------------------
__device__ __forceinline__ void stage_loadA(uint32_t sdst, const __half* A,
                                            int rowBase, int K, int k0, int tid)
{
    #pragma unroll
    for (int i = 0; i < 4; i++) {
        int idx = tid + i * 256;           // 0..1023
        int r  = idx >> 3;
        int ch = idx & 7;
        uint32_t so = (uint32_t)r * AROWB + (uint32_t)ch * 16;
        cp_async16(sdst + so, A + (size_t)(rowBase + r) * K + k0 + ch * 8);
    }
}

__device__ __forceinline__ void stage_loadB(uint32_t sdst, const __half* Bhi,
                                            const __half* Blo, int Nw, int colW,
                                            int k0, int tid)
{
    #pragma unroll
    for (int i = 0; i < 4; i++) {
        int idx = tid + i * 256;           // 0..1023
        int r  = idx >> 4;                 // row 0..63
        int ch = idx & 15;                 // 16B chunk 0..15
        uint32_t so = (uint32_t)r * BROWB + (uint32_t)ch * 16;
        size_t g = (size_t)(k0 + r) * Nw + colW + ch * 8;
        cp_async16(sdst + so,         Bhi + g);
        cp_async16(sdst + BHALF + so, Blo + g);
    }
}

template<int ACT, int OUTH>
__global__ __launch_bounds__(256, 2) void gemm_mma(const __half* __restrict__ A,
                                                   const __half* __restrict__ Whi,
                                                   const __half* __restrict__ Wlo,
                                                   const __half* __restrict__ Whib,
                                                   const __half* __restrict__ Wlob,
                                                   const __half* __restrict__ Whic,
                                                   const __half* __restrict__ Wloc,
                                                   const float* __restrict__ bias,
                                                   float* __restrict__ C,
                                                   __half* __restrict__ Ch,
                                                   int M, int Nw, int K, int ldC)
{
    extern __shared__ char smem[];
    const uint32_t sb = smem_u32(smem);
    const int tid  = threadIdx.x;
    const int wid  = tid >> 5;
    const int lane = tid & 31;
    const int rowBase = blockIdx.x * BM;

    const __half* Bhi = Whi;
    const __half* Blo = Wlo;
    int colW;
    if (Whib) {
        int wsel = blockIdx.y >> 3;
        if (wsel == 1)      { Bhi = Whib; Blo = Wlob; }
        else if (wsel == 2) { Bhi = Whic; Blo = Wloc; }
        colW = (blockIdx.y & 7) * BN;
    } else {
        colW = blockIdx.y * BN;
    }
    const int colC = blockIdx.y * BN;

    const int m0 = (wid >> 2) * 64;     // warp M offset (2 rows of warps)
    const int n0 = (wid & 3) * 32;      // warp N offset (4 cols of warps)
    const int g  = lane >> 3;
    const int lr = lane & 7;

    float acc[4][4][4];
    #pragma unroll
    for (int mt = 0; mt < 4; mt++)
        #pragma unroll
        for (int nt = 0; nt < 4; nt++)
            #pragma unroll
            for (int e = 0; e < 4; e++) acc[mt][nt][e] = 0.0f;

    const int KT = K / BK;

    stage_loadA(sb, A, rowBase, K, 0, tid);
    stage_loadB(sb + BBASE, Bhi, Blo, Nw, colW, 0, tid);
    cp_commit();

    for (int it = 0; it < KT; it++) {
        const int buf = it & 1;
        if (it + 1 < KT) {
            stage_loadA(sb + (buf ^ 1) * ASTG, A, rowBase, K, (it + 1) * BK, tid);
            stage_loadB(sb + BBASE + (buf ^ 1) * BSTG, Bhi, Blo, Nw, colW, (it + 1) * BK, tid);
            cp_commit();
            cp_wait1();
        } else {
            cp_wait0();
        }
        __syncthreads();

        const uint32_t aB = sb + buf * ASTG;
        const uint32_t bB = sb + BBASE + buf * BSTG;
        #pragma unroll
        for (int ks = 0; ks < 4; ks++) {
            uint32_t Af[4][4];
            #pragma unroll
            for (int mt = 0; mt < 4; mt++) {
                int r  = m0 + mt * 16 + (g & 1) * 8 + lr;
                int ch = ks * 2 + (g >> 1);
                uint32_t ad = aB + (uint32_t)r * AROWB + (uint32_t)ch * 16;
                ldmx4(ad, Af[mt][0], Af[mt][1], Af[mt][2], Af[mt][3]);
            }
            uint32_t Bh[4][2], Bl[4][2];
            #pragma unroll
            for (int p = 0; p < 2; p++) {
                int kr = ks * 16 + (lane & 15);
                int nc = n0 + p * 16 + (lane >> 4) * 8;
                uint32_t bd = bB + (uint32_t)kr * BROWB + (uint32_t)nc * 2;
                ldmx4t(bd,         Bh[2*p][0], Bh[2*p][1], Bh[2*p+1][0], Bh[2*p+1][1]);
                ldmx4t(bd + BHALF, Bl[2*p][0], Bl[2*p][1], Bl[2*p+1][0], Bl[2*p+1][1]);
            }
            #pragma unroll
            for (int mt = 0; mt < 4; mt++)
                #pragma unroll
                for (int nt = 0; nt < 4; nt++) {
                    mma_f16(acc[mt][nt], Af[mt], Bh[nt]);
                    mma_f16(acc[mt][nt], Af[mt], Bl[nt]);
                }
        }
        __syncthreads();
    }

    // Epilogue
    const int crow = lane >> 2;
    const int ccol = (lane & 3) * 2;
    #pragma unroll
    for (int mt = 0; mt < 4; mt++) {
        #pragma unroll
        for (int nt = 0; nt < 4; nt++) {
            int col = colC + n0 + nt * 8 + ccol;
            float b0 = 0.0f, b1 = 0.0f;
            if (bias) { b0 = __ldg(bias + col); b1 = __ldg(bias + col + 1); }
            #pragma unroll
            for (int half = 0; half < 2; half++) {
                int row = rowBase + m0 + mt * 16 + crow + half * 8;
                float v0 = acc[mt][nt][half * 2 + 0] + b0;
                float v1 = acc[mt][nt][half * 2 + 1] + b1;
                if (ACT == 1) {
                    v0 = 0.5f * v0 * (1.0f + erff(v0 * 0.7071067811865476f));
                    v1 = 0.5f * v1 * (1.0f + erff(v1 * 0.7071067811865476f));
                }
                if (OUTH) {
                    *reinterpret_cast<uint32_t*>(Ch + (size_t)row * ldC + col) = pack_h2(v0, v1);
                } else {
                    *reinterpret_cast<float2*>(&C[(size_t)row * ldC + col]) = make_float2(v0, v1);
                }
            }
        }
    }
}

// ---------------------------------------------------------------------------
// Flash attention (fp32) on packed qkv [NT, 3072]; emits fp16 ctx plane.
// ---------------------------------------------------------------------------
__global__ __launch_bounds__(128) void attn_kernel(const float* __restrict__ QKV,
                                                   const int* __restrict__ x,
                                                   __half* __restrict__ Oh)
{
    __shared__ float Ks[32][64];
    __shared__ float Vs[32][64];
    __shared__ int   validS[32];

    const int bh = blockIdx.x;
    const int b  = bh >> 4;
    const int h  = bh & 15;
    const int qt = blockIdx.y;
    const int tid = threadIdx.x;       // 0..127
    const int qrow = qt * 128 + tid;
    const int tQ = b * SS + qrow;

    const float* qp = QKV + (size_t)tQ * QKVW + h * DKH;
    float qreg[64], acc[64];
    #pragma unroll
    for (int d = 0; d < 64; d += 4) {
        float4 f = *reinterpret_cast<const float4*>(qp + d);
        qreg[d] = f.x; qreg[d+1] = f.y; qreg[d+2] = f.z; qreg[d+3] = f.w;
    }
    #pragma unroll
    for (int d = 0; d < 64; d++) acc[d] = 0.0f;

    float mrun = -1e30f, lsum = 0.0f;
    const int ntiles = 4 * qt + 4;

    const int lrow = tid >> 2;
    const int lcol = (tid & 3) * 16;

    for (int kt = 0; kt < ntiles; kt++) {
        const int kbase = kt * 32;
        {
            size_t off = (size_t)(b * SS + kbase + lrow) * QKVW + h * DKH + lcol;
            #pragma unroll
            for (int q = 0; q < 4; q++) {
                *reinterpret_cast<float4*>(&Ks[lrow][lcol + q * 4]) =
                    *reinterpret_cast<const float4*>(QKV + off + 1024 + q * 4);
                *reinterpret_cast<float4*>(&Vs[lrow][lcol + q * 4]) =
                    *reinterpret_cast<const float4*>(QKV + off + 2048 + q * 4);
            }
        }
        if (tid < 32) validS[tid] = (x[b * SS + kbase + tid] != 0);
        __syncthreads();

        int jmax = qrow - kbase + 1;
        if (jmax > 32) jmax = 32;
        if (jmax > 0) {
            float s[32];
            float tmax = -1e30f;
            #pragma unroll
            for (int j = 0; j < 32; j++) {
                if (j < jmax) {
                    float sum = 0.0f;
                    const float4* kr = reinterpret_cast<const float4*>(Ks[j]);
                    #pragma unroll
                    for (int dq = 0; dq < 16; dq++) {
                        float4 k4 = kr[dq];
                        sum += qreg[4*dq]   * k4.x;
                        sum += qreg[4*dq+1] * k4.y;
                        sum += qreg[4*dq+2] * k4.z;
                        sum += qreg[4*dq+3] * k4.w;
                    }
                    sum *= 0.125f;
                    if (!validS[j]) sum = -1e30f;
                    s[j] = sum;
                    tmax = fmaxf(tmax, sum);
                } else {
                    s[j] = -1e30f;
                }
            }
            float mnew = fmaxf(mrun, tmax);
            float corr = __expf(mrun - mnew);
            lsum *= corr;
            #pragma unroll
            for (int d = 0; d < 64; d++) acc[d] *= corr;
            mrun = mnew;
            #pragma unroll
            for (int j = 0; j < 32; j++) {
                float p = __expf(s[j] - mrun);
                lsum += p;
                const float4* vr = reinterpret_cast<const float4*>(Vs[j]);
                #pragma unroll
                for (int dq = 0; dq < 16; dq++) {
                    float4 v4 = vr[dq];
                    acc[4*dq]   += p * v4.x;
                    acc[4*dq+1] += p * v4.y;
                    acc[4*dq+2] += p * v4.z;
                    acc[4*dq+3] += p * v4.w;
                }
            }
        }
        __syncthreads();
    }

    float inv = 1.0f / lsum;
    size_t ob = (size_t)tQ * DD + h * DKH;
    #pragma unroll
    for (int d = 0; d < 64; d += 2) {
        *reinterpret_cast<uint32_t*>(Oh + ob + d) = pack_h2(acc[d] * inv, acc[d+1] * inv);
    }
}

// ---------------------------------------------------------------------------
// Residual add + LayerNorm (in place on h); also emits fp16 activation plane
// ---------------------------------------------------------------------------
__device__ __forceinline__ float block_sum(float v, float* red)
{
    #pragma unroll
    for (int o = 16; o > 0; o >>= 1) v += __shfl_xor_sync(0xffffffffu, v, o);
    int w = threadIdx.x >> 5;
    if ((threadIdx.x & 31) == 0) red[w] = v;
    __syncthreads();
    if (threadIdx.x < 32) {
        float t = (threadIdx.x < 8) ? red[threadIdx.x] : 0.0f;
        #pragma unroll
        for (int o = 4; o > 0; o >>= 1) t += __shfl_xor_sync(0xffffffffu, t, o);
        if (threadIdx.x == 0) red[0] = t;
    }
    __syncthreads();
    float r = red[0];
    __syncthreads();
    return r;
}

__global__ __launch_bounds__(256) void add_ln_kernel(float* __restrict__ h,
                                                     const float* __restrict__ r,
                                                     const float* __restrict__ g,
                                                     const float* __restrict__ bta,
                                                     __half* __restrict__ ah)
{
    __shared__ float red[32];
    const int t = blockIdx.x;
    const int tid = threadIdx.x;
    size_t base = (size_t)t * DD;
    float v[4];
    float sum = 0.0f;
    #pragma unroll
    for (int i = 0; i < 4; i++) {
        int d = tid * 2 + (i & 1) + (i >> 1) * 512;
        float val = h[base + d] + r[base + d];
        v[i] = val;
        sum += val;
    }
    float tot = block_sum(sum, red);
    float mu = tot * (1.0f / (float)DD);
    float sq = 0.0f;
    #pragma unroll
    for (int i = 0; i < 4; i++) { float dvi = v[i] - mu; sq += dvi * dvi; }
    float var = block_sum(sq, red) * (1.0f / (float)DD);
    float rs = rsqrtf(var + 1e-5f);
    #pragma unroll
    for (int p = 0; p < 2; p++) {
        int d = tid * 2 + p * 512;
        float o0 = (v[p*2]   - mu) * rs * g[d]     + bta[d];
        float o1 = (v[p*2+1] - mu) * rs * g[d + 1] + bta[d + 1];
        h[base + d]     = o0;
        h[base + d + 1] = o1;
        *reinterpret_cast<uint32_t*>(ah + base + d) = pack_h2(o0, o1);
    }
}

// ---------------------------------------------------------------------------
// Launch
// ---------------------------------------------------------------------------
extern "C" void kernel_launch(void* const* d_in, const int* in_sizes, int n_in,
                              void* d_out, int out_size)
{
    const int*   x    = (const int*)  d_in[0];
    const float* emb  = (const float*)d_in[1];
    const float* Wq   = (const float*)d_in[2];
    const float* Wk   = (const float*)d_in[3];
    const float* Wv   = (const float*)d_in[4];
    const float* Wo   = (const float*)d_in[5];
    const float* bo   = (const float*)d_in[6];
    const float* ln1g = (const float*)d_in[7];
    const float* ln1b = (const float*)d_in[8];
    const float* ln2g = (const float*)d_in[9];
    const float* ln2b = (const float*)d_in[10];
    const float* W1   = (const float*)d_in[11];
    const float* b1   = (const float*)d_in[12];
    const float* W2   = (const float*)d_in[13];
    const float* b2   = (const float*)d_in[14];
    const float* Wout = (const float*)d_in[15];
    const float* bout = (const float*)d_in[16];
    float* out = (float*)d_out;

    void* p;
    cudaGetSymbolAddress(&p, g_h);   float* h   = (float*)p;
    cudaGetSymbolAddress(&p, g_qkv); float* qkv = (float*)p;
    cudaGetSymbolAddress(&p, g_tmp); float* tmp = (float*)p;
    cudaGetSymbolAddress(&p, g_ah);  __half* ah = (__half*)p;
    cudaGetSymbolAddress(&p, g_fh);  __half* fh = (__half*)p;
    cudaGetSymbolAddress(&p, g_whi); __half* whi = (__half*)p;
    cudaGetSymbolAddress(&p, g_wlo); __half* wlo = (__half*)p;

    cudaFuncSetAttribute(gemm_mma<0,0>, cudaFuncAttributeMaxDynamicSharedMemorySize, GEMM_SMEM);
    cudaFuncSetAttribute(gemm_mma<1,1>, cudaFuncAttributeMaxDynamicSharedMemorySize, GEMM_SMEM);

    // Pre-split all weights to fp16 hi/lo planes (streaming, once per launch)
    wsplit_kernel<<<4096, 256>>>(Wq,   whi + OFF_WQ,   wlo + OFF_WQ,   LL*DD*DD/4);
    wsplit_kernel<<<4096, 256>>>(Wk,   whi + OFF_WK,   wlo + OFF_WK,   LL*DD*DD/4);
    wsplit_kernel<<<4096, 256>>>(Wv,   whi + OFF_WV,   wlo + OFF_WV,   LL*DD*DD/4);
    wsplit_kernel<<<4096, 256>>>(Wo,   whi + OFF_WO,   wlo + OFF_WO,   LL*DD*DD/4);
    wsplit_kernel<<<8192, 256>>>(W1,   whi + OFF_W1,   wlo + OFF_W1,   LL*DD*FF/4);
    wsplit_kernel<<<8192, 256>>>(W2,   whi + OFF_W2,   wlo + OFF_W2,   LL*DD*FF/4);
    wsplit_kernel<<<8192, 256>>>(Wout, whi + OFF_WOUT, wlo + OFF_WOUT, DD*VV/4);

    embed_kernel<<<NT, 256>>>(x, emb, h, ah);

    const dim3 gQKV(NT/BM, QKVW/BN);  // 32 x 24 (fused q|k|v)
    const dim3 gD(NT/BM, DD/BN);      // 32 x 8
    const dim3 gF(NT/BM, FF/BN);      // 32 x 32
    const dim3 gV(NT/BM, VV/BN);      // 32 x 250

    for (int l = 0; l < LL; l++) {
        const size_t oD = (size_t)l * DD * DD;
        const size_t oF = (size_t)l * DD * FF;

        // Fused QKV projection (one launch, W planes selected per block)
        gemm_mma<0,0><<<gQKV, 256, GEMM_SMEM>>>(ah,
            whi + OFF_WQ + oD, wlo + OFF_WQ + oD,
            whi + OFF_WK + oD, wlo + OFF_WK + oD,
            whi + OFF_WV + oD, wlo + OFF_WV + oD,
            nullptr, qkv, nullptr, NT, DD, DD, QKVW);

        attn_kernel<<<dim3(BB * HH, SS / 128), 128>>>(qkv, x, ah);   // ctx -> fp16 plane

        gemm_mma<0,0><<<gD, 256, GEMM_SMEM>>>(ah,
            whi + OFF_WO + oD, wlo + OFF_WO + oD,
            nullptr, nullptr, nullptr, nullptr,
            bo + l * DD, tmp, nullptr, NT, DD, DD, DD);
        add_ln_kernel<<<NT, 256>>>(h, tmp, ln1g + l * DD, ln1b + l * DD, ah);

        gemm_mma<1,1><<<gF, 256, GEMM_SMEM>>>(ah,
            whi + OFF_W1 + oF, wlo + OFF_W1 + oF,
            nullptr, nullptr, nullptr, nullptr,
            b1 + l * FF, nullptr, fh, NT, FF, DD, FF);
        gemm_mma<0,0><<<gD, 256, GEMM_SMEM>>>(fh,
            whi + OFF_W2 + oF, wlo + OFF_W2 + oF,
            nullptr, nullptr, nullptr, nullptr,
            b2 + l * DD, tmp, nullptr, NT, DD, FF, DD);
        add_ln_kernel<<<NT, 256>>>(h, tmp, ln2g + l * DD, ln2b + l * DD, ah);
    }

    gemm_mma<0,0><<<gV, 256, GEMM_SMEM>>>(ah,
        whi + OFF_WOUT, wlo + OFF_WOUT,
        nullptr, nullptr, nullptr, nullptr,
        bout, out, nullptr, NT, VV, DD, VV);
}

// round 11
// speedup vs baseline: 1.6068x; 1.0803x over previous
#include <cuda_runtime.h>
#include <cuda_fp16.h>
#include <cstdint>
#include <cmath>

// Problem constants
#define BB   4
#define SS   1024
#define DD   1024
#define HH   16
#define DKH  64
#define LL   4
#define FF   4096
#define VV   32000
#define NT   (BB*SS)   // 4096 tokens
#define QKVW 3072      // packed q|k|v width

// GEMM tile config: CTA 128x128, warp 64x32 (2x4 warps), BK=64, 2 CTAs/SM
#define BM 128
#define BN 128
#define BK 64
#define AROWB 144                  // A smem row: 128B data + 16B pad
#define ASTG (BM*AROWB)            // one 128xBK fp16 matrix: 18432 B
#define BROWB 272                  // B smem row: 256B data + 16B pad
#define BHALF (64*BROWB)           // one 64x128 fp16 plane: 17408 B
#define BSTG (2*BHALF)             // hi+lo per stage: 34816 B
#define BBASE (2*ASTG)             // 36864 (A double-buffered)
#define GEMM_SMEM (BBASE + 2*BSTG) // 106496 B  (x2 CTAs = 212992 <= 227KB)

// Pre-split weight plane offsets (elements)
#define OFF_WQ   0
#define OFF_WK   (4*DD*DD)
#define OFF_WV   (8*DD*DD)
#define OFF_WO   (12*DD*DD)
#define OFF_W1   (16*DD*DD)
#define OFF_W2   (OFF_W1 + LL*DD*FF)
#define OFF_WOUT (OFF_W2 + LL*DD*FF)
#define WTOT     (OFF_WOUT + (size_t)DD*VV)   // 83,099,648 elems

// ---------------------------------------------------------------------------
// Scratch (device globals — no runtime allocation allowed)
// ---------------------------------------------------------------------------
__device__ float g_h  [NT*(size_t)DD];
__device__ float g_qkv[NT*(size_t)QKVW];
__device__ float g_tmp[NT*(size_t)DD];
__device__ __half g_ah [NT*(size_t)DD];
__device__ __half g_fh [NT*(size_t)FF];
__device__ __half g_whi[WTOT];
__device__ __half g_wlo[WTOT];

// ---------------------------------------------------------------------------
// PTX helpers
// ---------------------------------------------------------------------------
__device__ __forceinline__ uint32_t smem_u32(const void* p) {
    uint32_t a;
    asm("{ .reg .u64 t; cvta.to.shared.u64 t, %1; cvt.u32.u64 %0, t; }" : "=r"(a) : "l"(p));
    return a;
}
__device__ __forceinline__ void cp_async16(uint32_t dst, const void* src) {
    asm volatile("cp.async.cg.shared.global [%0], [%1], 16;" :: "r"(dst), "l"(src));
}
__device__ __forceinline__ void cp_commit() {
    asm volatile("cp.async.commit_group;");
}
__device__ __forceinline__ void cp_wait1() {
    asm volatile("cp.async.wait_group 1;");
}
__device__ __forceinline__ void cp_wait0() {
    asm volatile("cp.async.wait_group 0;");
}
__device__ __forceinline__ void ldmx4(uint32_t addr, uint32_t& r0, uint32_t& r1,
                                      uint32_t& r2, uint32_t& r3) {
    asm volatile("ldmatrix.sync.aligned.m8n8.x4.shared.b16 {%0,%1,%2,%3}, [%4];"
                 : "=r"(r0), "=r"(r1), "=r"(r2), "=r"(r3) : "r"(addr));
}
__device__ __forceinline__ void ldmx4t(uint32_t addr, uint32_t& r0, uint32_t& r1,
                                       uint32_t& r2, uint32_t& r3) {
    asm volatile("ldmatrix.sync.aligned.m8n8.x4.trans.shared.b16 {%0,%1,%2,%3}, [%4];"
                 : "=r"(r0), "=r"(r1), "=r"(r2), "=r"(r3) : "r"(addr));
}
__device__ __forceinline__ void mma_f16(float* c, const uint32_t* a, const uint32_t* b) {
    asm volatile("mma.sync.aligned.m16n8k16.row.col.f32.f16.f16.f32 "
                 "{%0,%1,%2,%3}, {%4,%5,%6,%7}, {%8,%9}, {%0,%1,%2,%3};"
                 : "+f"(c[0]), "+f"(c[1]), "+f"(c[2]), "+f"(c[3])
                 : "r"(a[0]), "r"(a[1]), "r"(a[2]), "r"(a[3]), "r"(b[0]), "r"(b[1]));
}
__device__ __forceinline__ uint32_t h2_bits(__half2 v) {
    return *reinterpret_cast<uint32_t*>(&v);
}
// split a float pair into fp16 hi/lo words (hi + lo ~= x to ~2^-22)
__device__ __forceinline__ void split2h(float a, float b, uint32_t& hw, uint32_t& lw) {
    __half2 h = __floats2half2_rn(a, b);
    float la = a - __low2float(h);
    float lb = b - __high2float(h);
    __half2 l = __floats2half2_rn(la, lb);
    hw = h2_bits(h);
    lw = h2_bits(l);
}
__device__ __forceinline__ uint32_t pack_h2(float a, float b) {
    return h2_bits(__floats2half2_rn(a, b));
}
// packed fp32x2 ops (PTX-only FFMA2 path)
#define FMA2(acc, a, b) \
    asm("fma.rn.f32x2 %0, %1, %2, %0;" : "+l"(acc) : "l"(a), "l"(b))
#define MUL2(out, a, b) \
    asm("mul.rn.f32x2 %0, %1, %2;" : "=l"(out) : "l"(a), "l"(b))
__device__ __forceinline__ unsigned long long dup2(float v) {
    unsigned long long r;
    asm("mov.b64 %0, {%1, %1};" : "=l"(r) : "f"(v));
    return r;
}
__device__ __forceinline__ void unpack2(unsigned long long v, float& lo, float& hi) {
    asm("mov.b64 {%0, %1}, %2;" : "=f"(lo), "=f"(hi) : "l"(v));
}

// ---------------------------------------------------------------------------
// Weight split: W fp32 -> hi/lo fp16 planes, 8 elems/iter (uint4 stores)
// ---------------------------------------------------------------------------
__global__ __launch_bounds__(256) void wsplit_kernel(const float* __restrict__ W,
                                                     __half* __restrict__ hi,
                                                     __half* __restrict__ lo,
                                                     int n8)   // n/8
{
    const float4* W4 = reinterpret_cast<const float4*>(W);
    uint4* H4 = reinterpret_cast<uint4*>(hi);
    uint4* L4 = reinterpret_cast<uint4*>(lo);
    for (int i = blockIdx.x * blockDim.x + threadIdx.x; i < n8; i += gridDim.x * blockDim.x) {
        float4 f0 = W4[2 * i];
        float4 f1 = W4[2 * i + 1];
        uint4 h, l;
        split2h(f0.x, f0.y, h.x, l.x);
        split2h(f0.z, f0.w, h.y, l.y);
        split2h(f1.x, f1.y, h.z, l.z);
        split2h(f1.z, f1.w, h.w, l.w);
        H4[i] = h;
        L4[i] = l;
    }
}

// ---------------------------------------------------------------------------
// Embedding + positional encoding; writes fp32 h AND fp16 activation plane
// ---------------------------------------------------------------------------
__global__ __launch_bounds__(256) void embed_kernel(const int* __restrict__ x,
                                                    const float* __restrict__ emb,
                                                    float* __restrict__ h,
                                                    __half* __restrict__ ah)
{
    int t = blockIdx.x;
    int s = t & (SS - 1);
    int tok = x[t];
    const float* e = emb + (size_t)tok * DD;
    const float negln = -9.210340371976184f;
    size_t base = (size_t)t * DD;
    for (int d0 = threadIdx.x * 2; d0 < DD; d0 += blockDim.x * 2) {
        float v[2];
        #pragma unroll
        for (int j = 0; j < 2; j++) {
            int d = d0 + j;
            int i2 = (d >> 1) * 2;
            float div = expf((float)i2 * (negln / (float)DD));
            float ang = (float)s * div;
            float pe = (d & 1) ? cosf(ang) : sinf(ang);
            v[j] = e[d] * 32.0f + pe;
        }
        h[base + d0] = v[0];
        h[base + d0 + 1] = v[1];
        *reinterpret_cast<uint32_t*>(ah + base + d0) = pack_h2(v[0], v[1]);
    }
}

// ---------------------------------------------------------------------------
// fp16x2 GEMM via mma.sync (unchanged R10 config: 128x128, 2 CTAs/SM)
// ---------------------------------------------------------------------------
__device__ __forceinline__ void stage_loadA(uint32_t sdst, const __half* A,
                                            int rowBase, int K, int k0, int tid)
{
    #pragma unroll
    for (int i = 0; i < 4; i++) {
        int idx = tid + i * 256;
        int r  = idx >> 3;
        int ch = idx & 7;
        uint32_t so = (uint32_t)r * AROWB + (uint32_t)ch * 16;
        cp_async16(sdst + so, A + (size_t)(rowBase + r) * K + k0 + ch * 8);
    }
}

__device__ __forceinline__ void stage_loadB(uint32_t sdst, const __half* Bhi,
                                            const __half* Blo, int Nw, int colW,
                                            int k0, int tid)
{
    #pragma unroll
    for (int i = 0; i < 4; i++) {
        int idx = tid + i * 256;
        int r  = idx >> 4;
        int ch = idx & 15;
        uint32_t so = (uint32_t)r * BROWB + (uint32_t)ch * 16;
        size_t g = (size_t)(k0 + r) * Nw + colW + ch * 8;
        cp_async16(sdst + so,         Bhi + g);
        cp_async16(sdst + BHALF + so, Blo + g);
    }
}

template<int ACT, int OUTH>
__global__ __launch_bounds__(256, 2) void gemm_mma(const __half* __restrict__ A,
                                                   const __half* __restrict__ Whi,
                                                   const __half* __restrict__ Wlo,
                                                   const __half* __restrict__ Whib,
                                                   const __half* __restrict__ Wlob,
                                                   const __half* __restrict__ Whic,
                                                   const __half* __restrict__ Wloc,
                                                   const float* __restrict__ bias,
                                                   float* __restrict__ C,
                                                   __half* __restrict__ Ch,
                                                   int M, int Nw, int K, int ldC)
{
    extern __shared__ char smem[];
    const uint32_t sb = smem_u32(smem);
    const int tid  = threadIdx.x;
    const int wid  = tid >> 5;
    const int lane = tid & 31;
    const int rowBase = blockIdx.x * BM;

    const __half* Bhi = Whi;
    const __half* Blo = Wlo;
    int colW;
    if (Whib) {
        int wsel = blockIdx.y >> 3;
        if (wsel == 1)      { Bhi = Whib; Blo = Wlob; }
        else if (wsel == 2) { Bhi = Whic; Blo = Wloc; }
        colW = (blockIdx.y & 7) * BN;
    } else {
        colW = blockIdx.y * BN;
    }
    const int colC = blockIdx.y * BN;

    const int m0 = (wid >> 2) * 64;
    const int n0 = (wid & 3) * 32;
    const int g  = lane >> 3;
    const int lr = lane & 7;

    float acc[4][4][4];
    #pragma unroll
    for (int mt = 0; mt < 4; mt++)
        #pragma unroll
        for (int nt = 0; nt < 4; nt++)
            #pragma unroll
            for (int e = 0; e < 4; e++) acc[mt][nt][e] = 0.0f;

    const int KT = K / BK;

    stage_loadA(sb, A, rowBase, K, 0, tid);
    stage_loadB(sb + BBASE, Bhi, Blo, Nw, colW, 0, tid);
    cp_commit();

    for (int it = 0; it < KT; it++) {
        const int buf = it & 1;
        if (it + 1 < KT) {
            stage_loadA(sb + (buf ^ 1) * ASTG, A, rowBase, K, (it + 1) * BK, tid);
            stage_loadB(sb + BBASE + (buf ^ 1) * BSTG, Bhi, Blo, Nw, colW, (it + 1) * BK, tid);
            cp_commit();
            cp_wait1();
        } else {
            cp_wait0();
        }
        __syncthreads();

        const uint32_t aB = sb + buf * ASTG;
        const uint32_t bB = sb + BBASE + buf * BSTG;
        #pragma unroll
        for (int ks = 0; ks < 4; ks++) {
            uint32_t Af[4][4];
            #pragma unroll
            for (int mt = 0; mt < 4; mt++) {
                int r  = m0 + mt * 16 + (g & 1) * 8 + lr;
                int ch = ks * 2 + (g >> 1);
                uint32_t ad = aB + (uint32_t)r * AROWB + (uint32_t)ch * 16;
                ldmx4(ad, Af[mt][0], Af[mt][1], Af[mt][2], Af[mt][3]);
            }
            uint32_t Bh[4][2], Bl[4][2];
            #pragma unroll
            for (int p = 0; p < 2; p++) {
                int kr = ks * 16 + (lane & 15);
                int nc = n0 + p * 16 + (lane >> 4) * 8;
                uint32_t bd = bB + (uint32_t)kr * BROWB + (uint32_t)nc * 2;
                ldmx4t(bd,         Bh[2*p][0], Bh[2*p][1], Bh[2*p+1][0], Bh[2*p+1][1]);
                ldmx4t(bd + BHALF, Bl[2*p][0], Bl[2*p][1], Bl[2*p+1][0], Bl[2*p+1][1]);
            }
            #pragma unroll
            for (int mt = 0; mt < 4; mt++)
                #pragma unroll
                for (int nt = 0; nt < 4; nt++) {
                    mma_f16(acc[mt][nt], Af[mt], Bh[nt]);
                    mma_f16(acc[mt][nt], Af[mt], Bl[nt]);
                }
        }
        __syncthreads();
    }

    // Epilogue
    const int crow = lane >> 2;
    const int ccol = (lane & 3) * 2;
    #pragma unroll
    for (int mt = 0; mt < 4; mt++) {
        #pragma unroll
        for (int nt = 0; nt < 4; nt++) {
            int col = colC + n0 + nt * 8 + ccol;
            float b0 = 0.0f, b1 = 0.0f;
            if (bias) { b0 = __ldg(bias + col); b1 = __ldg(bias + col + 1); }
            #pragma unroll
            for (int half = 0; half < 2; half++) {
                int row = rowBase + m0 + mt * 16 + crow + half * 8;
                float v0 = acc[mt][nt][half * 2 + 0] + b0;
                float v1 = acc[mt][nt][half * 2 + 1] + b1;
                if (ACT == 1) {
                    v0 = 0.5f * v0 * (1.0f + erff(v0 * 0.7071067811865476f));
                    v1 = 0.5f * v1 * (1.0f + erff(v1 * 0.7071067811865476f));
                }
                if (OUTH) {
                    *reinterpret_cast<uint32_t*>(Ch + (size_t)row * ldC + col) = pack_h2(v0, v1);
                } else {
                    *reinterpret_cast<float2*>(&C[(size_t)row * ldC + col]) = make_float2(v0, v1);
                }
            }
        }
    }
}

// ---------------------------------------------------------------------------
// Flash attention (fp32, packed f32x2 FMA) on packed qkv [NT, 3072].
// 128 threads per block: one q row per thread. Emits fp16 ctx plane.
// ---------------------------------------------------------------------------
__global__ __launch_bounds__(128) void attn_kernel(const float* __restrict__ QKV,
                                                   const int* __restrict__ x,
                                                   __half* __restrict__ Oh)
{
    __shared__ float Ks[32][64];
    __shared__ float Vs[32][64];
    __shared__ int   validS[32];

    const int bh = blockIdx.x;
    const int b  = bh >> 4;
    const int h  = bh & 15;
    const int qt = blockIdx.y;
    const int tid = threadIdx.x;       // 0..127
    const int qrow = qt * 128 + tid;
    const int tQ = b * SS + qrow;

    // Q and accumulators as packed fp32x2 pairs
    const unsigned long long* qp2 =
        reinterpret_cast<const unsigned long long*>(QKV + (size_t)tQ * QKVW + h * DKH);
    unsigned long long q2[32], acc2[32];
    #pragma unroll
    for (int i = 0; i < 32; i++) { q2[i] = qp2[i]; acc2[i] = 0ull; }

    float mrun = -1e30f, lsum = 0.0f;
    const int ntiles = 4 * qt + 4;

    const int lrow = tid >> 2;
    const int lcol = (tid & 3) * 16;

    for (int kt = 0; kt < ntiles; kt++) {
        const int kbase = kt * 32;
        {
            size_t off = (size_t)(b * SS + kbase + lrow) * QKVW + h * DKH + lcol;
            #pragma unroll
            for (int q = 0; q < 4; q++) {
                *reinterpret_cast<float4*>(&Ks[lrow][lcol + q * 4]) =
                    *reinterpret_cast<const float4*>(QKV + off + 1024 + q * 4);
                *reinterpret_cast<float4*>(&Vs[lrow][lcol + q * 4]) =
                    *reinterpret_cast<const float4*>(QKV + off + 2048 + q * 4);
            }
        }
        if (tid < 32) validS[tid] = (x[b * SS + kbase + tid] != 0);
        __syncthreads();

        int jmax = qrow - kbase + 1;
        if (jmax > 32) jmax = 32;
        if (jmax > 0) {
            float s[32];
            float tmax = -1e30f;
            #pragma unroll
            for (int j = 0; j < 32; j++) {
                if (j < jmax) {
                    const ulonglong2* kr = reinterpret_cast<const ulonglong2*>(Ks[j]);
                    unsigned long long sa = 0ull, sb2 = 0ull;
                    #pragma unroll
                    for (int dq = 0; dq < 16; dq++) {
                        ulonglong2 k2 = kr[dq];
                        FMA2(sa,  q2[2*dq],     k2.x);
                        FMA2(sb2, q2[2*dq + 1], k2.y);
                    }
                    float a0, a1, b0, b1;
                    unpack2(sa, a0, a1);
                    unpack2(sb2, b0, b1);
                    float sum = (a0 + a1) + (b0 + b1);
                    sum *= 0.125f;                       // 1/sqrt(64)
                    if (!validS[j]) sum = -1e30f;
                    s[j] = sum;
                    tmax = fmaxf(tmax, sum);
                } else {
                    s[j] = -1e30f;
                }
            }
            float mnew = fmaxf(mrun, tmax);
            float corr = __expf(mrun - mnew);
            lsum *= corr;
            unsigned long long cd = dup2(corr);
            #pragma unroll
            for (int i = 0; i < 32; i++) MUL2(acc2[i], acc2[i], cd);
            mrun = mnew;
            #pragma unroll
            for (int j = 0; j < 32; j++) {
                float pj = __expf(s[j] - mrun);          // 0 for masked lanes
                lsum += pj;
                unsigned long long pd = dup2(pj);
                const ulonglong2* vr = reinterpret_cast<const ulonglong2*>(Vs[j]);
                #pragma unroll
                for (int dq = 0; dq < 16; dq++) {
                    ulonglong2 v2 = vr[dq];
                    FMA2(acc2[2*dq],     pd, v2.x);
                    FMA2(acc2[2*dq + 1], pd, v2.y);
                }
            }
        }
        __syncthreads();
    }

    float inv = 1.0f / lsum;
    size_t ob = (size_t)tQ * DD + h * DKH;
    #pragma unroll
    for (int i = 0; i < 32; i++) {
        float lo, hi;
        unpack2(acc2[i], lo, hi);
        *reinterpret_cast<uint32_t*>(Oh + ob + i * 2) = pack_h2(lo * inv, hi * inv);
    }
}

// ---------------------------------------------------------------------------
// Residual add + LayerNorm (in place on h); also emits fp16 activation plane
// ---------------------------------------------------------------------------
__device__ __forceinline__ float block_sum(float v, float* red)
{
    #pragma unroll
    for (int o = 16; o > 0; o >>= 1) v += __shfl_xor_sync(0xffffffffu, v, o);
    int w = threadIdx.x >> 5;
    if ((threadIdx.x & 31) == 0) red[w] = v;
    __syncthreads();
    if (threadIdx.x < 32) {
        float t = (threadIdx.x < 8) ? red[threadIdx.x] : 0.0f;
        #pragma unroll
        for (int o = 4; o > 0; o >>= 1) t += __shfl_xor_sync(0xffffffffu, t, o);
        if (threadIdx.x == 0) red[0] = t;
    }
    __syncthreads();
    float r = red[0];
    __syncthreads();
    return r;
}

__global__ __launch_bounds__(256) void add_ln_kernel(float* __restrict__ h,
                                                     const float* __restrict__ r,
                                                     const float* __restrict__ g,
                                                     const float* __restrict__ bta,
                                                     __half* __restrict__ ah)
{
    __shared__ float red[32];
    const int t = blockIdx.x;
    const int tid = threadIdx.x;
    size_t base = (size_t)t * DD;
    float v[4];
    float sum = 0.0f;
    #pragma unroll
    for (int i = 0; i < 4; i++) {
        int d = tid * 2 + (i & 1) + (i >> 1) * 512;
        float val = h[base + d] + r[base + d];
        v[i] = val;
        sum += val;
    }
    float tot = block_sum(sum, red);
    float mu = tot * (1.0f / (float)DD);
    float sq = 0.0f;
    #pragma unroll
    for (int i = 0; i < 4; i++) { float dvi = v[i] - mu; sq += dvi * dvi; }
    float var = block_sum(sq, red) * (1.0f / (float)DD);
    float rs = rsqrtf(var + 1e-5f);
    #pragma unroll
    for (int p = 0; p < 2; p++) {
        int d = tid * 2 + p * 512;
        float o0 = (v[p*2]   - mu) * rs * g[d]     + bta[d];
        float o1 = (v[p*2+1] - mu) * rs * g[d + 1] + bta[d + 1];
        h[base + d]     = o0;
        h[base + d + 1] = o1;
        *reinterpret_cast<uint32_t*>(ah + base + d) = pack_h2(o0, o1);
    }
}

// ---------------------------------------------------------------------------
// Launch
// ---------------------------------------------------------------------------
extern "C" void kernel_launch(void* const* d_in, const int* in_sizes, int n_in,
                              void* d_out, int out_size)
{
    const int*   x    = (const int*)  d_in[0];
    const float* emb  = (const float*)d_in[1];
    const float* Wq   = (const float*)d_in[2];
    const float* Wk   = (const float*)d_in[3];
    const float* Wv   = (const float*)d_in[4];
    const float* Wo   = (const float*)d_in[5];
    const float* bo   = (const float*)d_in[6];
    const float* ln1g = (const float*)d_in[7];
    const float* ln1b = (const float*)d_in[8];
    const float* ln2g = (const float*)d_in[9];
    const float* ln2b = (const float*)d_in[10];
    const float* W1   = (const float*)d_in[11];
    const float* b1   = (const float*)d_in[12];
    const float* W2   = (const float*)d_in[13];
    const float* b2   = (const float*)d_in[14];
    const float* Wout = (const float*)d_in[15];
    const float* bout = (const float*)d_in[16];
    float* out = (float*)d_out;

    void* p;
    cudaGetSymbolAddress(&p, g_h);   float* h   = (float*)p;
    cudaGetSymbolAddress(&p, g_qkv); float* qkv = (float*)p;
    cudaGetSymbolAddress(&p, g_tmp); float* tmp = (float*)p;
    cudaGetSymbolAddress(&p, g_ah);  __half* ah = (__half*)p;
    cudaGetSymbolAddress(&p, g_fh);  __half* fh = (__half*)p;
    cudaGetSymbolAddress(&p, g_whi); __half* whi = (__half*)p;
    cudaGetSymbolAddress(&p, g_wlo); __half* wlo = (__half*)p;

    cudaFuncSetAttribute(gemm_mma<0,0>, cudaFuncAttributeMaxDynamicSharedMemorySize, GEMM_SMEM);
    cudaFuncSetAttribute(gemm_mma<1,1>, cudaFuncAttributeMaxDynamicSharedMemorySize, GEMM_SMEM);

    // Pre-split all weights to fp16 hi/lo planes (streaming, once per launch)
    wsplit_kernel<<<2048, 256>>>(Wq,   whi + OFF_WQ,   wlo + OFF_WQ,   LL*DD*DD/8);
    wsplit_kernel<<<2048, 256>>>(Wk,   whi + OFF_WK,   wlo + OFF_WK,   LL*DD*DD/8);
    wsplit_kernel<<<2048, 256>>>(Wv,   whi + OFF_WV,   wlo + OFF_WV,   LL*DD*DD/8);
    wsplit_kernel<<<2048, 256>>>(Wo,   whi + OFF_WO,   wlo + OFF_WO,   LL*DD*DD/8);
    wsplit_kernel<<<4096, 256>>>(W1,   whi + OFF_W1,   wlo + OFF_W1,   LL*DD*FF/8);
    wsplit_kernel<<<4096, 256>>>(W2,   whi + OFF_W2,   wlo + OFF_W2,   LL*DD*FF/8);
    wsplit_kernel<<<4096, 256>>>(Wout, whi + OFF_WOUT, wlo + OFF_WOUT, DD*VV/8);

    embed_kernel<<<NT, 256>>>(x, emb, h, ah);

    const dim3 gQKV(NT/BM, QKVW/BN);  // 32 x 24 (fused q|k|v)
    const dim3 gD(NT/BM, DD/BN);      // 32 x 8
    const dim3 gF(NT/BM, FF/BN);      // 32 x 32
    const dim3 gV(NT/BM, VV/BN);      // 32 x 250

    for (int l = 0; l < LL; l++) {
        const size_t oD = (size_t)l * DD * DD;
        const size_t oF = (size_t)l * DD * FF;

        // Fused QKV projection (one launch, W planes selected per block)
        gemm_mma<0,0><<<gQKV, 256, GEMM_SMEM>>>(ah,
            whi + OFF_WQ + oD, wlo + OFF_WQ + oD,
            whi + OFF_WK + oD, wlo + OFF_WK + oD,
            whi + OFF_WV + oD, wlo + OFF_WV + oD,
            nullptr, qkv, nullptr, NT, DD, DD, QKVW);

        attn_kernel<<<dim3(BB * HH, SS / 128), 128>>>(qkv, x, ah);   // ctx -> fp16 plane

        gemm_mma<0,0><<<gD, 256, GEMM_SMEM>>>(ah,
            whi + OFF_WO + oD, wlo + OFF_WO + oD,
            nullptr, nullptr, nullptr, nullptr,
            bo + l * DD, tmp, nullptr, NT, DD, DD, DD);
        add_ln_kernel<<<NT, 256>>>(h, tmp, ln1g + l * DD, ln1b + l * DD, ah);

        gemm_mma<1,1><<<gF, 256, GEMM_SMEM>>>(ah,
            whi + OFF_W1 + oF, wlo + OFF_W1 + oF,
            nullptr, nullptr, nullptr, nullptr,
            b1 + l * FF, nullptr, fh, NT, FF, DD, FF);
        gemm_mma<0,0><<<gD, 256, GEMM_SMEM>>>(fh,
            whi + OFF_W2 + oF, wlo + OFF_W2 + oF,
            nullptr, nullptr, nullptr, nullptr,
            b2 + l * DD, tmp, nullptr, NT, DD, FF, DD);
        add_ln_kernel<<<NT, 256>>>(h, tmp, ln2g + l * DD, ln2b + l * DD, ah);
    }

    gemm_mma<0,0><<<gV, 256, GEMM_SMEM>>>(ah,
        whi + OFF_WOUT, wlo + OFF_WOUT,
        nullptr, nullptr, nullptr, nullptr,
        bout, out, nullptr, NT, VV, DD, VV);
}

// round 12
// speedup vs baseline: 2.1919x; 1.3641x over previous
#include <cuda_runtime.h>
#include <cuda_fp16.h>
#include <cstdint>
#include <cmath>

// Problem constants
#define BB   4
#define SS   1024
#define DD   1024
#define HH   16
#define DKH  64
#define LL   4
#define FF   4096
#define VV   32000
#define NT   (BB*SS)   // 4096 tokens
#define QKVW 3072      // packed q|k|v width

// GEMM tile config: CTA 128x128, warp 64x32 (2x4 warps), BK=64, 2 CTAs/SM
#define BM 128
#define BN 128
#define BK 64
#define AROWB 144                  // A smem row: 128B data + 16B pad
#define ASTG (BM*AROWB)            // one 128xBK fp16 matrix: 18432 B
#define BROWB 272                  // B smem row: 256B data + 16B pad
#define BSTG (64*BROWB)            // one 64x128 fp16 plane per stage: 17408 B
#define BBASE (2*ASTG)             // 36864 (A double-buffered)
#define GEMM_SMEM (BBASE + 2*BSTG) // 71680 B  (2 CTAs/SM: 143360 <= 227KB)

// fp16 weight plane offsets (elements)
#define OFF_WQ   0
#define OFF_WK   (4*DD*DD)
#define OFF_WV   (8*DD*DD)
#define OFF_WO   (12*DD*DD)
#define OFF_W1   (16*DD*DD)
#define OFF_W2   (OFF_W1 + LL*DD*FF)
#define OFF_WOUT (OFF_W2 + LL*DD*FF)
#define WTOT     (OFF_WOUT + (size_t)DD*VV)   // 83,099,648 elems

// ---------------------------------------------------------------------------
// Scratch (device globals — no runtime allocation allowed)
// ---------------------------------------------------------------------------
__device__ float g_h  [NT*(size_t)DD];
__device__ float g_qkv[NT*(size_t)QKVW];
__device__ float g_tmp[NT*(size_t)DD];
__device__ __half g_ah [NT*(size_t)DD];
__device__ __half g_fh [NT*(size_t)FF];
__device__ __half g_wh [WTOT];

// ---------------------------------------------------------------------------
// PTX helpers
// ---------------------------------------------------------------------------
__device__ __forceinline__ uint32_t smem_u32(const void* p) {
    uint32_t a;
    asm("{ .reg .u64 t; cvta.to.shared.u64 t, %1; cvt.u32.u64 %0, t; }" : "=r"(a) : "l"(p));
    return a;
}
__device__ __forceinline__ void cp_async16(uint32_t dst, const void* src) {
    asm volatile("cp.async.cg.shared.global [%0], [%1], 16;" :: "r"(dst), "l"(src));
}
__device__ __forceinline__ void cp_commit() {
    asm volatile("cp.async.commit_group;");
}
__device__ __forceinline__ void cp_wait1() {
    asm volatile("cp.async.wait_group 1;");
}
__device__ __forceinline__ void cp_wait0() {
    asm volatile("cp.async.wait_group 0;");
}
__device__ __forceinline__ void ldmx4(uint32_t addr, uint32_t& r0, uint32_t& r1,
                                      uint32_t& r2, uint32_t& r3) {
    asm volatile("ldmatrix.sync.aligned.m8n8.x4.shared.b16 {%0,%1,%2,%3}, [%4];"
                 : "=r"(r0), "=r"(r1), "=r"(r2), "=r"(r3) : "r"(addr));
}
__device__ __forceinline__ void ldmx4t(uint32_t addr, uint32_t& r0, uint32_t& r1,
                                       uint32_t& r2, uint32_t& r3) {
    asm volatile("ldmatrix.sync.aligned.m8n8.x4.trans.shared.b16 {%0,%1,%2,%3}, [%4];"
                 : "=r"(r0), "=r"(r1), "=r"(r2), "=r"(r3) : "r"(addr));
}
__device__ __forceinline__ void mma_f16(float* c, const uint32_t* a, const uint32_t* b) {
    asm volatile("mma.sync.aligned.m16n8k16.row.col.f32.f16.f16.f32 "
                 "{%0,%1,%2,%3}, {%4,%5,%6,%7}, {%8,%9}, {%0,%1,%2,%3};"
                 : "+f"(c[0]), "+f"(c[1]), "+f"(c[2]), "+f"(c[3])
                 : "r"(a[0]), "r"(a[1]), "r"(a[2]), "r"(a[3]), "r"(b[0]), "r"(b[1]));
}
__device__ __forceinline__ uint32_t h2_bits(__half2 v) {
    return *reinterpret_cast<uint32_t*>(&v);
}
__device__ __forceinline__ uint32_t pack_h2(float a, float b) {
    return h2_bits(__floats2half2_rn(a, b));
}
// packed fp32x2 ops (PTX-only FFMA2 path)
#define FMA2(acc, a, b) \
    asm("fma.rn.f32x2 %0, %1, %2, %0;" : "+l"(acc) : "l"(a), "l"(b))
#define MUL2(out, a, b) \
    asm("mul.rn.f32x2 %0, %1, %2;" : "=l"(out) : "l"(a), "l"(b))
__device__ __forceinline__ unsigned long long dup2(float v) {
    unsigned long long r;
    asm("mov.b64 %0, {%1, %1};" : "=l"(r) : "f"(v));
    return r;
}
__device__ __forceinline__ void unpack2(unsigned long long v, float& lo, float& hi) {
    asm("mov.b64 {%0, %1}, %2;" : "=f"(lo), "=f"(hi) : "l"(v));
}

// ---------------------------------------------------------------------------
// Weight convert: W fp32 -> fp16 plane, 8 elems/iter
// ---------------------------------------------------------------------------
__global__ __launch_bounds__(256) void wconv_kernel(const float* __restrict__ W,
                                                    __half* __restrict__ out,
                                                    int n8)   // n/8
{
    const float4* W4 = reinterpret_cast<const float4*>(W);
    uint4* O4 = reinterpret_cast<uint4*>(out);
    for (int i = blockIdx.x * blockDim.x + threadIdx.x; i < n8; i += gridDim.x * blockDim.x) {
        float4 f0 = W4[2 * i];
        float4 f1 = W4[2 * i + 1];
        uint4 o;
        o.x = pack_h2(f0.x, f0.y);
        o.y = pack_h2(f0.z, f0.w);
        o.z = pack_h2(f1.x, f1.y);
        o.w = pack_h2(f1.z, f1.w);
        O4[i] = o;
    }
}

// ---------------------------------------------------------------------------
// Embedding + positional encoding; writes fp32 h AND fp16 activation plane
// ---------------------------------------------------------------------------
__global__ __launch_bounds__(256) void embed_kernel(const int* __restrict__ x,
                                                    const float* __restrict__ emb,
                                                    float* __restrict__ h,
                                                    __half* __restrict__ ah)
{
    int t = blockIdx.x;
    int s = t & (SS - 1);
    int tok = x[t];
    const float* e = emb + (size_t)tok * DD;
    const float negln = -9.210340371976184f;
    size_t base = (size_t)t * DD;
    for (int d0 = threadIdx.x * 2; d0 < DD; d0 += blockDim.x * 2) {
        float v[2];
        #pragma unroll
        for (int j = 0; j < 2; j++) {
            int d = d0 + j;
            int i2 = (d >> 1) * 2;
            float div = expf((float)i2 * (negln / (float)DD));
            float ang = (float)s * div;
            float pe = (d & 1) ? cosf(ang) : sinf(ang);
            v[j] = e[d] * 32.0f + pe;
        }
        h[base + d0] = v[0];
        h[base + d0 + 1] = v[1];
        *reinterpret_cast<uint32_t*>(ah + base + d0) = pack_h2(v[0], v[1]);
    }
}

// ---------------------------------------------------------------------------
// fp16 GEMM via mma.sync: C[M,N] = A[M,K] @ W[K,N] (+bias)(+GELU)
// A: fp16 [M,K]. W: fp16 [K,N] plane, both via cp.async.
// CTA 128x128, 8 warps of 64x32 (2x4), BK=64, double-buffered, 2 CTAs/SM.
// ---------------------------------------------------------------------------
__device__ __forceinline__ void stage_loadA(uint32_t sdst, const __half* A,
                                            int rowBase, int K, int k0, int tid)
{
    #pragma unroll
    for (int i = 0; i < 4; i++) {
        int idx = tid + i * 256;
        int r  = idx >> 3;
        int ch = idx & 7;
        uint32_t so = (uint32_t)r * AROWB + (uint32_t)ch * 16;
        cp_async16(sdst + so, A + (size_t)(rowBase + r) * K + k0 + ch * 8);
    }
}

__device__ __forceinline__ void stage_loadB(uint32_t sdst, const __half* Bw,
                                            int Nw, int colW, int k0, int tid)
{
    #pragma unroll
    for (int i = 0; i < 4; i++) {
        int idx = tid + i * 256;
        int r  = idx >> 4;                 // row 0..63
        int ch = idx & 15;                 // 16B chunk 0..15
        uint32_t so = (uint32_t)r * BROWB + (uint32_t)ch * 16;
        cp_async16(sdst + so, Bw + (size_t)(k0 + r) * Nw + colW + ch * 8);
    }
}

template<int ACT, int OUTH>
__global__ __launch_bounds__(256, 2) void gemm_mma(const __half* __restrict__ A,
                                                   const __half* __restrict__ W0,
                                                   const __half* __restrict__ W1p,
                                                   const __half* __restrict__ W2p,
                                                   const float* __restrict__ bias,
                                                   float* __restrict__ C,
                                                   __half* __restrict__ Ch,
                                                   int M, int Nw, int K, int ldC)
{
    extern __shared__ char smem[];
    const uint32_t sb = smem_u32(smem);
    const int tid  = threadIdx.x;
    const int wid  = tid >> 5;
    const int lane = tid & 31;
    const int rowBase = blockIdx.x * BM;

    const __half* Bw = W0;
    int colW;
    if (W1p) {
        int wsel = blockIdx.y >> 3;
        if (wsel == 1)      Bw = W1p;
        else if (wsel == 2) Bw = W2p;
        colW = (blockIdx.y & 7) * BN;
    } else {
        colW = blockIdx.y * BN;
    }
    const int colC = blockIdx.y * BN;

    const int m0 = (wid >> 2) * 64;
    const int n0 = (wid & 3) * 32;
    const int g  = lane >> 3;
    const int lr = lane & 7;

    float acc[4][4][4];
    #pragma unroll
    for (int mt = 0; mt < 4; mt++)
        #pragma unroll
        for (int nt = 0; nt < 4; nt++)
            #pragma unroll
            for (int e = 0; e < 4; e++) acc[mt][nt][e] = 0.0f;

    const int KT = K / BK;

    stage_loadA(sb, A, rowBase, K, 0, tid);
    stage_loadB(sb + BBASE, Bw, Nw, colW, 0, tid);
    cp_commit();

    for (int it = 0; it < KT; it++) {
        const int buf = it & 1;
        if (it + 1 < KT) {
            stage_loadA(sb + (buf ^ 1) * ASTG, A, rowBase, K, (it + 1) * BK, tid);
            stage_loadB(sb + BBASE + (buf ^ 1) * BSTG, Bw, Nw, colW, (it + 1) * BK, tid);
            cp_commit();
            cp_wait1();
        } else {
            cp_wait0();
        }
        __syncthreads();

        const uint32_t aB = sb + buf * ASTG;
        const uint32_t bB = sb + BBASE + buf * BSTG;
        #pragma unroll
        for (int ks = 0; ks < 4; ks++) {
            uint32_t Af[4][4];
            #pragma unroll
            for (int mt = 0; mt < 4; mt++) {
                int r  = m0 + mt * 16 + (g & 1) * 8 + lr;
                int ch = ks * 2 + (g >> 1);
                uint32_t ad = aB + (uint32_t)r * AROWB + (uint32_t)ch * 16;
                ldmx4(ad, Af[mt][0], Af[mt][1], Af[mt][2], Af[mt][3]);
            }
            uint32_t Bf[4][2];
            #pragma unroll
            for (int p = 0; p < 2; p++) {
                int kr = ks * 16 + (lane & 15);
                int nc = n0 + p * 16 + (lane >> 4) * 8;
                uint32_t bd = bB + (uint32_t)kr * BROWB + (uint32_t)nc * 2;
                ldmx4t(bd, Bf[2*p][0], Bf[2*p][1], Bf[2*p+1][0], Bf[2*p+1][1]);
            }
            #pragma unroll
            for (int mt = 0; mt < 4; mt++)
                #pragma unroll
                for (int nt = 0; nt < 4; nt++)
                    mma_f16(acc[mt][nt], Af[mt], Bf[nt]);
        }
        __syncthreads();
    }

    // Epilogue
    const int crow = lane >> 2;
    const int ccol = (lane & 3) * 2;
    #pragma unroll
    for (int mt = 0; mt < 4; mt++) {
        #pragma unroll
        for (int nt = 0; nt < 4; nt++) {
            int col = colC + n0 + nt * 8 + ccol;
            float b0 = 0.0f, b1 = 0.0f;
            if (bias) { b0 = __ldg(bias + col); b1 = __ldg(bias + col + 1); }
            #pragma unroll
            for (int half = 0; half < 2; half++) {
                int row = rowBase + m0 + mt * 16 + crow + half * 8;
                float v0 = acc[mt][nt][half * 2 + 0] + b0;
                float v1 = acc[mt][nt][half * 2 + 1] + b1;
                if (ACT == 1) {
                    v0 = 0.5f * v0 * (1.0f + erff(v0 * 0.7071067811865476f));
                    v1 = 0.5f * v1 * (1.0f + erff(v1 * 0.7071067811865476f));
                }
                if (OUTH) {
                    *reinterpret_cast<uint32_t*>(Ch + (size_t)row * ldC + col) = pack_h2(v0, v1);
                } else {
                    *reinterpret_cast<float2*>(&C[(size_t)row * ldC + col]) = make_float2(v0, v1);
                }
            }
        }
    }
}

// ---------------------------------------------------------------------------
// Flash attention (fp32, packed f32x2 FMA) on packed qkv [NT, 3072].
// ---------------------------------------------------------------------------
__global__ __launch_bounds__(128) void attn_kernel(const float* __restrict__ QKV,
                                                   const int* __restrict__ x,
                                                   __half* __restrict__ Oh)
{
    __shared__ float Ks[32][64];
    __shared__ float Vs[32][64];
    __shared__ int   validS[32];

    const int bh = blockIdx.x;
    const int b  = bh >> 4;
    const int h  = bh & 15;
    const int qt = blockIdx.y;
    const int tid = threadIdx.x;       // 0..127
    const int qrow = qt * 128 + tid;
    const int tQ = b * SS + qrow;

    const unsigned long long* qp2 =
        reinterpret_cast<const unsigned long long*>(QKV + (size_t)tQ * QKVW + h * DKH);
    unsigned long long q2[32], acc2[32];
    #pragma unroll
    for (int i = 0; i < 32; i++) { q2[i] = qp2[i]; acc2[i] = 0ull; }

    float mrun = -1e30f, lsum = 0.0f;
    const int ntiles = 4 * qt + 4;

    const int lrow = tid >> 2;
    const int lcol = (tid & 3) * 16;

    for (int kt = 0; kt < ntiles; kt++) {
        const int kbase = kt * 32;
        {
            size_t off = (size_t)(b * SS + kbase + lrow) * QKVW + h * DKH + lcol;
            #pragma unroll
            for (int q = 0; q < 4; q++) {
                *reinterpret_cast<float4*>(&Ks[lrow][lcol + q * 4]) =
                    *reinterpret_cast<const float4*>(QKV + off + 1024 + q * 4);
                *reinterpret_cast<float4*>(&Vs[lrow][lcol + q * 4]) =
                    *reinterpret_cast<const float4*>(QKV + off + 2048 + q * 4);
            }
        }
        if (tid < 32) validS[tid] = (x[b * SS + kbase + tid] != 0);
        __syncthreads();

        int jmax = qrow - kbase + 1;
        if (jmax > 32) jmax = 32;
        if (jmax > 0) {
            float s[32];
            float tmax = -1e30f;
            #pragma unroll
            for (int j = 0; j < 32; j++) {
                if (j < jmax) {
                    const ulonglong2* kr = reinterpret_cast<const ulonglong2*>(Ks[j]);
                    unsigned long long sa = 0ull, sb2 = 0ull;
                    #pragma unroll
                    for (int dq = 0; dq < 16; dq++) {
                        ulonglong2 k2 = kr[dq];
                        FMA2(sa,  q2[2*dq],     k2.x);
                        FMA2(sb2, q2[2*dq + 1], k2.y);
                    }
                    float a0, a1, b0, b1;
                    unpack2(sa, a0, a1);
                    unpack2(sb2, b0, b1);
                    float sum = (a0 + a1) + (b0 + b1);
                    sum *= 0.125f;
                    if (!validS[j]) sum = -1e30f;
                    s[j] = sum;
                    tmax = fmaxf(tmax, sum);
                } else {
                    s[j] = -1e30f;
                }
            }
            float mnew = fmaxf(mrun, tmax);
            float corr = __expf(mrun - mnew);
            lsum *= corr;
            unsigned long long cd = dup2(corr);
            #pragma unroll
            for (int i = 0; i < 32; i++) MUL2(acc2[i], acc2[i], cd);
            mrun = mnew;
            #pragma unroll
            for (int j = 0; j < 32; j++) {
                float pj = __expf(s[j] - mrun);
                lsum += pj;
                unsigned long long pd = dup2(pj);
                const ulonglong2* vr = reinterpret_cast<const ulonglong2*>(Vs[j]);
                #pragma unroll
                for (int dq = 0; dq < 16; dq++) {
                    ulonglong2 v2 = vr[dq];
                    FMA2(acc2[2*dq],     pd, v2.x);
                    FMA2(acc2[2*dq + 1], pd, v2.y);
                }
            }
        }
        __syncthreads();
    }

    float inv = 1.0f / lsum;
    size_t ob = (size_t)tQ * DD + h * DKH;
    #pragma unroll
    for (int i = 0; i < 32; i++) {
        float lo, hi;
        unpack2(acc2[i], lo, hi);
        *reinterpret_cast<uint32_t*>(Oh + ob + i * 2) = pack_h2(lo * inv, hi * inv);
    }
}

// ---------------------------------------------------------------------------
// Residual add + LayerNorm (in place on h); also emits fp16 activation plane
// ---------------------------------------------------------------------------
__device__ __forceinline__ float block_sum(float v, float* red)
{
    #pragma unroll
    for (int o = 16; o > 0; o >>= 1) v += __shfl_xor_sync(0xffffffffu, v, o);
    int w = threadIdx.x >> 5;
    if ((threadIdx.x & 31) == 0) red[w] = v;
    __syncthreads();
    if (threadIdx.x < 32) {
        float t = (threadIdx.x < 8) ? red[threadIdx.x] : 0.0f;
        #pragma unroll
        for (int o = 4; o > 0; o >>= 1) t += __shfl_xor_sync(0xffffffffu, t, o);
        if (threadIdx.x == 0) red[0] = t;
    }
    __syncthreads();
    float r = red[0];
    __syncthreads();
    return r;
}

__global__ __launch_bounds__(256) void add_ln_kernel(float* __restrict__ h,
                                                     const float* __restrict__ r,
                                                     const float* __restrict__ g,
                                                     const float* __restrict__ bta,
                                                     __half* __restrict__ ah)
{
    __shared__ float red[32];
    const int t = blockIdx.x;
    const int tid = threadIdx.x;
    size_t base = (size_t)t * DD;
    float v[4];
    float sum = 0.0f;
    #pragma unroll
    for (int i = 0; i < 4; i++) {
        int d = tid * 2 + (i & 1) + (i >> 1) * 512;
        float val = h[base + d] + r[base + d];
        v[i] = val;
        sum += val;
    }
    float tot = block_sum(sum, red);
    float mu = tot * (1.0f / (float)DD);
    float sq = 0.0f;
    #pragma unroll
    for (int i = 0; i < 4; i++) { float dvi = v[i] - mu; sq += dvi * dvi; }
    float var = block_sum(sq, red) * (1.0f / (float)DD);
    float rs = rsqrtf(var + 1e-5f);
    #pragma unroll
    for (int p = 0; p < 2; p++) {
        int d = tid * 2 + p * 512;
        float o0 = (v[p*2]   - mu) * rs * g[d]     + bta[d];
        float o1 = (v[p*2+1] - mu) * rs * g[d + 1] + bta[d + 1];
        h[base + d]     = o0;
        h[base + d + 1] = o1;
        *reinterpret_cast<uint32_t*>(ah + base + d) = pack_h2(o0, o1);
    }
}

// ---------------------------------------------------------------------------
// Launch
// ---------------------------------------------------------------------------
extern "C" void kernel_launch(void* const* d_in, const int* in_sizes, int n_in,
                              void* d_out, int out_size)
{
    const int*   x    = (const int*)  d_in[0];
    const float* emb  = (const float*)d_in[1];
    const float* Wq   = (const float*)d_in[2];
    const float* Wk   = (const float*)d_in[3];
    const float* Wv   = (const float*)d_in[4];
    const float* Wo   = (const float*)d_in[5];
    const float* bo   = (const float*)d_in[6];
    const float* ln1g = (const float*)d_in[7];
    const float* ln1b = (const float*)d_in[8];
    const float* ln2g = (const float*)d_in[9];
    const float* ln2b = (const float*)d_in[10];
    const float* W1   = (const float*)d_in[11];
    const float* b1   = (const float*)d_in[12];
    const float* W2   = (const float*)d_in[13];
    const float* b2   = (const float*)d_in[14];
    const float* Wout = (const float*)d_in[15];
    const float* bout = (const float*)d_in[16];
    float* out = (float*)d_out;

    void* p;
    cudaGetSymbolAddress(&p, g_h);   float* h   = (float*)p;
    cudaGetSymbolAddress(&p, g_qkv); float* qkv = (float*)p;
    cudaGetSymbolAddress(&p, g_tmp); float* tmp = (float*)p;
    cudaGetSymbolAddress(&p, g_ah);  __half* ah = (__half*)p;
    cudaGetSymbolAddress(&p, g_fh);  __half* fh = (__half*)p;
    cudaGetSymbolAddress(&p, g_wh);  __half* wh = (__half*)p;

    cudaFuncSetAttribute(gemm_mma<0,0>, cudaFuncAttributeMaxDynamicSharedMemorySize, GEMM_SMEM);
    cudaFuncSetAttribute(gemm_mma<1,1>, cudaFuncAttributeMaxDynamicSharedMemorySize, GEMM_SMEM);

    // Convert all weights to fp16 planes (streaming, once per launch)
    wconv_kernel<<<2048, 256>>>(Wq,   wh + OFF_WQ,   LL*DD*DD/8);
    wconv_kernel<<<2048, 256>>>(Wk,   wh + OFF_WK,   LL*DD*DD/8);
    wconv_kernel<<<2048, 256>>>(Wv,   wh + OFF_WV,   LL*DD*DD/8);
    wconv_kernel<<<2048, 256>>>(Wo,   wh + OFF_WO,   LL*DD*DD/8);
    wconv_kernel<<<4096, 256>>>(W1,   wh + OFF_W1,   LL*DD*FF/8);
    wconv_kernel<<<4096, 256>>>(W2,   wh + OFF_W2,   LL*DD*FF/8);
    wconv_kernel<<<4096, 256>>>(Wout, wh + OFF_WOUT, DD*VV/8);

    embed_kernel<<<NT, 256>>>(x, emb, h, ah);

    const dim3 gQKV(NT/BM, QKVW/BN);  // 32 x 24 (fused q|k|v)
    const dim3 gD(NT/BM, DD/BN);      // 32 x 8
    const dim3 gF(NT/BM, FF/BN);      // 32 x 32
    const dim3 gV(NT/BM, VV/BN);      // 32 x 250

    for (int l = 0; l < LL; l++) {
        const size_t oD = (size_t)l * DD * DD;
        const size_t oF = (size_t)l * DD * FF;

        // Fused QKV projection (one launch, W plane selected per block)
        gemm_mma<0,0><<<gQKV, 256, GEMM_SMEM>>>(ah,
            wh + OFF_WQ + oD, wh + OFF_WK + oD, wh + OFF_WV + oD,
            nullptr, qkv, nullptr, NT, DD, DD, QKVW);

        attn_kernel<<<dim3(BB * HH, SS / 128), 128>>>(qkv, x, ah);   // ctx -> fp16 plane

        gemm_mma<0,0><<<gD, 256, GEMM_SMEM>>>(ah,
            wh + OFF_WO + oD, nullptr, nullptr,
            bo + l * DD, tmp, nullptr, NT, DD, DD, DD);
        add_ln_kernel<<<NT, 256>>>(h, tmp, ln1g + l * DD, ln1b + l * DD, ah);

        gemm_mma<1,1><<<gF, 256, GEMM_SMEM>>>(ah,
            wh + OFF_W1 + oF, nullptr, nullptr,
            b1 + l * FF, nullptr, fh, NT, FF, DD, FF);
        gemm_mma<0,0><<<gD, 256, GEMM_SMEM>>>(fh,
            wh + OFF_W2 + oF, nullptr, nullptr,
            b2 + l * DD, tmp, nullptr, NT, DD, FF, DD);
        add_ln_kernel<<<NT, 256>>>(h, tmp, ln2g + l * DD, ln2b + l * DD, ah);
    }

    gemm_mma<0,0><<<gV, 256, GEMM_SMEM>>>(ah,
        wh + OFF_WOUT, nullptr, nullptr,
        bout, out, nullptr, NT, VV, DD, VV);
}

// round 14
// speedup vs baseline: 2.2197x; 1.0127x over previous
#include <cuda_runtime.h>
#include <cuda_fp16.h>
#include <cstdint>
#include <cmath>

// Problem constants
#define BB   4
#define SS   1024
#define DD   1024
#define HH   16
#define DKH  64
#define LL   4
#define FF   4096
#define VV   32000
#define NT   (BB*SS)   // 4096 tokens
#define QKVW 3072      // packed q|k|v width

// GEMM tile config: CTA 128x128, warp 64x32 (2x4 warps), BK=64, 3-stage, 2 CTAs/SM
#define BM 128
#define BN 128
#define BK 64
#define AROWB 144                  // A smem row: 128B data + 16B pad
#define ASTG (BM*AROWB)            // one 128xBK fp16 matrix: 18432 B
#define BROWB 272                  // B smem row: 256B data + 16B pad
#define BSTG (64*BROWB)            // one 64x128 fp16 plane per stage: 17408 B
#define STG (ASTG + BSTG)          // 35840 B per stage
#define GEMM_SMEM (3*STG)          // 107520 B  (2 CTAs/SM: 215040 <= ~227KB)

// fp16 weight plane offsets (elements)
#define OFF_WQ   0
#define OFF_WK   (4*DD*DD)
#define OFF_WV   (8*DD*DD)
#define OFF_WO   (12*DD*DD)
#define OFF_W1   (16*DD*DD)
#define OFF_W2   (OFF_W1 + LL*DD*FF)
#define OFF_WOUT (OFF_W2 + LL*DD*FF)
#define WTOT     (OFF_WOUT + (size_t)DD*VV)   // 83,099,648 elems

// ---------------------------------------------------------------------------
// Scratch (device globals — no runtime allocation allowed)
// ---------------------------------------------------------------------------
__device__ float g_h  [NT*(size_t)DD];
__device__ float g_qkv[NT*(size_t)QKVW];
__device__ float g_tmp[NT*(size_t)DD];
__device__ __half g_ah [NT*(size_t)DD];
__device__ __half g_fh [NT*(size_t)FF];
__device__ __half g_wh [WTOT];

// ---------------------------------------------------------------------------
// PTX helpers
// ---------------------------------------------------------------------------
__device__ __forceinline__ uint32_t smem_u32(const void* p) {
    uint32_t a;
    asm("{ .reg .u64 t; cvta.to.shared.u64 t, %1; cvt.u32.u64 %0, t; }" : "=r"(a) : "l"(p));
    return a;
}
__device__ __forceinline__ void cp_async16(uint32_t dst, const void* src) {
    asm volatile("cp.async.cg.shared.global [%0], [%1], 16;" :: "r"(dst), "l"(src));
}
__device__ __forceinline__ void cp_commit() {
    asm volatile("cp.async.commit_group;");
}
__device__ __forceinline__ void cp_wait1() {
    asm volatile("cp.async.wait_group 1;");
}
__device__ __forceinline__ void ldmx4(uint32_t addr, uint32_t& r0, uint32_t& r1,
                                      uint32_t& r2, uint32_t& r3) {
    asm volatile("ldmatrix.sync.aligned.m8n8.x4.shared.b16 {%0,%1,%2,%3}, [%4];"
                 : "=r"(r0), "=r"(r1), "=r"(r2), "=r"(r3) : "r"(addr));
}
__device__ __forceinline__ void ldmx4t(uint32_t addr, uint32_t& r0, uint32_t& r1,
                                       uint32_t& r2, uint32_t& r3) {
    asm volatile("ldmatrix.sync.aligned.m8n8.x4.trans.shared.b16 {%0,%1,%2,%3}, [%4];"
                 : "=r"(r0), "=r"(r1), "=r"(r2), "=r"(r3) : "r"(addr));
}
__device__ __forceinline__ void mma_f16(float* c, const uint32_t* a, const uint32_t* b) {
    asm volatile("mma.sync.aligned.m16n8k16.row.col.f32.f16.f16.f32 "
                 "{%0,%1,%2,%3}, {%4,%5,%6,%7}, {%8,%9}, {%0,%1,%2,%3};"
                 : "+f"(c[0]), "+f"(c[1]), "+f"(c[2]), "+f"(c[3])
                 : "r"(a[0]), "r"(a[1]), "r"(a[2]), "r"(a[3]), "r"(b[0]), "r"(b[1]));
}
__device__ __forceinline__ uint32_t h2_bits(__half2 v) {
    return *reinterpret_cast<uint32_t*>(&v);
}
__device__ __forceinline__ uint32_t pack_h2(float a, float b) {
    return h2_bits(__floats2half2_rn(a, b));
}
// packed fp32x2 ops (PTX-only FFMA2 path)
#define FMA2(acc, a, b) \
    asm("fma.rn.f32x2 %0, %1, %2, %0;" : "+l"(acc) : "l"(a), "l"(b))
#define MUL2(out, a, b) \
    asm("mul.rn.f32x2 %0, %1, %2;" : "=l"(out) : "l"(a), "l"(b))
__device__ __forceinline__ unsigned long long dup2(float v) {
    unsigned long long r;
    asm("mov.b64 %0, {%1, %1};" : "=l"(r) : "f"(v));
    return r;
}
__device__ __forceinline__ void unpack2(unsigned long long v, float& lo, float& hi) {
    asm("mov.b64 {%0, %1}, %2;" : "=f"(lo), "=f"(hi) : "l"(v));
}

// ---------------------------------------------------------------------------
// Weight convert: W fp32 -> fp16 plane, 16 elems/iter (MLP=4)
// ---------------------------------------------------------------------------
__global__ __launch_bounds__(256) void wconv_kernel(const float* __restrict__ W,
                                                    __half* __restrict__ out,
                                                    int n16)   // n/16
{
    const float4* W4 = reinterpret_cast<const float4*>(W);
    uint4* O4 = reinterpret_cast<uint4*>(out);
    for (int i = blockIdx.x * blockDim.x + threadIdx.x; i < n16; i += gridDim.x * blockDim.x) {
        float4 f0 = W4[4 * i];
        float4 f1 = W4[4 * i + 1];
        float4 f2 = W4[4 * i + 2];
        float4 f3 = W4[4 * i + 3];
        uint4 o0, o1;
        o0.x = pack_h2(f0.x, f0.y);
        o0.y = pack_h2(f0.z, f0.w);
        o0.z = pack_h2(f1.x, f1.y);
        o0.w = pack_h2(f1.z, f1.w);
        o1.x = pack_h2(f2.x, f2.y);
        o1.y = pack_h2(f2.z, f2.w);
        o1.z = pack_h2(f3.x, f3.y);
        o1.w = pack_h2(f3.z, f3.w);
        O4[2 * i]     = o0;
        O4[2 * i + 1] = o1;
    }
}

// ---------------------------------------------------------------------------
// Embedding + positional encoding; writes fp32 h AND fp16 activation plane
// ---------------------------------------------------------------------------
__global__ __launch_bounds__(256) void embed_kernel(const int* __restrict__ x,
                                                    const float* __restrict__ emb,
                                                    float* __restrict__ h,
                                                    __half* __restrict__ ah)
{
    int t = blockIdx.x;
    int s = t & (SS - 1);
    int tok = x[t];
    const float* e = emb + (size_t)tok * DD;
    const float negln = -9.210340371976184f;
    size_t base = (size_t)t * DD;
    for (int d0 = threadIdx.x * 2; d0 < DD; d0 += blockDim.x * 2) {
        float v[2];
        #pragma unroll
        for (int j = 0; j < 2; j++) {
            int d = d0 + j;
            int i2 = (d >> 1) * 2;
            float div = expf((float)i2 * (negln / (float)DD));
            float ang = (float)s * div;
            float pe = (d & 1) ? cosf(ang) : sinf(ang);
            v[j] = e[d] * 32.0f + pe;
        }
        h[base + d0] = v[0];
        h[base + d0 + 1] = v[1];
        *reinterpret_cast<uint32_t*>(ah + base + d0) = pack_h2(v[0], v[1]);
    }
}

// ---------------------------------------------------------------------------
// fp16 GEMM via mma.sync: C[M,N] = A[M,K] @ W[K,N] (+bias)(+GELU)
// 3-stage cp.async pipeline (wait -> sync -> issue -> commit -> compute),
// CTA 128x128, 8 warps of 64x32, 2 CTAs/SM.
// ---------------------------------------------------------------------------
__device__ __forceinline__ void stage_loadA(uint32_t sdst, const __half* A,
                                            int rowBase, int K, int k0, int tid)
{
    #pragma unroll
    for (int i = 0; i < 4; i++) {
        int idx = tid + i * 256;
        int r  = idx >> 3;
        int ch = idx & 7;
        uint32_t so = (uint32_t)r * AROWB + (uint32_t)ch * 16;
        cp_async16(sdst + so, A + (size_t)(rowBase + r) * K + k0 + ch * 8);
    }
}

__device__ __forceinline__ void stage_loadB(uint32_t sdst, const __half* Bw,
                                            int Nw, int colW, int k0, int tid)
{
    #pragma unroll
    for (int i = 0; i < 4; i++) {
        int idx = tid + i * 256;
        int r  = idx >> 4;                 // row 0..63
        int ch = idx & 15;                 // 16B chunk 0..15
        uint32_t so = (uint32_t)r * BROWB + (uint32_t)ch * 16;
        cp_async16(sdst + so, Bw + (size_t)(k0 + r) * Nw + colW + ch * 8);
    }
}

template<int ACT, int OUTH>
__global__ __launch_bounds__(256, 2) void gemm_mma(const __half* __restrict__ A,
                                                   const __half* __restrict__ W0,
                                                   const __half* __restrict__ W1p,
                                                   const __half* __restrict__ W2p,
                                                   const float* __restrict__ bias,
                                                   float* __restrict__ C,
                                                   __half* __restrict__ Ch,
                                                   int M, int Nw, int K, int ldC)
{
    extern __shared__ char smem[];
    const uint32_t sb = smem_u32(smem);
    const int tid  = threadIdx.x;
    const int wid  = tid >> 5;
    const int lane = tid & 31;
    const int rowBase = blockIdx.x * BM;

    const __half* Bw = W0;
    int colW;
    if (W1p) {
        int wsel = blockIdx.y >> 3;
        if (wsel == 1)      Bw = W1p;
        else if (wsel == 2) Bw = W2p;
        colW = (blockIdx.y & 7) * BN;
    } else {
        colW = blockIdx.y * BN;
    }
    const int colC = blockIdx.y * BN;

    const int m0 = (wid >> 2) * 64;
    const int n0 = (wid & 3) * 32;
    const int g  = lane >> 3;
    const int lr = lane & 7;

    float acc[4][4][4];
    #pragma unroll
    for (int mt = 0; mt < 4; mt++)
        #pragma unroll
        for (int nt = 0; nt < 4; nt++)
            #pragma unroll
            for (int e = 0; e < 4; e++) acc[mt][nt][e] = 0.0f;

    const int KT = K / BK;   // >= 8 in all calls

    // Prologue: stages 0 and 1 in flight (one commit group each)
    stage_loadA(sb,        A,  rowBase, K, 0,  tid);
    stage_loadB(sb + ASTG, Bw, Nw, colW, 0,  tid);
    cp_commit();
    stage_loadA(sb + STG,        A,  rowBase, K, BK, tid);
    stage_loadB(sb + STG + ASTG, Bw, Nw, colW, BK, tid);
    cp_commit();

    int b0 = 0, b1 = 1, b2 = 2;   // buffers for stages it, it+1, it+2

    for (int it = 0; it < KT; it++) {
        // Before the wait at iteration it, committed groups are G0..G_{it+1};
        // wait_group 1 => oldest (stage it) retired for THIS thread.
        cp_wait1();
        // Cross-thread visibility of stage it + close last iteration's reads
        // of buffer b2 before overwriting it.
        __syncthreads();
        if (it + 2 < KT) {
            uint32_t d = sb + (uint32_t)b2 * STG;
            stage_loadA(d,        A,  rowBase, K, (it + 2) * BK, tid);
            stage_loadB(d + ASTG, Bw, Nw, colW, (it + 2) * BK, tid);
        }
        cp_commit();               // real or empty group — uniform counting

        const uint32_t aB = sb + (uint32_t)b0 * STG;
        const uint32_t bB = aB + ASTG;
        #pragma unroll
        for (int ks = 0; ks < 4; ks++) {
            uint32_t Af[4][4];
            #pragma unroll
            for (int mt = 0; mt < 4; mt++) {
                int r  = m0 + mt * 16 + (g & 1) * 8 + lr;
                int ch = ks * 2 + (g >> 1);
                uint32_t ad = aB + (uint32_t)r * AROWB + (uint32_t)ch * 16;
                ldmx4(ad, Af[mt][0], Af[mt][1], Af[mt][2], Af[mt][3]);
            }
            uint32_t Bf[4][2];
            #pragma unroll
            for (int p = 0; p < 2; p++) {
                int kr = ks * 16 + (lane & 15);
                int nc = n0 + p * 16 + (lane >> 4) * 8;
                uint32_t bd = bB + (uint32_t)kr * BROWB + (uint32_t)nc * 2;
                ldmx4t(bd, Bf[2*p][0], Bf[2*p][1], Bf[2*p+1][0], Bf[2*p+1][1]);
            }
            #pragma unroll
            for (int mt = 0; mt < 4; mt++)
                #pragma unroll
                for (int nt = 0; nt < 4; nt++)
                    mma_f16(acc[mt][nt], Af[mt], Bf[nt]);
        }

        int t0 = b0; b0 = b1; b1 = b2; b2 = t0;   // rotate
    }

    // Epilogue
    const int crow = lane >> 2;
    const int ccol = (lane & 3) * 2;
    #pragma unroll
    for (int mt = 0; mt < 4; mt++) {
        #pragma unroll
        for (int nt = 0; nt < 4; nt++) {
            int col = colC + n0 + nt * 8 + ccol;
            float bv0 = 0.0f, bv1 = 0.0f;
            if (bias) { bv0 = __ldg(bias + col); bv1 = __ldg(bias + col + 1); }
            #pragma unroll
            for (int half = 0; half < 2; half++) {
                int row = rowBase + m0 + mt * 16 + crow + half * 8;
                float v0 = acc[mt][nt][half * 2 + 0] + bv0;
                float v1 = acc[mt][nt][half * 2 + 1] + bv1;
                if (ACT == 1) {
                    v0 = 0.5f * v0 * (1.0f + erff(v0 * 0.7071067811865476f));
                    v1 = 0.5f * v1 * (1.0f + erff(v1 * 0.7071067811865476f));
                }
                if (OUTH) {
                    *reinterpret_cast<uint32_t*>(Ch + (size_t)row * ldC + col) = pack_h2(v0, v1);
                } else {
                    *reinterpret_cast<float2*>(&C[(size_t)row * ldC + col]) = make_float2(v0, v1);
                }
            }
        }
    }
}

// ---------------------------------------------------------------------------
// Flash attention (fp32, packed f32x2 FMA) on packed qkv [NT, 3072].
// ---------------------------------------------------------------------------
__global__ __launch_bounds__(128) void attn_kernel(const float* __restrict__ QKV,
                                                   const int* __restrict__ x,
                                                   __half* __restrict__ Oh)
{
    __shared__ float Ks[32][64];
    __shared__ float Vs[32][64];
    __shared__ int   validS[32];

    const int bh = blockIdx.x;
    const int b  = bh >> 4;
    const int h  = bh & 15;
    const int qt = blockIdx.y;
    const int tid = threadIdx.x;       // 0..127
    const int qrow = qt * 128 + tid;
    const int tQ = b * SS + qrow;

    const unsigned long long* qp2 =
        reinterpret_cast<const unsigned long long*>(QKV + (size_t)tQ * QKVW + h * DKH);
    unsigned long long q2[32], acc2[32];
    #pragma unroll
    for (int i = 0; i < 32; i++) { q2[i] = qp2[i]; acc2[i] = 0ull; }

    float mrun = -1e30f, lsum = 0.0f;
    const int ntiles = 4 * qt + 4;

    const int lrow = tid >> 2;
    const int lcol = (tid & 3) * 16;

    for (int kt = 0; kt < ntiles; kt++) {
        const int kbase = kt * 32;
        {
            size_t off = (size_t)(b * SS + kbase + lrow) * QKVW + h * DKH + lcol;
            #pragma unroll
            for (int q = 0; q < 4; q++) {
                *reinterpret_cast<float4*>(&Ks[lrow][lcol + q * 4]) =
                    *reinterpret_cast<const float4*>(QKV + off + 1024 + q * 4);
                *reinterpret_cast<float4*>(&Vs[lrow][lcol + q * 4]) =
                    *reinterpret_cast<const float4*>(QKV + off + 2048 + q * 4);
            }
        }
        if (tid < 32) validS[tid] = (x[b * SS + kbase + tid] != 0);
        __syncthreads();

        int jmax = qrow - kbase + 1;
        if (jmax > 32) jmax = 32;
        if (jmax > 0) {
            float s[32];
            float tmax = -1e30f;
            #pragma unroll
            for (int j = 0; j < 32; j++) {
                if (j < jmax) {
                    const ulonglong2* kr = reinterpret_cast<const ulonglong2*>(Ks[j]);
                    unsigned long long sa = 0ull, sb2 = 0ull;
                    #pragma unroll
                    for (int dq = 0; dq < 16; dq++) {
                        ulonglong2 k2 = kr[dq];
                        FMA2(sa,  q2[2*dq],     k2.x);
                        FMA2(sb2, q2[2*dq + 1], k2.y);
                    }
                    float a0, a1, b0, b1;
                    unpack2(sa, a0, a1);
                    unpack2(sb2, b0, b1);
                    float sum = (a0 + a1) + (b0 + b1);
                    sum *= 0.125f;
                    if (!validS[j]) sum = -1e30f;
                    s[j] = sum;
                    tmax = fmaxf(tmax, sum);
                } else {
                    s[j] = -1e30f;
                }
            }
            float mnew = fmaxf(mrun, tmax);
            float corr = __expf(mrun - mnew);
            lsum *= corr;
            unsigned long long cd = dup2(corr);
            #pragma unroll
            for (int i = 0; i < 32; i++) MUL2(acc2[i], acc2[i], cd);
            mrun = mnew;
            #pragma unroll
            for (int j = 0; j < 32; j++) {
                float pj = __expf(s[j] - mrun);
                lsum += pj;
                unsigned long long pd = dup2(pj);
                const ulonglong2* vr = reinterpret_cast<const ulonglong2*>(Vs[j]);
                #pragma unroll
                for (int dq = 0; dq < 16; dq++) {
                    ulonglong2 v2 = vr[dq];
                    FMA2(acc2[2*dq],     pd, v2.x);
                    FMA2(acc2[2*dq + 1], pd, v2.y);
                }
            }
        }
        __syncthreads();
    }

    float inv = 1.0f / lsum;
    size_t ob = (size_t)tQ * DD + h * DKH;
    #pragma unroll
    for (int i = 0; i < 32; i++) {
        float lo, hi;
        unpack2(acc2[i], lo, hi);
        *reinterpret_cast<uint32_t*>(Oh + ob + i * 2) = pack_h2(lo * inv, hi * inv);
    }
}

// ---------------------------------------------------------------------------
// Residual add + LayerNorm (in place on h); also emits fp16 activation plane
// ---------------------------------------------------------------------------
__device__ __forceinline__ float block_sum(float v, float* red)
{
    #pragma unroll
    for (int o = 16; o > 0; o >>= 1) v += __shfl_xor_sync(0xffffffffu, v, o);
    int w = threadIdx.x >> 5;
    if ((threadIdx.x & 31) == 0) red[w] = v;
    __syncthreads();
    if (threadIdx.x < 32) {
        float t = (threadIdx.x < 8) ? red[threadIdx.x] : 0.0f;
        #pragma unroll
        for (int o = 4; o > 0; o >>= 1) t += __shfl_xor_sync(0xffffffffu, t, o);
        if (threadIdx.x == 0) red[0] = t;
    }
    __syncthreads();
    float r = red[0];
    __syncthreads();
    return r;
}

__global__ __launch_bounds__(256) void add_ln_kernel(float* __restrict__ h,
                                                     const float* __restrict__ r,
                                                     const float* __restrict__ g,
                                                     const float* __restrict__ bta,
                                                     __half* __restrict__ ah)
{
    __shared__ float red[32];
    const int t = blockIdx.x;
    const int tid = threadIdx.x;
    size_t base = (size_t)t * DD;
    float v[4];
    float sum = 0.0f;
    #pragma unroll
    for (int i = 0; i < 4; i++) {
        int d = tid * 2 + (i & 1) + (i >> 1) * 512;
        float val = h[base + d] + r[base + d];
        v[i] = val;
        sum += val;
    }
    float tot = block_sum(sum, red);
    float mu = tot * (1.0f / (float)DD);
    float sq = 0.0f;
    #pragma unroll
    for (int i = 0; i < 4; i++) { float dvi = v[i] - mu; sq += dvi * dvi; }
    float var = block_sum(sq, red) * (1.0f / (float)DD);
    float rs = rsqrtf(var + 1e-5f);
    #pragma unroll
    for (int p = 0; p < 2; p++) {
        int d = tid * 2 + p * 512;
        float o0 = (v[p*2]   - mu) * rs * g[d]     + bta[d];
        float o1 = (v[p*2+1] - mu) * rs * g[d + 1] + bta[d + 1];
        h[base + d]     = o0;
        h[base + d + 1] = o1;
        *reinterpret_cast<uint32_t*>(ah + base + d) = pack_h2(o0, o1);
    }
}

// ---------------------------------------------------------------------------
// Launch
// ---------------------------------------------------------------------------
extern "C" void kernel_launch(void* const* d_in, const int* in_sizes, int n_in,
                              void* d_out, int out_size)
{
    const int*   x    = (const int*)  d_in[0];
    const float* emb  = (const float*)d_in[1];
    const float* Wq   = (const float*)d_in[2];
    const float* Wk   = (const float*)d_in[3];
    const float* Wv   = (const float*)d_in[4];
    const float* Wo   = (const float*)d_in[5];
    const float* bo   = (const float*)d_in[6];
    const float* ln1g = (const float*)d_in[7];
    const float* ln1b = (const float*)d_in[8];
    const float* ln2g = (const float*)d_in[9];
    const float* ln2b = (const float*)d_in[10];
    const float* W1   = (const float*)d_in[11];
    const float* b1   = (const float*)d_in[12];
    const float* W2   = (const float*)d_in[13];
    const float* b2   = (const float*)d_in[14];
    const float* Wout = (const float*)d_in[15];
    const float* bout = (const float*)d_in[16];
    float* out = (float*)d_out;

    void* p;
    cudaGetSymbolAddress(&p, g_h);   float* h   = (float*)p;
    cudaGetSymbolAddress(&p, g_qkv); float* qkv = (float*)p;
    cudaGetSymbolAddress(&p, g_tmp); float* tmp = (float*)p;
    cudaGetSymbolAddress(&p, g_ah);  __half* ah = (__half*)p;
    cudaGetSymbolAddress(&p, g_fh);  __half* fh = (__half*)p;
    cudaGetSymbolAddress(&p, g_wh);  __half* wh = (__half*)p;

    cudaFuncSetAttribute(gemm_mma<0,0>, cudaFuncAttributeMaxDynamicSharedMemorySize, GEMM_SMEM);
    cudaFuncSetAttribute(gemm_mma<1,1>, cudaFuncAttributeMaxDynamicSharedMemorySize, GEMM_SMEM);

    // Convert all weights to fp16 planes (streaming, once per launch)
    wconv_kernel<<<1024, 256>>>(Wq,   wh + OFF_WQ,   LL*DD*DD/16);
    wconv_kernel<<<1024, 256>>>(Wk,   wh + OFF_WK,   LL*DD*DD/16);
    wconv_kernel<<<1024, 256>>>(Wv,   wh + OFF_WV,   LL*DD*DD/16);
    wconv_kernel<<<1024, 256>>>(Wo,   wh + OFF_WO,   LL*DD*DD/16);
    wconv_kernel<<<2048, 256>>>(W1,   wh + OFF_W1,   LL*DD*FF/16);
    wconv_kernel<<<2048, 256>>>(W2,   wh + OFF_W2,   LL*DD*FF/16);
    wconv_kernel<<<2048, 256>>>(Wout, wh + OFF_WOUT, DD*VV/16);

    embed_kernel<<<NT, 256>>>(x, emb, h, ah);

    const dim3 gQKV(NT/BM, QKVW/BN);  // 32 x 24 (fused q|k|v)
    const dim3 gD(NT/BM, DD/BN);      // 32 x 8
    const dim3 gF(NT/BM, FF/BN);      // 32 x 32
    const dim3 gV(NT/BM, VV/BN);      // 32 x 250

    for (int l = 0; l < LL; l++) {
        const size_t oD = (size_t)l * DD * DD;
        const size_t oF = (size_t)l * DD * FF;

        // Fused QKV projection (one launch, W plane selected per block)
        gemm_mma<0,0><<<gQKV, 256, GEMM_SMEM>>>(ah,
            wh + OFF_WQ + oD, wh + OFF_WK + oD, wh + OFF_WV + oD,
            nullptr, qkv, nullptr, NT, DD, DD, QKVW);

        attn_kernel<<<dim3(BB * HH, SS / 128), 128>>>(qkv, x, ah);   // ctx -> fp16 plane

        gemm_mma<0,0><<<gD, 256, GEMM_SMEM>>>(ah,
            wh + OFF_WO + oD, nullptr, nullptr,
            bo + l * DD, tmp, nullptr, NT, DD, DD, DD);
        add_ln_kernel<<<NT, 256>>>(h, tmp, ln1g + l * DD, ln1b + l * DD, ah);

        gemm_mma<1,1><<<gF, 256, GEMM_SMEM>>>(ah,
            wh + OFF_W1 + oF, nullptr, nullptr,
            b1 + l * FF, nullptr, fh, NT, FF, DD, FF);
        gemm_mma<0,0><<<gD, 256, GEMM_SMEM>>>(fh,
            wh + OFF_W2 + oF, nullptr, nullptr,
            b2 + l * DD, tmp, nullptr, NT, DD, FF, DD);
        add_ln_kernel<<<NT, 256>>>(h, tmp, ln2g + l * DD, ln2b + l * DD, ah);
    }

    gemm_mma<0,0><<<gV, 256, GEMM_SMEM>>>(ah,
        wh + OFF_WOUT, nullptr, nullptr,
        bout, out, nullptr, NT, VV, DD, VV);
}

// round 15
// speedup vs baseline: 3.5578x; 1.6029x over previous
#include <cuda_runtime.h>
#include <cuda_fp16.h>
#include <cstdint>
#include <cmath>

// Problem constants
#define BB   4
#define SS   1024
#define DD   1024
#define HH   16
#define DKH  64
#define LL   4
#define FF   4096
#define VV   32000
#define NT   (BB*SS)   // 4096 tokens
#define QKVW 3072      // packed q|k|v width

// GEMM tile config: CTA 128x128, warp 64x32 (2x4 warps), BK=64, 3-stage, 2 CTAs/SM
#define BM 128
#define BN 128
#define BK 64
#define AROWB 144                  // A smem row: 128B data + 16B pad
#define ASTG (BM*AROWB)            // one 128xBK fp16 matrix: 18432 B
#define BROWB 272                  // B smem row: 256B data + 16B pad
#define BSTG (64*BROWB)            // one 64x128 fp16 plane per stage: 17408 B
#define STG (ASTG + BSTG)          // 35840 B per stage
#define GEMM_SMEM (3*STG)          // 107520 B  (2 CTAs/SM: 215040 <= ~227KB)

// Attention smem
#define TROWB 144                  // 64 fp16 = 128B + 16B pad
#define TTILE (64*TROWB)           // 9216 B

// fp16 weight plane offsets (elements)
#define OFF_WQ   0
#define OFF_WK   (4*DD*DD)
#define OFF_WV   (8*DD*DD)
#define OFF_WO   (12*DD*DD)
#define OFF_W1   (16*DD*DD)
#define OFF_W2   (OFF_W1 + LL*DD*FF)
#define OFF_WOUT (OFF_W2 + LL*DD*FF)
#define WTOT     (OFF_WOUT + (size_t)DD*VV)   // 83,099,648 elems

// ---------------------------------------------------------------------------
// Scratch (device globals — no runtime allocation allowed)
// ---------------------------------------------------------------------------
__device__ float g_h  [NT*(size_t)DD];
__device__ float g_tmp[NT*(size_t)DD];
__device__ __half g_qh [NT*(size_t)QKVW];
__device__ __half g_ah [NT*(size_t)DD];
__device__ __half g_fh [NT*(size_t)FF];
__device__ __half g_wh [WTOT];

// ---------------------------------------------------------------------------
// PTX helpers
// ---------------------------------------------------------------------------
__device__ __forceinline__ uint32_t smem_u32(const void* p) {
    uint32_t a;
    asm("{ .reg .u64 t; cvta.to.shared.u64 t, %1; cvt.u32.u64 %0, t; }" : "=r"(a) : "l"(p));
    return a;
}
__device__ __forceinline__ void cp_async16(uint32_t dst, const void* src) {
    asm volatile("cp.async.cg.shared.global [%0], [%1], 16;" :: "r"(dst), "l"(src));
}
__device__ __forceinline__ void cp_commit() {
    asm volatile("cp.async.commit_group;");
}
__device__ __forceinline__ void cp_wait1() {
    asm volatile("cp.async.wait_group 1;");
}
__device__ __forceinline__ void cp_wait0() {
    asm volatile("cp.async.wait_group 0;");
}
__device__ __forceinline__ void ldmx4(uint32_t addr, uint32_t& r0, uint32_t& r1,
                                      uint32_t& r2, uint32_t& r3) {
    asm volatile("ldmatrix.sync.aligned.m8n8.x4.shared.b16 {%0,%1,%2,%3}, [%4];"
                 : "=r"(r0), "=r"(r1), "=r"(r2), "=r"(r3) : "r"(addr));
}
__device__ __forceinline__ void ldmx4t(uint32_t addr, uint32_t& r0, uint32_t& r1,
                                       uint32_t& r2, uint32_t& r3) {
    asm volatile("ldmatrix.sync.aligned.m8n8.x4.trans.shared.b16 {%0,%1,%2,%3}, [%4];"
                 : "=r"(r0), "=r"(r1), "=r"(r2), "=r"(r3) : "r"(addr));
}
__device__ __forceinline__ void mma_f16(float* c, const uint32_t* a, const uint32_t* b) {
    asm volatile("mma.sync.aligned.m16n8k16.row.col.f32.f16.f16.f32 "
                 "{%0,%1,%2,%3}, {%4,%5,%6,%7}, {%8,%9}, {%0,%1,%2,%3};"
                 : "+f"(c[0]), "+f"(c[1]), "+f"(c[2]), "+f"(c[3])
                 : "r"(a[0]), "r"(a[1]), "r"(a[2]), "r"(a[3]), "r"(b[0]), "r"(b[1]));
}
__device__ __forceinline__ uint32_t h2_bits(__half2 v) {
    return *reinterpret_cast<uint32_t*>(&v);
}
__device__ __forceinline__ uint32_t pack_h2(float a, float b) {
    return h2_bits(__floats2half2_rn(a, b));
}

// ---------------------------------------------------------------------------
// Weight convert: W fp32 -> fp16 plane, 16 elems/iter (MLP=4)
// ---------------------------------------------------------------------------
__global__ __launch_bounds__(256) void wconv_kernel(const float* __restrict__ W,
                                                    __half* __restrict__ out,
                                                    int n16)   // n/16
{
    const float4* W4 = reinterpret_cast<const float4*>(W);
    uint4* O4 = reinterpret_cast<uint4*>(out);
    for (int i = blockIdx.x * blockDim.x + threadIdx.x; i < n16; i += gridDim.x * blockDim.x) {
        float4 f0 = W4[4 * i];
        float4 f1 = W4[4 * i + 1];
        float4 f2 = W4[4 * i + 2];
        float4 f3 = W4[4 * i + 3];
        uint4 o0, o1;
        o0.x = pack_h2(f0.x, f0.y);
        o0.y = pack_h2(f0.z, f0.w);
        o0.z = pack_h2(f1.x, f1.y);
        o0.w = pack_h2(f1.z, f1.w);
        o1.x = pack_h2(f2.x, f2.y);
        o1.y = pack_h2(f2.z, f2.w);
        o1.z = pack_h2(f3.x, f3.y);
        o1.w = pack_h2(f3.z, f3.w);
        O4[2 * i]     = o0;
        O4[2 * i + 1] = o1;
    }
}

// ---------------------------------------------------------------------------
// Embedding + positional encoding; writes fp32 h AND fp16 activation plane
// ---------------------------------------------------------------------------
__global__ __launch_bounds__(256) void embed_kernel(const int* __restrict__ x,
                                                    const float* __restrict__ emb,
                                                    float* __restrict__ h,
                                                    __half* __restrict__ ah)
{
    int t = blockIdx.x;
    int s = t & (SS - 1);
    int tok = x[t];
    const float* e = emb + (size_t)tok * DD;
    const float negln = -9.210340371976184f;
    size_t base = (size_t)t * DD;
    for (int d0 = threadIdx.x * 2; d0 < DD; d0 += blockDim.x * 2) {
        float v[2];
        #pragma unroll
        for (int j = 0; j < 2; j++) {
            int d = d0 + j;
            int i2 = (d >> 1) * 2;
            float div = expf((float)i2 * (negln / (float)DD));
            float ang = (float)s * div;
            float pe = (d & 1) ? cosf(ang) : sinf(ang);
            v[j] = e[d] * 32.0f + pe;
        }
        h[base + d0] = v[0];
        h[base + d0 + 1] = v[1];
        *reinterpret_cast<uint32_t*>(ah + base + d0) = pack_h2(v[0], v[1]);
    }
}

// ---------------------------------------------------------------------------
// fp16 GEMM via mma.sync (R14 config, unchanged): 3-stage pipeline, 2 CTAs/SM.
// ---------------------------------------------------------------------------
__device__ __forceinline__ void stage_loadA(uint32_t sdst, const __half* A,
                                            int rowBase, int K, int k0, int tid)
{
    #pragma unroll
    for (int i = 0; i < 4; i++) {
        int idx = tid + i * 256;
        int r  = idx >> 3;
        int ch = idx & 7;
        uint32_t so = (uint32_t)r * AROWB + (uint32_t)ch * 16;
        cp_async16(sdst + so, A + (size_t)(rowBase + r) * K + k0 + ch * 8);
    }
}

__device__ __forceinline__ void stage_loadB(uint32_t sdst, const __half* Bw,
                                            int Nw, int colW, int k0, int tid)
{
    #pragma unroll
    for (int i = 0; i < 4; i++) {
        int idx = tid + i * 256;
        int r  = idx >> 4;
        int ch = idx & 15;
        uint32_t so = (uint32_t)r * BROWB + (uint32_t)ch * 16;
        cp_async16(sdst + so, Bw + (size_t)(k0 + r) * Nw + colW + ch * 8);
    }
}

template<int ACT, int OUTH>
__global__ __launch_bounds__(256, 2) void gemm_mma(const __half* __restrict__ A,
                                                   const __half* __restrict__ W0,
                                                   const __half* __restrict__ W1p,
                                                   const __half* __restrict__ W2p,
                                                   const float* __restrict__ bias,
                                                   float* __restrict__ C,
                                                   __half* __restrict__ Ch,
                                                   int M, int Nw, int K, int ldC)
{
    extern __shared__ char smem[];
    const uint32_t sb = smem_u32(smem);
    const int tid  = threadIdx.x;
    const int wid  = tid >> 5;
    const int lane = tid & 31;
    const int rowBase = blockIdx.x * BM;

    const __half* Bw = W0;
    int colW;
    if (W1p) {
        int wsel = blockIdx.y >> 3;
        if (wsel == 1)      Bw = W1p;
        else if (wsel == 2) Bw = W2p;
        colW = (blockIdx.y & 7) * BN;
    } else {
        colW = blockIdx.y * BN;
    }
    const int colC = blockIdx.y * BN;

    const int m0 = (wid >> 2) * 64;
    const int n0 = (wid & 3) * 32;
    const int g  = lane >> 3;
    const int lr = lane & 7;

    float acc[4][4][4];
    #pragma unroll
    for (int mt = 0; mt < 4; mt++)
        #pragma unroll
        for (int nt = 0; nt < 4; nt++)
            #pragma unroll
            for (int e = 0; e < 4; e++) acc[mt][nt][e] = 0.0f;

    const int KT = K / BK;

    stage_loadA(sb,        A,  rowBase, K, 0,  tid);
    stage_loadB(sb + ASTG, Bw, Nw, colW, 0,  tid);
    cp_commit();
    stage_loadA(sb + STG,        A,  rowBase, K, BK, tid);
    stage_loadB(sb + STG + ASTG, Bw, Nw, colW, BK, tid);
    cp_commit();

    int b0 = 0, b1 = 1, b2 = 2;

    for (int it = 0; it < KT; it++) {
        cp_wait1();
        __syncthreads();
        if (it + 2 < KT) {
            uint32_t d = sb + (uint32_t)b2 * STG;
            stage_loadA(d,        A,  rowBase, K, (it + 2) * BK, tid);
            stage_loadB(d + ASTG, Bw, Nw, colW, (it + 2) * BK, tid);
        }
        cp_commit();

        const uint32_t aB = sb + (uint32_t)b0 * STG;
        const uint32_t bB = aB + ASTG;
        #pragma unroll
        for (int ks = 0; ks < 4; ks++) {
            uint32_t Af[4][4];
            #pragma unroll
            for (int mt = 0; mt < 4; mt++) {
                int r  = m0 + mt * 16 + (g & 1) * 8 + lr;
                int ch = ks * 2 + (g >> 1);
                uint32_t ad = aB + (uint32_t)r * AROWB + (uint32_t)ch * 16;
                ldmx4(ad, Af[mt][0], Af[mt][1], Af[mt][2], Af[mt][3]);
            }
            uint32_t Bf[4][2];
            #pragma unroll
            for (int p = 0; p < 2; p++) {
                int kr = ks * 16 + (lane & 15);
                int nc = n0 + p * 16 + (lane >> 4) * 8;
                uint32_t bd = bB + (uint32_t)kr * BROWB + (uint32_t)nc * 2;
                ldmx4t(bd, Bf[2*p][0], Bf[2*p][1], Bf[2*p+1][0], Bf[2*p+1][1]);
            }
            #pragma unroll
            for (int mt = 0; mt < 4; mt++)
                #pragma unroll
                for (int nt = 0; nt < 4; nt++)
                    mma_f16(acc[mt][nt], Af[mt], Bf[nt]);
        }

        int t0 = b0; b0 = b1; b1 = b2; b2 = t0;
    }

    const int crow = lane >> 2;
    const int ccol = (lane & 3) * 2;
    #pragma unroll
    for (int mt = 0; mt < 4; mt++) {
        #pragma unroll
        for (int nt = 0; nt < 4; nt++) {
            int col = colC + n0 + nt * 8 + ccol;
            float bv0 = 0.0f, bv1 = 0.0f;
            if (bias) { bv0 = __ldg(bias + col); bv1 = __ldg(bias + col + 1); }
            #pragma unroll
            for (int half = 0; half < 2; half++) {
                int row = rowBase + m0 + mt * 16 + crow + half * 8;
                float v0 = acc[mt][nt][half * 2 + 0] + bv0;
                float v1 = acc[mt][nt][half * 2 + 1] + bv1;
                if (ACT == 1) {
                    v0 = 0.5f * v0 * (1.0f + erff(v0 * 0.7071067811865476f));
                    v1 = 0.5f * v1 * (1.0f + erff(v1 * 0.7071067811865476f));
                }
                if (OUTH) {
                    *reinterpret_cast<uint32_t*>(Ch + (size_t)row * ldC + col) = pack_h2(v0, v1);
                } else {
                    *reinterpret_cast<float2*>(&C[(size_t)row * ldC + col]) = make_float2(v0, v1);
                }
            }
        }
    }
}

// ---------------------------------------------------------------------------
// Tensor-core flash attention on fp16 qkv [NT, 3072]; emits fp16 ctx plane.
// Block = (b, h, 64 q-rows), 4 warps x 16-row tiles; 64-key K-tiles.
// S = Q@K^T via ldmx4 [n][k] operand; P@V via ldmx4t [k][n] operand.
// ---------------------------------------------------------------------------
__global__ __launch_bounds__(128) void attn_kernel(const __half* __restrict__ QKV,
                                                   const int* __restrict__ x,
                                                   __half* __restrict__ Oh)
{
    __shared__ char smem[3 * TTILE + 256];
    const uint32_t qB = smem_u32(smem);
    const uint32_t kB = qB + TTILE;
    const uint32_t vB = qB + 2 * TTILE;
    int* validS = reinterpret_cast<int*>(smem + 3 * TTILE);

    const int tid  = threadIdx.x;
    const int b    = blockIdx.x >> 4;
    const int hh   = blockIdx.x & 15;
    const int qt   = (int)gridDim.y - 1 - (int)blockIdx.y;   // heavy blocks first
    const int qbase = qt * 64;
    const int w    = tid >> 5;
    const int lane = tid & 31;
    const int g    = lane >> 3;
    const int lr   = lane & 7;
    const int q4   = lane & 3;

    // Load Q tile (64 rows x 64 fp16)
    #pragma unroll
    for (int i = 0; i < 4; i++) {
        int idx = tid + i * 128;
        int r = idx >> 3, c = idx & 7;
        cp_async16(qB + (uint32_t)r * TROWB + (uint32_t)c * 16,
                   QKV + (size_t)(b * SS + qbase + r) * QKVW + hh * DKH + c * 8);
    }
    cp_commit();
    cp_wait0();
    __syncthreads();

    // Q fragments (A operand), 4 k16 chunks
    uint32_t aQ[4][4];
    #pragma unroll
    for (int ks = 0; ks < 4; ks++) {
        int r  = 16 * w + (g & 1) * 8 + lr;
        int ch = ks * 2 + (g >> 1);
        ldmx4(qB + (uint32_t)r * TROWB + (uint32_t)ch * 16,
              aQ[ks][0], aQ[ks][1], aQ[ks][2], aQ[ks][3]);
    }

    float o[8][4];
    #pragma unroll
    for (int dt = 0; dt < 8; dt++)
        #pragma unroll
        for (int e = 0; e < 4; e++) o[dt][e] = 0.0f;
    float m0 = -1e30f, m1 = -1e30f, l0 = 0.0f, l1 = 0.0f;

    const int r0 = qbase + 16 * w + (lane >> 2);   // this thread's rows (seq-local)
    const int r1 = r0 + 8;

    for (int kt = 0; kt <= qt; kt++) {
        const int kbase = kt * 64;
        __syncthreads();   // close previous tile reads before overwriting K/V
        #pragma unroll
        for (int i = 0; i < 4; i++) {
            int idx = tid + i * 128;
            int r = idx >> 3, c = idx & 7;
            size_t gsrc = (size_t)(b * SS + kbase + r) * QKVW + hh * DKH + c * 8;
            cp_async16(kB + (uint32_t)r * TROWB + (uint32_t)c * 16, QKV + gsrc + 1024);
            cp_async16(vB + (uint32_t)r * TROWB + (uint32_t)c * 16, QKV + gsrc + 2048);
        }
        if (tid < 64) validS[tid] = (x[b * SS + kbase + tid] != 0);
        cp_commit();
        cp_wait0();
        __syncthreads();

        // --- S = Q @ K^T  (n = key, k = dk; K rows are [n][k] -> plain ldmx4)
        float s[8][4];
        #pragma unroll
        for (int nt = 0; nt < 8; nt++)
            #pragma unroll
            for (int e = 0; e < 4; e++) s[nt][e] = 0.0f;
        #pragma unroll
        for (int ks = 0; ks < 4; ks++) {
            uint32_t Bk[8][2];
            #pragma unroll
            for (int p = 0; p < 4; p++) {
                int r  = p * 16 + (g >> 1) * 8 + lr;
                int ch = ks * 2 + (g & 1);
                ldmx4(kB + (uint32_t)r * TROWB + (uint32_t)ch * 16,
                      Bk[2*p][0], Bk[2*p][1], Bk[2*p+1][0], Bk[2*p+1][1]);
            }
            #pragma unroll
            for (int nt = 0; nt < 8; nt++)
                mma_f16(s[nt], aQ[ks], Bk[nt]);
        }

        // --- scale + mask
        #pragma unroll
        for (int nt = 0; nt < 8; nt++) {
            #pragma unroll
            for (int e = 0; e < 4; e++) {
                int col = nt * 8 + q4 * 2 + (e & 1);
                int key = kbase + col;
                int row = (e < 2) ? r0 : r1;
                float v = s[nt][e] * 0.125f;
                if (key > row || !validS[col]) v = -1e30f;
                s[nt][e] = v;
            }
        }

        // --- row max (quad reduction)
        float mx0 = -1e30f, mx1 = -1e30f;
        #pragma unroll
        for (int nt = 0; nt < 8; nt++) {
            mx0 = fmaxf(mx0, fmaxf(s[nt][0], s[nt][1]));
            mx1 = fmaxf(mx1, fmaxf(s[nt][2], s[nt][3]));
        }
        mx0 = fmaxf(mx0, __shfl_xor_sync(0xffffffffu, mx0, 1));
        mx0 = fmaxf(mx0, __shfl_xor_sync(0xffffffffu, mx0, 2));
        mx1 = fmaxf(mx1, __shfl_xor_sync(0xffffffffu, mx1, 1));
        mx1 = fmaxf(mx1, __shfl_xor_sync(0xffffffffu, mx1, 2));

        float mn0 = fmaxf(m0, mx0), mn1 = fmaxf(m1, mx1);
        float c0 = __expf(m0 - mn0), c1 = __expf(m1 - mn1);
        m0 = mn0; m1 = mn1;
        l0 *= c0; l1 *= c1;
        #pragma unroll
        for (int dt = 0; dt < 8; dt++) {
            o[dt][0] *= c0; o[dt][1] *= c0;
            o[dt][2] *= c1; o[dt][3] *= c1;
        }

        // --- P = exp(S - m), row sums
        float rs0 = 0.0f, rs1 = 0.0f;
        #pragma unroll
        for (int nt = 0; nt < 8; nt++) {
            s[nt][0] = __expf(s[nt][0] - m0);
            s[nt][1] = __expf(s[nt][1] - m0);
            s[nt][2] = __expf(s[nt][2] - m1);
            s[nt][3] = __expf(s[nt][3] - m1);
            rs0 += s[nt][0] + s[nt][1];
            rs1 += s[nt][2] + s[nt][3];
        }
        rs0 += __shfl_xor_sync(0xffffffffu, rs0, 1);
        rs0 += __shfl_xor_sync(0xffffffffu, rs0, 2);
        rs1 += __shfl_xor_sync(0xffffffffu, rs1, 1);
        rs1 += __shfl_xor_sync(0xffffffffu, rs1, 2);
        l0 += rs0; l1 += rs1;

        // --- O += P @ V  (k = key, n = d; V rows are [k][n] -> ldmx4t)
        #pragma unroll
        for (int kk = 0; kk < 4; kk++) {
            uint32_t aP[4];
            aP[0] = pack_h2(s[2*kk][0],   s[2*kk][1]);
            aP[1] = pack_h2(s[2*kk][2],   s[2*kk][3]);
            aP[2] = pack_h2(s[2*kk+1][0], s[2*kk+1][1]);
            aP[3] = pack_h2(s[2*kk+1][2], s[2*kk+1][3]);
            uint32_t Bv[8][2];
            #pragma unroll
            for (int p = 0; p < 4; p++) {
                int kr = kk * 16 + (lane & 15);
                int nc = p * 16 + (lane >> 4) * 8;
                ldmx4t(vB + (uint32_t)kr * TROWB + (uint32_t)nc * 2,
                       Bv[2*p][0], Bv[2*p][1], Bv[2*p+1][0], Bv[2*p+1][1]);
            }
            #pragma unroll
            for (int dt = 0; dt < 8; dt++)
                mma_f16(o[dt], aP, Bv[dt]);
        }
    }

    // --- finalize: O /= l, write fp16 ctx plane
    float inv0 = 1.0f / l0, inv1 = 1.0f / l1;
    size_t ob0 = (size_t)(b * SS + r0) * DD + hh * DKH;
    size_t ob1 = (size_t)(b * SS + r1) * DD + hh * DKH;
    #pragma unroll
    for (int dt = 0; dt < 8; dt++) {
        int col = dt * 8 + q4 * 2;
        *reinterpret_cast<uint32_t*>(Oh + ob0 + col) = pack_h2(o[dt][0] * inv0, o[dt][1] * inv0);
        *reinterpret_cast<uint32_t*>(Oh + ob1 + col) = pack_h2(o[dt][2] * inv1, o[dt][3] * inv1);
    }
}

// ---------------------------------------------------------------------------
// Residual add + LayerNorm (in place on h); also emits fp16 activation plane
// ---------------------------------------------------------------------------
__device__ __forceinline__ float block_sum(float v, float* red)
{
    #pragma unroll
    for (int o = 16; o > 0; o >>= 1) v += __shfl_xor_sync(0xffffffffu, v, o);
    int w = threadIdx.x >> 5;
    if ((threadIdx.x & 31) == 0) red[w] = v;
    __syncthreads();
    if (threadIdx.x < 32) {
        float t = (threadIdx.x < 8) ? red[threadIdx.x] : 0.0f;
        #pragma unroll
        for (int o = 4; o > 0; o >>= 1) t += __shfl_xor_sync(0xffffffffu, t, o);
        if (threadIdx.x == 0) red[0] = t;
    }
    __syncthreads();
    float r = red[0];
    __syncthreads();
    return r;
}

__global__ __launch_bounds__(256) void add_ln_kernel(float* __restrict__ h,
                                                     const float* __restrict__ r,
                                                     const float* __restrict__ g,
                                                     const float* __restrict__ bta,
                                                     __half* __restrict__ ah)
{
    __shared__ float red[32];
    const int t = blockIdx.x;
    const int tid = threadIdx.x;
    size_t base = (size_t)t * DD;
    float v[4];
    float sum = 0.0f;
    #pragma unroll
    for (int i = 0; i < 4; i++) {
        int d = tid * 2 + (i & 1) + (i >> 1) * 512;
        float val = h[base + d] + r[base + d];
        v[i] = val;
        sum += val;
    }
    float tot = block_sum(sum, red);
    float mu = tot * (1.0f / (float)DD);
    float sq = 0.0f;
    #pragma unroll
    for (int i = 0; i < 4; i++) { float dvi = v[i] - mu; sq += dvi * dvi; }
    float var = block_sum(sq, red) * (1.0f / (float)DD);
    float rs = rsqrtf(var + 1e-5f);
    #pragma unroll
    for (int p = 0; p < 2; p++) {
        int d = tid * 2 + p * 512;
        float o0 = (v[p*2]   - mu) * rs * g[d]     + bta[d];
        float o1 = (v[p*2+1] - mu) * rs * g[d + 1] + bta[d + 1];
        h[base + d]     = o0;
        h[base + d + 1] = o1;
        *reinterpret_cast<uint32_t*>(ah + base + d) = pack_h2(o0, o1);
    }
}

// ---------------------------------------------------------------------------
// Launch
// ---------------------------------------------------------------------------
extern "C" void kernel_launch(void* const* d_in, const int* in_sizes, int n_in,
                              void* d_out, int out_size)
{
    const int*   x    = (const int*)  d_in[0];
    const float* emb  = (const float*)d_in[1];
    const float* Wq   = (const float*)d_in[2];
    const float* Wk   = (const float*)d_in[3];
    const float* Wv   = (const float*)d_in[4];
    const float* Wo   = (const float*)d_in[5];
    const float* bo   = (const float*)d_in[6];
    const float* ln1g = (const float*)d_in[7];
    const float* ln1b = (const float*)d_in[8];
    const float* ln2g = (const float*)d_in[9];
    const float* ln2b = (const float*)d_in[10];
    const float* W1   = (const float*)d_in[11];
    const float* b1   = (const float*)d_in[12];
    const float* W2   = (const float*)d_in[13];
    const float* b2   = (const float*)d_in[14];
    const float* Wout = (const float*)d_in[15];
    const float* bout = (const float*)d_in[16];
    float* out = (float*)d_out;

    void* p;
    cudaGetSymbolAddress(&p, g_h);   float* h   = (float*)p;
    cudaGetSymbolAddress(&p, g_tmp); float* tmp = (float*)p;
    cudaGetSymbolAddress(&p, g_qh);  __half* qh = (__half*)p;
    cudaGetSymbolAddress(&p, g_ah);  __half* ah = (__half*)p;
    cudaGetSymbolAddress(&p, g_fh);  __half* fh = (__half*)p;
    cudaGetSymbolAddress(&p, g_wh);  __half* wh = (__half*)p;

    cudaFuncSetAttribute(gemm_mma<0,0>, cudaFuncAttributeMaxDynamicSharedMemorySize, GEMM_SMEM);
    cudaFuncSetAttribute(gemm_mma<0,1>, cudaFuncAttributeMaxDynamicSharedMemorySize, GEMM_SMEM);
    cudaFuncSetAttribute(gemm_mma<1,1>, cudaFuncAttributeMaxDynamicSharedMemorySize, GEMM_SMEM);

    // Convert all weights to fp16 planes (streaming, once per launch)
    wconv_kernel<<<1024, 256>>>(Wq,   wh + OFF_WQ,   LL*DD*DD/16);
    wconv_kernel<<<1024, 256>>>(Wk,   wh + OFF_WK,   LL*DD*DD/16);
    wconv_kernel<<<1024, 256>>>(Wv,   wh + OFF_WV,   LL*DD*DD/16);
    wconv_kernel<<<1024, 256>>>(Wo,   wh + OFF_WO,   LL*DD*DD/16);
    wconv_kernel<<<2048, 256>>>(W1,   wh + OFF_W1,   LL*DD*FF/16);
    wconv_kernel<<<2048, 256>>>(W2,   wh + OFF_W2,   LL*DD*FF/16);
    wconv_kernel<<<2048, 256>>>(Wout, wh + OFF_WOUT, DD*VV/16);

    embed_kernel<<<NT, 256>>>(x, emb, h, ah);

    const dim3 gQKV(NT/BM, QKVW/BN);  // 32 x 24 (fused q|k|v)
    const dim3 gD(NT/BM, DD/BN);      // 32 x 8
    const dim3 gF(NT/BM, FF/BN);      // 32 x 32
    const dim3 gV(NT/BM, VV/BN);      // 32 x 250

    for (int l = 0; l < LL; l++) {
        const size_t oD = (size_t)l * DD * DD;
        const size_t oF = (size_t)l * DD * FF;

        // Fused QKV projection -> fp16 qh buffer
        gemm_mma<0,1><<<gQKV, 256, GEMM_SMEM>>>(ah,
            wh + OFF_WQ + oD, wh + OFF_WK + oD, wh + OFF_WV + oD,
            nullptr, nullptr, qh, NT, DD, DD, QKVW);

        attn_kernel<<<dim3(BB * HH, SS / 64), 128>>>(qh, x, ah);   // ctx -> fp16 plane

        gemm_mma<0,0><<<gD, 256, GEMM_SMEM>>>(ah,
            wh + OFF_WO + oD, nullptr, nullptr,
            bo + l * DD, tmp, nullptr, NT, DD, DD, DD);
        add_ln_kernel<<<NT, 256>>>(h, tmp, ln1g + l * DD, ln1b + l * DD, ah);

        gemm_mma<1,1><<<gF, 256, GEMM_SMEM>>>(ah,
            wh + OFF_W1 + oF, nullptr, nullptr,
            b1 + l * FF, nullptr, fh, NT, FF, DD, FF);
        gemm_mma<0,0><<<gD, 256, GEMM_SMEM>>>(fh,
            wh + OFF_W2 + oF, nullptr, nullptr,
            b2 + l * DD, tmp, nullptr, NT, DD, FF, DD);
        add_ln_kernel<<<NT, 256>>>(h, tmp, ln2g + l * DD, ln2b + l * DD, ah);
    }

    gemm_mma<0,0><<<gV, 256, GEMM_SMEM>>>(ah,
        wh + OFF_WOUT, nullptr, nullptr,
        bout, out, nullptr, NT, VV, DD, VV);
}